// round 5
// baseline (speedup 1.0000x reference)
#include <cuda_runtime.h>
#include <cuda_bf16.h>
#include <cstdint>
#include <math.h>
using bf16 = __nv_bfloat16;
typedef long long ll;

#define BATCH 2
#define SEQ 2048
#define HID 2048
#define NHEAD 16
#define HDIM 128
#define FFD 8192
#define ROWS 4096
#define RMS_EPS 1e-5f
#define RH 8388608LL
#define H2 4194304LL
#define FF2 16777216LL
#define GGN 33554432LL
#define SCN 134217728LL

// ------------------------- scratch -------------------------
__device__ float g_q[RH], g_k[RH], g_v[RH], g_att[RH], g_mod[RH], g_t1[RH], g_t2[RH], g_x[RH];
__device__ float g_sc[SCN];
__device__ float g_gate[GGN], g_up[GGN];
__device__ bf16 g_wh[8*H2+3*FF2], g_wl[8*H2+3*FF2];
__device__ bf16 g_ah[8*RH+GGN],  g_al[8*RH+GGN];
__device__ bf16 g_ph[SCN], g_pl[SCN];

// weight arena offsets
#define OWQ  (0*H2)
#define OWK  (1*H2)
#define OWV  (2*H2)
#define OWO  (3*H2)
#define OFBW (4*H2)
#define OFBG (5*H2)
#define ODRW (6*H2)
#define ODRG (7*H2)
#define OWG  (8*H2)
#define OWU  (8*H2+FF2)
#define OWD  (8*H2+2*FF2)
// activation arena offsets
#define OQN  (0*RH)
#define OXB  (1*RH)
#define OXM  (2*RH)
#define OQ   (3*RH)
#define OK2  (4*RH)
#define OVT  (5*RH)
#define OATT (6*RH)
#define OHB  (7*RH)
#define OGG  (8*RH)

// ------------------------- PTX helpers -------------------------
__device__ __forceinline__ uint32_t smem_u32(const void* p) {
    uint32_t a;
    asm("{ .reg .u64 t; cvta.to.shared.u64 t, %1; cvt.u32.u64 %0, t; }" : "=r"(a) : "l"(p));
    return a;
}
__device__ __forceinline__ void cp16(uint32_t s, const void* g) {
    asm volatile("cp.async.cg.shared.global [%0], [%1], 16;" :: "r"(s), "l"(g));
}
__device__ __forceinline__ void cpcommit() { asm volatile("cp.async.commit_group;" ::: "memory"); }
__device__ __forceinline__ void cpwait0()  { asm volatile("cp.async.wait_group 0;" ::: "memory"); }
__device__ __forceinline__ void cpwait1()  { asm volatile("cp.async.wait_group 1;" ::: "memory"); }
__device__ __forceinline__ void cpwait2()  { asm volatile("cp.async.wait_group 2;" ::: "memory"); }

__device__ __forceinline__ void ldsm4(uint32_t* r, uint32_t addr) {
    asm volatile("ldmatrix.sync.aligned.m8n8.x4.shared.b16 {%0,%1,%2,%3}, [%4];"
        : "=r"(r[0]), "=r"(r[1]), "=r"(r[2]), "=r"(r[3]) : "r"(addr));
}
__device__ __forceinline__ void mma16816(float* c, const uint32_t* a, uint32_t b0, uint32_t b1) {
    asm volatile("mma.sync.aligned.m16n8k16.row.col.f32.bf16.bf16.f32 "
        "{%0,%1,%2,%3}, {%4,%5,%6,%7}, {%8,%9}, {%0,%1,%2,%3};"
        : "+f"(c[0]), "+f"(c[1]), "+f"(c[2]), "+f"(c[3])
        : "r"(a[0]), "r"(a[1]), "r"(a[2]), "r"(a[3]), "r"(b0), "r"(b1));
}
__device__ __forceinline__ void split2(float x, bf16& h, bf16& l) {
    h = __float2bfloat16(x);
    l = __float2bfloat16(x - __bfloat162float(h));
}

// ---------------------------------------------------------------------------
// Wide bf16x3 HMMA GEMM: C = alpha*(A @ B^T). 128x256 CTA tile, KTILE=32,
// 4-stage cp.async, 8 warps (warp tile 64x64), 64B rows, xor-16B swizzle.
// Stage layout: Ah@0(8K), Al@8K, Bh@16K(16K), Bl@32K. Stage 48KB.
// ---------------------------------------------------------------------------
#define STG2 49152
#define NSTG 4
#define TC2_SMEM (NSTG*STG2)

__global__ __launch_bounds__(256, 1)
void mma_gemm256(const bf16* __restrict__ Ahg, const bf16* __restrict__ Alg,
                 const bf16* __restrict__ Bhg, const bf16* __restrict__ Blg,
                 float* __restrict__ Cg,
                 int K, int lda, int ldb, int ldc, float alpha,
                 int zdiv, ll sAa, ll sAb, ll sBa, ll sBb, ll sCa, ll sCb)
{
    extern __shared__ char smem_raw[];
    const uint32_t tiles = smem_u32(smem_raw);
    const int tid = threadIdx.x, wid = tid >> 5, lane = tid & 31;
    const int wm = wid & 1, wn = wid >> 1;     // 2x4 warp grid, warp tile 64x64

    const int z = blockIdx.z;
    const ll aoff = (ll)(z / zdiv) * sAa + (ll)(z % zdiv) * sAb;
    const ll boff = (ll)(z / zdiv) * sBa + (ll)(z % zdiv) * sBb;
    const ll coff = (ll)(z / zdiv) * sCa + (ll)(z % zdiv) * sCb;
    const bf16* Ah = Ahg + aoff; const bf16* Al = Alg + aoff;
    const bf16* Bh = Bhg + boff; const bf16* Bl = Blg + boff;

    const int bm = blockIdx.y << 7, bn = blockIdx.x << 8;
    const int nk = K >> 5;

    auto load_stage = [&](int kt) {
        const uint32_t st = tiles + (uint32_t)(kt & (NSTG-1)) * STG2;
        const ll kb = (ll)kt * 32;
#pragma unroll
        for (int i = tid; i < 512; i += 256) {
            const int r = i >> 2, c = i & 3;
            const uint32_t sw = (uint32_t)r * 64u + (uint32_t)((c ^ ((r >> 1) & 3)) << 4);
            const ll ao = (ll)(bm + r) * lda + kb + c * 8;
            cp16(st        + sw, Ah + ao);
            cp16(st + 8192 + sw, Al + ao);
        }
#pragma unroll
        for (int i = tid; i < 1024; i += 256) {
            const int r = i >> 2, c = i & 3;
            const uint32_t sw = (uint32_t)r * 64u + (uint32_t)((c ^ ((r >> 1) & 3)) << 4);
            const ll bo = (ll)(bn + r) * ldb + kb + c * 8;
            cp16(st + 16384 + sw, Bh + bo);
            cp16(st + 32768 + sw, Bl + bo);
        }
        cpcommit();
    };

    float acc[4][8][4];
#pragma unroll
    for (int i = 0; i < 4; i++)
#pragma unroll
        for (int j = 0; j < 8; j++)
#pragma unroll
            for (int t = 0; t < 4; t++) acc[i][j][t] = 0.f;

    const int aRow  = wm * 64 + (lane & 15);
    const int aCpar = lane >> 4;
    const int bNadd = ((lane >> 4) << 3) + (lane & 7);
    const int bCpar = (lane >> 3) & 1;

    load_stage(0);
    if (1 < nk) load_stage(1); else cpcommit();
    if (2 < nk) load_stage(2); else cpcommit();

    for (int kt = 0; kt < nk; kt++) {
        cpwait2();
        __syncthreads();
        if (kt + 3 < nk) load_stage(kt + 3); else cpcommit();

        const uint32_t st = tiles + (uint32_t)(kt & (NSTG-1)) * STG2;
#pragma unroll
        for (int ks = 0; ks < 2; ks++) {
            uint32_t ahf[4][4], alf[4][4];
#pragma unroll
            for (int mt = 0; mt < 4; mt++) {
                const int row = aRow + mt * 16;
                const int ch = ks * 2 + aCpar;
                const uint32_t ad = st + (uint32_t)row * 64u + (uint32_t)((ch ^ ((row >> 1) & 3)) << 4);
                ldsm4(ahf[mt], ad);
                ldsm4(alf[mt], ad + 8192);
            }
#pragma unroll
            for (int nt = 0; nt < 4; nt++) {
                const int row = wn * 64 + nt * 16 + bNadd;
                const int ch = ks * 2 + bCpar;
                const uint32_t bd = st + 16384u + (uint32_t)row * 64u + (uint32_t)((ch ^ ((row >> 1) & 3)) << 4);
                uint32_t bh[4], bl[4];
                ldsm4(bh, bd);
                ldsm4(bl, bd + 16384);
#pragma unroll
                for (int mt = 0; mt < 4; mt++) {
                    mma16816(acc[mt][nt*2],   ahf[mt], bh[0], bh[1]);
                    mma16816(acc[mt][nt*2+1], ahf[mt], bh[2], bh[3]);
                }
#pragma unroll
                for (int mt = 0; mt < 4; mt++) {
                    mma16816(acc[mt][nt*2],   ahf[mt], bl[0], bl[1]);
                    mma16816(acc[mt][nt*2+1], ahf[mt], bl[2], bl[3]);
                }
#pragma unroll
                for (int mt = 0; mt < 4; mt++) {
                    mma16816(acc[mt][nt*2],   alf[mt], bh[0], bh[1]);
                    mma16816(acc[mt][nt*2+1], alf[mt], bh[2], bh[3]);
                }
            }
        }
    }

    const int erow = bm + wm * 64 + (lane >> 2);
    const int ecol = bn + wn * 64 + (lane & 3) * 2;
#pragma unroll
    for (int mt = 0; mt < 4; mt++) {
#pragma unroll
        for (int j = 0; j < 8; j++) {
            float* p0 = Cg + coff + (ll)(erow + mt*16)     * ldc + ecol + j*8;
            float* p1 = Cg + coff + (ll)(erow + mt*16 + 8) * ldc + ecol + j*8;
            *(float2*)p0 = make_float2(acc[mt][j][0]*alpha, acc[mt][j][1]*alpha);
            *(float2*)p1 = make_float2(acc[mt][j][2]*alpha, acc[mt][j][3]*alpha);
        }
    }
}

// ---------------------------------------------------------------------------
// Narrow (N=128) bf16x3 HMMA GEMM — used for P@V only. As in R4.
// ---------------------------------------------------------------------------
#define STG 65536
#define TC_SMEM (3*STG)

__global__ __launch_bounds__(256)
void mma_gemm(const bf16* __restrict__ Ahg, const bf16* __restrict__ Alg,
              const bf16* __restrict__ Bhg, const bf16* __restrict__ Blg,
              float* __restrict__ Cg,
              int K, int lda, int ldb, int ldc, float alpha,
              int zdiv, ll sAa, ll sAb, ll sBa, ll sBb, ll sCa, ll sCb)
{
    extern __shared__ char smem_raw[];
    const uint32_t tiles = smem_u32(smem_raw);
    const int tid = threadIdx.x, wid = tid >> 5, lane = tid & 31;
    const int wm = wid & 3, wn = wid >> 2;

    const int z = blockIdx.z;
    const ll aoff = (ll)(z / zdiv) * sAa + (ll)(z % zdiv) * sAb;
    const ll boff = (ll)(z / zdiv) * sBa + (ll)(z % zdiv) * sBb;
    const ll coff = (ll)(z / zdiv) * sCa + (ll)(z % zdiv) * sCb;
    const bf16* Ah = Ahg + aoff; const bf16* Al = Alg + aoff;
    const bf16* Bh = Bhg + boff; const bf16* Bl = Blg + boff;

    const int bm = blockIdx.y << 7, bn = blockIdx.x << 7;
    const int nk = K >> 6;

    auto load_stage = [&](int kt) {
        const uint32_t st = tiles + (uint32_t)(kt % 3) * STG;
        const ll kb = (ll)kt * 64;
#pragma unroll
        for (int i = tid; i < 1024; i += 256) {
            const int r = i >> 3, c = i & 7;
            const uint32_t sw = (uint32_t)r * 128u + (uint32_t)((c ^ (r & 7)) << 4);
            const ll ao = (ll)(bm + r) * lda + kb + c * 8;
            const ll bo = (ll)(bn + r) * ldb + kb + c * 8;
            cp16(st         + sw, Ah + ao);
            cp16(st + 16384 + sw, Al + ao);
            cp16(st + 32768 + sw, Bh + bo);
            cp16(st + 49152 + sw, Bl + bo);
        }
        cpcommit();
    };

    float acc[2][8][4];
#pragma unroll
    for (int i = 0; i < 2; i++)
#pragma unroll
        for (int j = 0; j < 8; j++)
#pragma unroll
            for (int t = 0; t < 4; t++) acc[i][j][t] = 0.f;

    const int aRow  = wm * 32 + (lane & 15);
    const int aCpar = lane >> 4;
    const int bNadd = ((lane >> 4) << 3) + (lane & 7);
    const int bCpar = (lane >> 3) & 1;

    load_stage(0);
    if (nk > 1) load_stage(1);

    for (int kt = 0; kt < nk; kt++) {
        if (kt >= nk - 2) cpwait0(); else cpwait1();
        __syncthreads();
        if (kt + 2 < nk) load_stage(kt + 2);

        const uint32_t st = tiles + (uint32_t)(kt % 3) * STG;
#pragma unroll
        for (int ks = 0; ks < 4; ks++) {
            uint32_t ahf[2][4], alf[2][4];
#pragma unroll
            for (int mt = 0; mt < 2; mt++) {
                const int row = aRow + mt * 16;
                const int ch = ks * 2 + aCpar;
                const uint32_t ad = st + (uint32_t)row * 128u + (uint32_t)((ch ^ (row & 7)) << 4);
                ldsm4(ahf[mt], ad);
                ldsm4(alf[mt], ad + 16384);
            }
#pragma unroll
            for (int nt = 0; nt < 4; nt++) {
                const int row = wn * 64 + nt * 16 + bNadd;
                const int ch = ks * 2 + bCpar;
                const uint32_t bd = st + 32768u + (uint32_t)row * 128u + (uint32_t)((ch ^ (row & 7)) << 4);
                uint32_t bh[4], bl[4];
                ldsm4(bh, bd);
                ldsm4(bl, bd + 16384);
#pragma unroll
                for (int mt = 0; mt < 2; mt++) {
                    mma16816(acc[mt][nt*2],   ahf[mt], bh[0], bh[1]);
                    mma16816(acc[mt][nt*2+1], ahf[mt], bh[2], bh[3]);
                }
#pragma unroll
                for (int mt = 0; mt < 2; mt++) {
                    mma16816(acc[mt][nt*2],   ahf[mt], bl[0], bl[1]);
                    mma16816(acc[mt][nt*2+1], ahf[mt], bl[2], bl[3]);
                }
#pragma unroll
                for (int mt = 0; mt < 2; mt++) {
                    mma16816(acc[mt][nt*2],   alf[mt], bh[0], bh[1]);
                    mma16816(acc[mt][nt*2+1], alf[mt], bh[2], bh[3]);
                }
            }
        }
        __syncthreads();
    }

    const int erow = bm + wm * 32 + (lane >> 2);
    const int ecol = bn + wn * 64 + (lane & 3) * 2;
#pragma unroll
    for (int mt = 0; mt < 2; mt++) {
#pragma unroll
        for (int j = 0; j < 8; j++) {
            float* p0 = Cg + coff + (ll)(erow + mt*16)     * ldc + ecol + j*8;
            float* p1 = Cg + coff + (ll)(erow + mt*16 + 8) * ldc + ecol + j*8;
            *(float2*)p0 = make_float2(acc[mt][j][0]*alpha, acc[mt][j][1]*alpha);
            *(float2*)p1 = make_float2(acc[mt][j][2]*alpha, acc[mt][j][3]*alpha);
        }
    }
}

// ------------------------- reductions -------------------------
__device__ __forceinline__ float wsum(float v) {
#pragma unroll
    for (int o = 16; o; o >>= 1) v += __shfl_xor_sync(0xffffffffu, v, o);
    return v;
}
__device__ __forceinline__ float wmax(float v) {
#pragma unroll
    for (int o = 16; o; o >>= 1) v = fmaxf(v, __shfl_xor_sync(0xffffffffu, v, o));
    return v;
}
__device__ __forceinline__ float bsum(float v) {
    __shared__ float sh[8];
    v = wsum(v); __syncthreads();
    if ((threadIdx.x & 31) == 0) sh[threadIdx.x >> 5] = v;
    __syncthreads();
    float r = 0.f;
#pragma unroll
    for (int i = 0; i < 8; i++) r += sh[i];
    return r;
}
__device__ __forceinline__ float bmax(float v) {
    __shared__ float sh[8];
    v = wmax(v); __syncthreads();
    if ((threadIdx.x & 31) == 0) sh[threadIdx.x >> 5] = v;
    __syncthreads();
    float r = sh[0];
#pragma unroll
    for (int i = 1; i < 8; i++) r = fmaxf(r, sh[i]);
    return r;
}

// ------------------------- elementwise kernels -------------------------
__global__ __launch_bounds__(256)
void split_kernel(const float* __restrict__ s, bf16* __restrict__ oh, bf16* __restrict__ ol, int n4)
{
    const int i = blockIdx.x * 256 + threadIdx.x;
    if (i >= n4) return;
    float4 v = ((const float4*)s)[i];
    bf16 h0,l0,h1,l1,h2,l2,h3,l3;
    split2(v.x,h0,l0); split2(v.y,h1,l1); split2(v.z,h2,l2); split2(v.w,h3,l3);
    ((__nv_bfloat162*)oh)[2*i]   = __nv_bfloat162(h0,h1);
    ((__nv_bfloat162*)oh)[2*i+1] = __nv_bfloat162(h2,h3);
    ((__nv_bfloat162*)ol)[2*i]   = __nv_bfloat162(l0,l1);
    ((__nv_bfloat162*)ol)[2*i+1] = __nv_bfloat162(l2,l3);
}

__global__ __launch_bounds__(256)
void rmsnorm_split(const float* __restrict__ in, const float* __restrict__ w,
                   bf16* __restrict__ oh, bf16* __restrict__ ol)
{
    const ll base = (ll)blockIdx.x * HID;
    const float4* xin = (const float4*)(in + base);
    float ss = 0.f;
    for (int i = threadIdx.x; i < HID/4; i += 256) {
        float4 v = xin[i];
        ss += v.x*v.x + v.y*v.y + v.z*v.z + v.w*v.w;
    }
    ss = bsum(ss);
    const float r = rsqrtf(ss * (1.f/HID) + RMS_EPS);
    for (int i = threadIdx.x; i < HID/4; i += 256) {
        float4 v = xin[i];
        float4 ww = ((const float4*)w)[i];
        bf16 h0,l0,h1,l1,h2,l2,h3,l3;
        split2(v.x*r*ww.x,h0,l0); split2(v.y*r*ww.y,h1,l1);
        split2(v.z*r*ww.z,h2,l2); split2(v.w*r*ww.w,h3,l3);
        ((__nv_bfloat162*)(oh + base))[2*i]   = __nv_bfloat162(h0,h1);
        ((__nv_bfloat162*)(oh + base))[2*i+1] = __nv_bfloat162(h2,h3);
        ((__nv_bfloat162*)(ol + base))[2*i]   = __nv_bfloat162(l0,l1);
        ((__nv_bfloat162*)(ol + base))[2*i+1] = __nv_bfloat162(l2,l3);
    }
}

__global__ __launch_bounds__(256)
void rmsadd_kernel(float* __restrict__ x, const float* __restrict__ w)
{
    const ll base = (ll)blockIdx.x * HID;
    float4* xp = (float4*)(x + base);
    float ss = 0.f;
    for (int i = threadIdx.x; i < HID/4; i += 256) {
        float4 v = xp[i];
        ss += v.x*v.x + v.y*v.y + v.z*v.z + v.w*v.w;
    }
    ss = bsum(ss);
    const float r = rsqrtf(ss * (1.f/HID) + RMS_EPS);
    for (int i = threadIdx.x; i < HID/4; i += 256) {
        float4 v = xp[i];
        float4 ww = ((const float4*)w)[i];
        xp[i] = make_float4(v.x*(1.f+r*ww.x), v.y*(1.f+r*ww.y), v.z*(1.f+r*ww.z), v.w*(1.f+r*ww.w));
    }
}

__global__ void rope_split(const float* __restrict__ src, bf16* __restrict__ oh, bf16* __restrict__ ol)
{
    const int idx = blockIdx.x * blockDim.x + threadIdx.x;
    if (idx >= ROWS * NHEAD * 64) return;
    const int j = idx & 63, h = (idx >> 6) & (NHEAD-1), row = idx >> 10;
    const int pos = row & (SEQ - 1);
    const float inv = (float)exp(-(double)(2*j) / (double)HDIM * log(10000.0));
    float s_, c;
    sincosf((float)pos * inv, &s_, &c);
    const ll p0 = (ll)row * HID + h * HDIM + j;
    const float q0 = src[p0], q1 = src[p0 + 64];
    bf16 hh, lll;
    split2(q0*c - q1*s_, hh, lll); oh[p0]    = hh; ol[p0]    = lll;
    split2(q1*c + q0*s_, hh, lll); oh[p0+64] = hh; ol[p0+64] = lll;
}

// V transpose-split: v[b*SEQ+s][h*128+d] -> vt[(z*128+d)*SEQ + s], z=b*16+h
__global__ void vtrans_kernel(const float* __restrict__ v, bf16* __restrict__ oh, bf16* __restrict__ ol)
{
    __shared__ float t[32][33];
    const int z = blockIdx.z, b = z >> 4, h = z & 15;
    const int s0 = blockIdx.x * 32, d0 = blockIdx.y * 32;
    const int tx = threadIdx.x, ty = threadIdx.y;
#pragma unroll
    for (int i = 0; i < 4; i++) {
        const int s = s0 + ty + i*8;
        t[ty + i*8][tx] = v[((ll)(b*SEQ + s)) * HID + h*HDIM + d0 + tx];
    }
    __syncthreads();
#pragma unroll
    for (int i = 0; i < 4; i++) {
        const int d = d0 + ty + i*8;
        const float x = t[tx][ty + i*8];
        bf16 hh, lll; split2(x, hh, lll);
        const ll o = ((ll)z * HDIM + d) * SEQ + s0 + tx;
        oh[o] = hh; ol[o] = lll;
    }
}

__global__ __launch_bounds__(256)
void softmax_split(const float* __restrict__ sc, const float* __restrict__ mask,
                   bf16* __restrict__ ph, bf16* __restrict__ pl)
{
    const ll off = ((ll)blockIdx.y * SEQ + blockIdx.x) * SEQ;
    const float* p = sc + off;
    const float* mp = mask + (ll)blockIdx.x * SEQ;
    const int t = threadIdx.x * 8;
    float v[8];
    float4 a = *(const float4*)(p + t), b = *(const float4*)(p + t + 4);
    float4 ma = *(const float4*)(mp + t), mb = *(const float4*)(mp + t + 4);
    v[0]=a.x+ma.x; v[1]=a.y+ma.y; v[2]=a.z+ma.z; v[3]=a.w+ma.w;
    v[4]=b.x+mb.x; v[5]=b.y+mb.y; v[6]=b.z+mb.z; v[7]=b.w+mb.w;
    float mx = v[0];
#pragma unroll
    for (int i = 1; i < 8; i++) mx = fmaxf(mx, v[i]);
    mx = bmax(mx);
    float s = 0.f;
#pragma unroll
    for (int i = 0; i < 8; i++) { v[i] = expf(v[i] - mx); s += v[i]; }
    s = bsum(s);
    const float inv = 1.f / s;
    __nv_bfloat162 hv[4], lv[4];
#pragma unroll
    for (int i = 0; i < 4; i++) {
        bf16 h0,l0,h1,l1;
        split2(v[2*i]*inv, h0, l0); split2(v[2*i+1]*inv, h1, l1);
        hv[i] = __nv_bfloat162(h0,h1); lv[i] = __nv_bfloat162(l0,l1);
    }
#pragma unroll
    for (int i = 0; i < 4; i++) {
        ((__nv_bfloat162*)(ph + off + t))[i] = hv[i];
        ((__nv_bfloat162*)(pl + off + t))[i] = lv[i];
    }
}

__device__ __forceinline__ float sigm(float z) { return 1.f / (1.f + expf(-z)); }

__global__ void highway_kernel(const float* __restrict__ g, const float* __restrict__ hh,
                               const float* __restrict__ bias, float* __restrict__ out, int n4)
{
    const int i = blockIdx.x * blockDim.x + threadIdx.x;
    if (i >= n4) return;
    float4 gv = ((const float4*)g)[i], hv = ((const float4*)hh)[i];
    float4 bv = ((const float4*)bias)[i & (HID/4 - 1)];
    ((float4*)out)[i] = make_float4(hv.x*sigm(gv.x+bv.x), hv.y*sigm(gv.y+bv.y),
                                    hv.z*sigm(gv.z+bv.z), hv.w*sigm(gv.w+bv.w));
}

__global__ void combinex_kernel(const float* __restrict__ xm, const float* __restrict__ mod,
                                const float* __restrict__ g, const float* __restrict__ hh,
                                const float* __restrict__ bias, float* __restrict__ out, int n4)
{
    const int i = blockIdx.x * blockDim.x + threadIdx.x;
    if (i >= n4) return;
    float4 xv = ((const float4*)xm)[i], mv = ((const float4*)mod)[i];
    float4 gv = ((const float4*)g)[i], hv = ((const float4*)hh)[i];
    float4 bv = ((const float4*)bias)[i & (HID/4 - 1)];
    ((float4*)out)[i] = make_float4(xv.x+mv.x+hv.x*sigm(gv.x+bv.x), xv.y+mv.y+hv.y*sigm(gv.y+bv.y),
                                    xv.z+mv.z+hv.z*sigm(gv.z+bv.z), xv.w+mv.w+hv.w*sigm(gv.w+bv.w));
}

__global__ void silumul_split(const float* __restrict__ g, const float* __restrict__ u,
                              bf16* __restrict__ oh, bf16* __restrict__ ol, int n4)
{
    const int i = blockIdx.x * blockDim.x + threadIdx.x;
    if (i >= n4) return;
    float4 gv = ((const float4*)g)[i], uv = ((const float4*)u)[i];
    float r0 = gv.x*sigm(gv.x)*uv.x, r1 = gv.y*sigm(gv.y)*uv.y;
    float r2 = gv.z*sigm(gv.z)*uv.z, r3 = gv.w*sigm(gv.w)*uv.w;
    bf16 h0,l0,h1,l1,h2,l2,h3,l3;
    split2(r0,h0,l0); split2(r1,h1,l1); split2(r2,h2,l2); split2(r3,h3,l3);
    ((__nv_bfloat162*)oh)[2*i]   = __nv_bfloat162(h0,h1);
    ((__nv_bfloat162*)oh)[2*i+1] = __nv_bfloat162(h2,h3);
    ((__nv_bfloat162*)ol)[2*i]   = __nv_bfloat162(l0,l1);
    ((__nv_bfloat162*)ol)[2*i+1] = __nv_bfloat162(l2,l3);
}

__global__ void add2_kernel(const float* __restrict__ a, const float* __restrict__ b,
                            float* __restrict__ out, int n4)
{
    const int i = blockIdx.x * blockDim.x + threadIdx.x;
    if (i >= n4) return;
    float4 av = ((const float4*)a)[i], bv = ((const float4*)b)[i];
    ((float4*)out)[i] = make_float4(av.x+bv.x, av.y+bv.y, av.z+bv.z, av.w+bv.w);
}

// ------------------------- launch -------------------------
extern "C" void kernel_launch(void* const* d_in, const int* in_sizes, int n_in,
                              void* d_out, int out_size)
{
    const float* x_mod = (const float*)d_in[0];
    const float* x_back= (const float*)d_in[1];
    const float* mask  = (const float*)d_in[2];
    const float* wq = (const float*)d_in[3];
    const float* wk = (const float*)d_in[4];
    const float* wv = (const float*)d_in[5];
    const float* wo = (const float*)d_in[6];
    const float* cross_ln_w = (const float*)d_in[7];
    const float* fb_w = (const float*)d_in[8];
    const float* fb_g = (const float*)d_in[9];
    const float* fb_gb= (const float*)d_in[10];
    const float* dr_w = (const float*)d_in[11];
    const float* dr_g = (const float*)d_in[12];
    const float* dr_gb= (const float*)d_in[13];
    const float* in_ln_w   = (const float*)d_in[14];
    const float* post_ln_w = (const float*)d_in[15];
    const float* w_gate = (const float*)d_in[16];
    const float* w_up   = (const float*)d_in[17];
    const float* w_down = (const float*)d_in[18];

    float* outx = (float*)d_out;
    float* outd = outx + (size_t)ROWS * HID;

    float *q,*k,*v,*att,*mod,*t1,*t2,*x,*sc,*gg,*uu;
    bf16 *wh,*wl,*ah,*al,*pph,*ppl;
    cudaGetSymbolAddress((void**)&q, g_q);   cudaGetSymbolAddress((void**)&k, g_k);
    cudaGetSymbolAddress((void**)&v, g_v);   cudaGetSymbolAddress((void**)&att, g_att);
    cudaGetSymbolAddress((void**)&mod, g_mod); cudaGetSymbolAddress((void**)&t1, g_t1);
    cudaGetSymbolAddress((void**)&t2, g_t2); cudaGetSymbolAddress((void**)&x, g_x);
    cudaGetSymbolAddress((void**)&sc, g_sc); cudaGetSymbolAddress((void**)&gg, g_gate);
    cudaGetSymbolAddress((void**)&uu, g_up);
    cudaGetSymbolAddress((void**)&wh, g_wh); cudaGetSymbolAddress((void**)&wl, g_wl);
    cudaGetSymbolAddress((void**)&ah, g_ah); cudaGetSymbolAddress((void**)&al, g_al);
    cudaGetSymbolAddress((void**)&pph, g_ph); cudaGetSymbolAddress((void**)&ppl, g_pl);

    cudaFuncSetAttribute(mma_gemm,    cudaFuncAttributeMaxDynamicSharedMemorySize, TC_SMEM);
    cudaFuncSetAttribute(mma_gemm256, cudaFuncAttributeMaxDynamicSharedMemorySize, TC2_SMEM);

    const float ATT_SCALE = 0.08838834764831845f;
    const int n4h = (int)(RH/4), n4f = (int)(GGN/4), n4w = (int)(H2/4), n4ff = (int)(FF2/4);
    const dim3 B256(256);

    // wide kernel for everything except P@V
    auto gemm = [&](const bf16* pah, const bf16* pal, const bf16* pbh, const bf16* pbl,
                    float* c, int M, int N, int K, int lda, int ldb, int ldc, float alpha,
                    int gz, int zdiv, ll saa, ll sab, ll sba, ll sbb, ll sca, ll scb) {
        dim3 g(N/256, M/128, gz);
        mma_gemm256<<<g, 256, TC2_SMEM>>>(pah, pal, pbh, pbl, c, K, lda, ldb, ldc, alpha,
                                          zdiv, saa, sab, sba, sbb, sca, scb);
    };
    auto gemm128 = [&](const bf16* pah, const bf16* pal, const bf16* pbh, const bf16* pbl,
                       float* c, int M, int N, int K, int lda, int ldb, int ldc, float alpha,
                       int gz, int zdiv, ll saa, ll sab, ll sba, ll sbb, ll sca, ll scb) {
        dim3 g(N/128, M/128, gz);
        mma_gemm<<<g, 256, TC_SMEM>>>(pah, pal, pbh, pbl, c, K, lda, ldb, ldc, alpha,
                                      zdiv, saa, sab, sba, sbb, sca, scb);
    };

    // ---- splits of inputs ----
    split_kernel<<<n4h/256, B256>>>(x_mod,  ah+OXM, al+OXM, n4h);
    split_kernel<<<n4h/256, B256>>>(x_back, ah+OXB, al+OXB, n4h);
    rmsnorm_split<<<ROWS, B256>>>(x_mod, cross_ln_w, ah+OQN, al+OQN);
    split_kernel<<<n4w/256, B256>>>(wq,   wh+OWQ,  wl+OWQ,  n4w);
    split_kernel<<<n4w/256, B256>>>(wk,   wh+OWK,  wl+OWK,  n4w);
    split_kernel<<<n4w/256, B256>>>(wv,   wh+OWV,  wl+OWV,  n4w);
    split_kernel<<<n4w/256, B256>>>(wo,   wh+OWO,  wl+OWO,  n4w);
    split_kernel<<<n4w/256, B256>>>(fb_w, wh+OFBW, wl+OFBW, n4w);
    split_kernel<<<n4w/256, B256>>>(fb_g, wh+OFBG, wl+OFBG, n4w);
    split_kernel<<<n4w/256, B256>>>(dr_w, wh+ODRW, wl+ODRW, n4w);
    split_kernel<<<n4w/256, B256>>>(dr_g, wh+ODRG, wl+ODRG, n4w);
    split_kernel<<<n4ff/256, B256>>>(w_gate, wh+OWG, wl+OWG, n4ff);
    split_kernel<<<n4ff/256, B256>>>(w_up,   wh+OWU, wl+OWU, n4ff);
    split_kernel<<<n4ff/256, B256>>>(w_down, wh+OWD, wl+OWD, n4ff);

    // ---- q/k/v projections ----
    gemm(ah+OQN, al+OQN, wh+OWQ, wl+OWQ, q, ROWS, HID, HID, HID, HID, HID, 1.f, 1,1, 0,0,0,0,0,0);
    gemm(ah+OXB, al+OXB, wh+OWK, wl+OWK, k, ROWS, HID, HID, HID, HID, HID, 1.f, 1,1, 0,0,0,0,0,0);
    gemm(ah+OXB, al+OXB, wh+OWV, wl+OWV, v, ROWS, HID, HID, HID, HID, HID, 1.f, 1,1, 0,0,0,0,0,0);

    const int ropeN = ROWS * NHEAD * 64;
    rope_split<<<(ropeN+255)/256, B256>>>(q, ah+OQ,  al+OQ);
    rope_split<<<(ropeN+255)/256, B256>>>(k, ah+OK2, al+OK2);
    vtrans_kernel<<<dim3(SEQ/32, HDIM/32, BATCH*NHEAD), dim3(32,8)>>>(v, ah+OVT, al+OVT);

    // ---- attention ----
    gemm(ah+OQ, al+OQ, ah+OK2, al+OK2, sc, SEQ, SEQ, HDIM, HID, HID, SEQ, ATT_SCALE,
         BATCH*NHEAD, NHEAD, (ll)SEQ*HID, 128, (ll)SEQ*HID, 128,
         (ll)NHEAD*SEQ*SEQ, (ll)SEQ*SEQ);
    softmax_split<<<dim3(SEQ, BATCH*NHEAD), B256>>>(sc, mask, pph, ppl);
    gemm128(pph, ppl, ah+OVT, al+OVT, att, SEQ, HDIM, SEQ, SEQ, SEQ, HID, 1.f,
            BATCH*NHEAD, NHEAD, (ll)NHEAD*SEQ*SEQ, (ll)SEQ*SEQ,
            (ll)NHEAD*HDIM*SEQ, (ll)HDIM*SEQ, (ll)SEQ*HID, 128);
    split_kernel<<<n4h/256, B256>>>(att, ah+OATT, al+OATT, n4h);
    gemm(ah+OATT, al+OATT, wh+OWO, wl+OWO, mod, ROWS, HID, HID, HID, HID, HID, 1.f, 1,1, 0,0,0,0,0,0);

    // ---- feedback highway -> delta ----
    gemm(ah+OXM, al+OXM, wh+OFBG, wl+OFBG, t1, ROWS, HID, HID, HID, HID, HID, 1.f, 1,1, 0,0,0,0,0,0);
    gemm(ah+OXM, al+OXM, wh+OFBW, wl+OFBW, t2, ROWS, HID, HID, HID, HID, HID, 1.f, 1,1, 0,0,0,0,0,0);
    highway_kernel<<<n4h/256, B256>>>(t1, t2, fb_gb, outd, n4h);

    // ---- driver highway + combine ----
    gemm(ah+OXB, al+OXB, wh+ODRG, wl+ODRG, t1, ROWS, HID, HID, HID, HID, HID, 1.f, 1,1, 0,0,0,0,0,0);
    gemm(ah+OXB, al+OXB, wh+ODRW, wl+ODRW, t2, ROWS, HID, HID, HID, HID, HID, 1.f, 1,1, 0,0,0,0,0,0);
    combinex_kernel<<<n4h/256, B256>>>(x_mod, mod, t1, t2, dr_gb, x, n4h);

    // ---- decoder ----
    rmsadd_kernel<<<ROWS, B256>>>(x, in_ln_w);
    rmsnorm_split<<<ROWS, B256>>>(x, post_ln_w, ah+OHB, al+OHB);
    gemm(ah+OHB, al+OHB, wh+OWG, wl+OWG, gg, ROWS, FFD, HID, HID, HID, FFD, 1.f, 1,1, 0,0,0,0,0,0);
    gemm(ah+OHB, al+OHB, wh+OWU, wl+OWU, uu, ROWS, FFD, HID, HID, HID, FFD, 1.f, 1,1, 0,0,0,0,0,0);
    silumul_split<<<n4f/256, B256>>>(gg, uu, ah+OGG, al+OGG, n4f);
    gemm(ah+OGG, al+OGG, wh+OWD, wl+OWD, mod, ROWS, HID, FFD, FFD, FFD, HID, 1.f, 1,1, 0,0,0,0,0,0);
    add2_kernel<<<n4h/256, B256>>>(x, mod, outx, n4h);
}

// round 6
// speedup vs baseline: 1.0400x; 1.0400x over previous
#include <cuda_runtime.h>
#include <cuda_bf16.h>
#include <cstdint>
#include <math.h>
using bf16 = __nv_bfloat16;
typedef long long ll;

#define BATCH 2
#define SEQ 2048
#define HID 2048
#define NHEAD 16
#define HDIM 128
#define FFD 8192
#define ROWS 4096
#define RMS_EPS 1e-5f
#define RH 8388608LL
#define H2 4194304LL
#define FF2 16777216LL
#define GGN 33554432LL
#define SCN 134217728LL

// ------------------------- scratch -------------------------
__device__ float g_q[RH], g_k[RH], g_v[RH], g_att[RH], g_mod[RH], g_t1[RH], g_t2[RH], g_x[RH];
__device__ float g_sc[SCN];
__device__ float g_gate[GGN], g_up[GGN];
__device__ bf16 g_wh[8*H2+3*FF2], g_wl[8*H2+3*FF2];
__device__ bf16 g_ah[8*RH+GGN],  g_al[8*RH+GGN];
__device__ bf16 g_ph[SCN], g_pl[SCN];

// weight arena offsets
#define OWQ  (0*H2)
#define OWK  (1*H2)
#define OWV  (2*H2)
#define OWO  (3*H2)
#define OFBW (4*H2)
#define OFBG (5*H2)
#define ODRW (6*H2)
#define ODRG (7*H2)
#define OWG  (8*H2)
#define OWU  (8*H2+FF2)
#define OWD  (8*H2+2*FF2)
// activation arena offsets
#define OQN  (0*RH)
#define OXB  (1*RH)
#define OXM  (2*RH)
#define OQ   (3*RH)
#define OK2  (4*RH)
#define OVT  (5*RH)
#define OATT (6*RH)
#define OHB  (7*RH)
#define OGG  (8*RH)

// ------------------------- PTX helpers -------------------------
__device__ __forceinline__ uint32_t smem_u32(const void* p) {
    uint32_t a;
    asm("{ .reg .u64 t; cvta.to.shared.u64 t, %1; cvt.u32.u64 %0, t; }" : "=r"(a) : "l"(p));
    return a;
}
__device__ __forceinline__ void cp16(uint32_t s, const void* g) {
    asm volatile("cp.async.cg.shared.global [%0], [%1], 16;" :: "r"(s), "l"(g));
}
__device__ __forceinline__ void cpcommit() { asm volatile("cp.async.commit_group;" ::: "memory"); }
__device__ __forceinline__ void cpwait0()  { asm volatile("cp.async.wait_group 0;" ::: "memory"); }
__device__ __forceinline__ void cpwait1()  { asm volatile("cp.async.wait_group 1;" ::: "memory"); }

__device__ __forceinline__ void ldsm4(uint32_t* r, uint32_t addr) {
    asm volatile("ldmatrix.sync.aligned.m8n8.x4.shared.b16 {%0,%1,%2,%3}, [%4];"
        : "=r"(r[0]), "=r"(r[1]), "=r"(r[2]), "=r"(r[3]) : "r"(addr));
}
__device__ __forceinline__ void mma16816(float* c, const uint32_t* a, uint32_t b0, uint32_t b1) {
    asm volatile("mma.sync.aligned.m16n8k16.row.col.f32.bf16.bf16.f32 "
        "{%0,%1,%2,%3}, {%4,%5,%6,%7}, {%8,%9}, {%0,%1,%2,%3};"
        : "+f"(c[0]), "+f"(c[1]), "+f"(c[2]), "+f"(c[3])
        : "r"(a[0]), "r"(a[1]), "r"(a[2]), "r"(a[3]), "r"(b0), "r"(b1));
}
__device__ __forceinline__ void split2(float x, bf16& h, bf16& l) {
    h = __float2bfloat16(x);
    l = __float2bfloat16(x - __bfloat162float(h));
}

// ---------------------------------------------------------------------------
// bf16x3 HMMA GEMM: C = alpha*(A @ B^T). A:[M,K] lda, B:[N,K] ldb, K-major.
// 128x128 CTA tile, KTILE=32, 3-stage cp.async (96KB -> 2 CTAs/SM),
// 8 warps (warp tile 32x64), 64B rows, xor-16B swizzle (conflict-free).
// per-z offsets: off = (z/zdiv)*s?a + (z%zdiv)*s?b
// ---------------------------------------------------------------------------
#define STG 32768
#define TC_SMEM (3*STG)

__global__ __launch_bounds__(256, 2)
void mma_gemm(const bf16* __restrict__ Ahg, const bf16* __restrict__ Alg,
              const bf16* __restrict__ Bhg, const bf16* __restrict__ Blg,
              float* __restrict__ Cg,
              int K, int lda, int ldb, int ldc, float alpha,
              int zdiv, ll sAa, ll sAb, ll sBa, ll sBb, ll sCa, ll sCb)
{
    extern __shared__ char smem_raw[];
    const uint32_t tiles = smem_u32(smem_raw);
    const int tid = threadIdx.x, wid = tid >> 5, lane = tid & 31;
    const int wm = wid & 3, wn = wid >> 2;   // 4x2 warp grid, warp tile 32x64

    const int z = blockIdx.z;
    const ll aoff = (ll)(z / zdiv) * sAa + (ll)(z % zdiv) * sAb;
    const ll boff = (ll)(z / zdiv) * sBa + (ll)(z % zdiv) * sBb;
    const ll coff = (ll)(z / zdiv) * sCa + (ll)(z % zdiv) * sCb;
    const bf16* Ah = Ahg + aoff; const bf16* Al = Alg + aoff;
    const bf16* Bh = Bhg + boff; const bf16* Bl = Blg + boff;

    const int bm = blockIdx.y << 7, bn = blockIdx.x << 7;
    const int nk = K >> 5;

    auto load_stage = [&](int kt) {
        const uint32_t st = tiles + (uint32_t)(kt % 3) * STG;
        const ll kb = (ll)kt * 32;
#pragma unroll
        for (int i = tid; i < 512; i += 256) {
            const int r = i >> 2, c = i & 3;
            const uint32_t sw = (uint32_t)r * 64u + (uint32_t)((c ^ ((r >> 1) & 3)) << 4);
            const ll ao = (ll)(bm + r) * lda + kb + c * 8;
            const ll bo = (ll)(bn + r) * ldb + kb + c * 8;
            cp16(st         + sw, Ah + ao);
            cp16(st + 8192  + sw, Al + ao);
            cp16(st + 16384 + sw, Bh + bo);
            cp16(st + 24576 + sw, Bl + bo);
        }
        cpcommit();
    };

    float acc[2][8][4];
#pragma unroll
    for (int i = 0; i < 2; i++)
#pragma unroll
        for (int j = 0; j < 8; j++)
#pragma unroll
            for (int t = 0; t < 4; t++) acc[i][j][t] = 0.f;

    const int aRow  = wm * 32 + (lane & 15);
    const int aCpar = lane >> 4;
    const int bNadd = ((lane >> 4) << 3) + (lane & 7);
    const int bCpar = (lane >> 3) & 1;

    load_stage(0);
    if (nk > 1) load_stage(1); else cpcommit();

    for (int kt = 0; kt < nk; kt++) {
        if (kt >= nk - 2) cpwait0(); else cpwait1();
        __syncthreads();
        if (kt + 2 < nk) load_stage(kt + 2); else cpcommit();

        const uint32_t st = tiles + (uint32_t)(kt % 3) * STG;
#pragma unroll
        for (int ks = 0; ks < 2; ks++) {
            uint32_t ahf[2][4], alf[2][4];
#pragma unroll
            for (int mt = 0; mt < 2; mt++) {
                const int row = aRow + mt * 16;
                const int ch = ks * 2 + aCpar;
                const uint32_t ad = st + (uint32_t)row * 64u + (uint32_t)((ch ^ ((row >> 1) & 3)) << 4);
                ldsm4(ahf[mt], ad);
                ldsm4(alf[mt], ad + 8192);
            }
#pragma unroll
            for (int nt = 0; nt < 4; nt++) {
                const int row = wn * 64 + nt * 16 + bNadd;
                const int ch = ks * 2 + bCpar;
                const uint32_t bd = st + 16384u + (uint32_t)row * 64u + (uint32_t)((ch ^ ((row >> 1) & 3)) << 4);
                uint32_t bh[4], bl[4];
                ldsm4(bh, bd);
                ldsm4(bl, bd + 8192);
#pragma unroll
                for (int mt = 0; mt < 2; mt++) {
                    mma16816(acc[mt][nt*2],   ahf[mt], bh[0], bh[1]);
                    mma16816(acc[mt][nt*2+1], ahf[mt], bh[2], bh[3]);
                }
#pragma unroll
                for (int mt = 0; mt < 2; mt++) {
                    mma16816(acc[mt][nt*2],   ahf[mt], bl[0], bl[1]);
                    mma16816(acc[mt][nt*2+1], ahf[mt], bl[2], bl[3]);
                }
#pragma unroll
                for (int mt = 0; mt < 2; mt++) {
                    mma16816(acc[mt][nt*2],   alf[mt], bh[0], bh[1]);
                    mma16816(acc[mt][nt*2+1], alf[mt], bh[2], bh[3]);
                }
            }
        }
    }

    const int erow = bm + wm * 32 + (lane >> 2);
    const int ecol = bn + wn * 64 + (lane & 3) * 2;
#pragma unroll
    for (int mt = 0; mt < 2; mt++) {
#pragma unroll
        for (int j = 0; j < 8; j++) {
            float* p0 = Cg + coff + (ll)(erow + mt*16)     * ldc + ecol + j*8;
            float* p1 = Cg + coff + (ll)(erow + mt*16 + 8) * ldc + ecol + j*8;
            *(float2*)p0 = make_float2(acc[mt][j][0]*alpha, acc[mt][j][1]*alpha);
            *(float2*)p1 = make_float2(acc[mt][j][2]*alpha, acc[mt][j][3]*alpha);
        }
    }
}

// ------------------------- reductions -------------------------
__device__ __forceinline__ float wsum(float v) {
#pragma unroll
    for (int o = 16; o; o >>= 1) v += __shfl_xor_sync(0xffffffffu, v, o);
    return v;
}
__device__ __forceinline__ float wmax(float v) {
#pragma unroll
    for (int o = 16; o; o >>= 1) v = fmaxf(v, __shfl_xor_sync(0xffffffffu, v, o));
    return v;
}
__device__ __forceinline__ float bsum(float v) {
    __shared__ float sh[8];
    v = wsum(v); __syncthreads();
    if ((threadIdx.x & 31) == 0) sh[threadIdx.x >> 5] = v;
    __syncthreads();
    float r = 0.f;
#pragma unroll
    for (int i = 0; i < 8; i++) r += sh[i];
    return r;
}
__device__ __forceinline__ float bmax(float v) {
    __shared__ float sh[8];
    v = wmax(v); __syncthreads();
    if ((threadIdx.x & 31) == 0) sh[threadIdx.x >> 5] = v;
    __syncthreads();
    float r = sh[0];
#pragma unroll
    for (int i = 1; i < 8; i++) r = fmaxf(r, sh[i]);
    return r;
}

// ------------------------- elementwise kernels -------------------------
__global__ __launch_bounds__(256)
void split_kernel(const float* __restrict__ s, bf16* __restrict__ oh, bf16* __restrict__ ol, int n4)
{
    const int i = blockIdx.x * 256 + threadIdx.x;
    if (i >= n4) return;
    float4 v = ((const float4*)s)[i];
    bf16 h0,l0,h1,l1,h2,l2,h3,l3;
    split2(v.x,h0,l0); split2(v.y,h1,l1); split2(v.z,h2,l2); split2(v.w,h3,l3);
    ((__nv_bfloat162*)oh)[2*i]   = __nv_bfloat162(h0,h1);
    ((__nv_bfloat162*)oh)[2*i+1] = __nv_bfloat162(h2,h3);
    ((__nv_bfloat162*)ol)[2*i]   = __nv_bfloat162(l0,l1);
    ((__nv_bfloat162*)ol)[2*i+1] = __nv_bfloat162(l2,l3);
}

__global__ __launch_bounds__(256)
void rmsnorm_split(const float* __restrict__ in, const float* __restrict__ w,
                   bf16* __restrict__ oh, bf16* __restrict__ ol)
{
    const ll base = (ll)blockIdx.x * HID;
    const float4* xin = (const float4*)(in + base);
    float ss = 0.f;
    for (int i = threadIdx.x; i < HID/4; i += 256) {
        float4 v = xin[i];
        ss += v.x*v.x + v.y*v.y + v.z*v.z + v.w*v.w;
    }
    ss = bsum(ss);
    const float r = rsqrtf(ss * (1.f/HID) + RMS_EPS);
    for (int i = threadIdx.x; i < HID/4; i += 256) {
        float4 v = xin[i];
        float4 ww = ((const float4*)w)[i];
        bf16 h0,l0,h1,l1,h2,l2,h3,l3;
        split2(v.x*r*ww.x,h0,l0); split2(v.y*r*ww.y,h1,l1);
        split2(v.z*r*ww.z,h2,l2); split2(v.w*r*ww.w,h3,l3);
        ((__nv_bfloat162*)(oh + base))[2*i]   = __nv_bfloat162(h0,h1);
        ((__nv_bfloat162*)(oh + base))[2*i+1] = __nv_bfloat162(h2,h3);
        ((__nv_bfloat162*)(ol + base))[2*i]   = __nv_bfloat162(l0,l1);
        ((__nv_bfloat162*)(ol + base))[2*i+1] = __nv_bfloat162(l2,l3);
    }
}

__global__ __launch_bounds__(256)
void rmsadd_kernel(float* __restrict__ x, const float* __restrict__ w)
{
    const ll base = (ll)blockIdx.x * HID;
    float4* xp = (float4*)(x + base);
    float ss = 0.f;
    for (int i = threadIdx.x; i < HID/4; i += 256) {
        float4 v = xp[i];
        ss += v.x*v.x + v.y*v.y + v.z*v.z + v.w*v.w;
    }
    ss = bsum(ss);
    const float r = rsqrtf(ss * (1.f/HID) + RMS_EPS);
    for (int i = threadIdx.x; i < HID/4; i += 256) {
        float4 v = xp[i];
        float4 ww = ((const float4*)w)[i];
        xp[i] = make_float4(v.x*(1.f+r*ww.x), v.y*(1.f+r*ww.y), v.z*(1.f+r*ww.z), v.w*(1.f+r*ww.w));
    }
}

__global__ void rope_split(const float* __restrict__ src, bf16* __restrict__ oh, bf16* __restrict__ ol)
{
    const int idx = blockIdx.x * blockDim.x + threadIdx.x;
    if (idx >= ROWS * NHEAD * 64) return;
    const int j = idx & 63, h = (idx >> 6) & (NHEAD-1), row = idx >> 10;
    const int pos = row & (SEQ - 1);
    const float inv = (float)exp(-(double)(2*j) / (double)HDIM * log(10000.0));
    float s_, c;
    sincosf((float)pos * inv, &s_, &c);
    const ll p0 = (ll)row * HID + h * HDIM + j;
    const float q0 = src[p0], q1 = src[p0 + 64];
    bf16 hh, lll;
    split2(q0*c - q1*s_, hh, lll); oh[p0]    = hh; ol[p0]    = lll;
    split2(q1*c + q0*s_, hh, lll); oh[p0+64] = hh; ol[p0+64] = lll;
}

// V transpose-split: v[b*SEQ+s][h*128+d] -> vt[(z*128+d)*SEQ + s], z=b*16+h
__global__ void vtrans_kernel(const float* __restrict__ v, bf16* __restrict__ oh, bf16* __restrict__ ol)
{
    __shared__ float t[32][33];
    const int z = blockIdx.z, b = z >> 4, h = z & 15;
    const int s0 = blockIdx.x * 32, d0 = blockIdx.y * 32;
    const int tx = threadIdx.x, ty = threadIdx.y;
#pragma unroll
    for (int i = 0; i < 4; i++) {
        const int s = s0 + ty + i*8;
        t[ty + i*8][tx] = v[((ll)(b*SEQ + s)) * HID + h*HDIM + d0 + tx];
    }
    __syncthreads();
#pragma unroll
    for (int i = 0; i < 4; i++) {
        const int d = d0 + ty + i*8;
        const float x = t[tx][ty + i*8];
        bf16 hh, lll; split2(x, hh, lll);
        const ll o = ((ll)z * HDIM + d) * SEQ + s0 + tx;
        oh[o] = hh; ol[o] = lll;
    }
}

__global__ __launch_bounds__(256)
void softmax_split(const float* __restrict__ sc, const float* __restrict__ mask,
                   bf16* __restrict__ ph, bf16* __restrict__ pl)
{
    const ll off = ((ll)blockIdx.y * SEQ + blockIdx.x) * SEQ;
    const float* p = sc + off;
    const float* mp = mask + (ll)blockIdx.x * SEQ;
    const int t = threadIdx.x * 8;
    float v[8];
    float4 a = *(const float4*)(p + t), b = *(const float4*)(p + t + 4);
    float4 ma = *(const float4*)(mp + t), mb = *(const float4*)(mp + t + 4);
    v[0]=a.x+ma.x; v[1]=a.y+ma.y; v[2]=a.z+ma.z; v[3]=a.w+ma.w;
    v[4]=b.x+mb.x; v[5]=b.y+mb.y; v[6]=b.z+mb.z; v[7]=b.w+mb.w;
    float mx = v[0];
#pragma unroll
    for (int i = 1; i < 8; i++) mx = fmaxf(mx, v[i]);
    mx = bmax(mx);
    float s = 0.f;
#pragma unroll
    for (int i = 0; i < 8; i++) { v[i] = expf(v[i] - mx); s += v[i]; }
    s = bsum(s);
    const float inv = 1.f / s;
    __nv_bfloat162 hv[4], lv[4];
#pragma unroll
    for (int i = 0; i < 4; i++) {
        bf16 h0,l0,h1,l1;
        split2(v[2*i]*inv, h0, l0); split2(v[2*i+1]*inv, h1, l1);
        hv[i] = __nv_bfloat162(h0,h1); lv[i] = __nv_bfloat162(l0,l1);
    }
#pragma unroll
    for (int i = 0; i < 4; i++) {
        ((__nv_bfloat162*)(ph + off + t))[i] = hv[i];
        ((__nv_bfloat162*)(pl + off + t))[i] = lv[i];
    }
}

__device__ __forceinline__ float sigm(float z) { return 1.f / (1.f + expf(-z)); }

__global__ void highway_kernel(const float* __restrict__ g, const float* __restrict__ hh,
                               const float* __restrict__ bias, float* __restrict__ out, int n4)
{
    const int i = blockIdx.x * blockDim.x + threadIdx.x;
    if (i >= n4) return;
    float4 gv = ((const float4*)g)[i], hv = ((const float4*)hh)[i];
    float4 bv = ((const float4*)bias)[i & (HID/4 - 1)];
    ((float4*)out)[i] = make_float4(hv.x*sigm(gv.x+bv.x), hv.y*sigm(gv.y+bv.y),
                                    hv.z*sigm(gv.z+bv.z), hv.w*sigm(gv.w+bv.w));
}

__global__ void combinex_kernel(const float* __restrict__ xm, const float* __restrict__ mod,
                                const float* __restrict__ g, const float* __restrict__ hh,
                                const float* __restrict__ bias, float* __restrict__ out, int n4)
{
    const int i = blockIdx.x * blockDim.x + threadIdx.x;
    if (i >= n4) return;
    float4 xv = ((const float4*)xm)[i], mv = ((const float4*)mod)[i];
    float4 gv = ((const float4*)g)[i], hv = ((const float4*)hh)[i];
    float4 bv = ((const float4*)bias)[i & (HID/4 - 1)];
    ((float4*)out)[i] = make_float4(xv.x+mv.x+hv.x*sigm(gv.x+bv.x), xv.y+mv.y+hv.y*sigm(gv.y+bv.y),
                                    xv.z+mv.z+hv.z*sigm(gv.z+bv.z), xv.w+mv.w+hv.w*sigm(gv.w+bv.w));
}

__global__ void silumul_split(const float* __restrict__ g, const float* __restrict__ u,
                              bf16* __restrict__ oh, bf16* __restrict__ ol, int n4)
{
    const int i = blockIdx.x * blockDim.x + threadIdx.x;
    if (i >= n4) return;
    float4 gv = ((const float4*)g)[i], uv = ((const float4*)u)[i];
    float r0 = gv.x*sigm(gv.x)*uv.x, r1 = gv.y*sigm(gv.y)*uv.y;
    float r2 = gv.z*sigm(gv.z)*uv.z, r3 = gv.w*sigm(gv.w)*uv.w;
    bf16 h0,l0,h1,l1,h2,l2,h3,l3;
    split2(r0,h0,l0); split2(r1,h1,l1); split2(r2,h2,l2); split2(r3,h3,l3);
    ((__nv_bfloat162*)oh)[2*i]   = __nv_bfloat162(h0,h1);
    ((__nv_bfloat162*)oh)[2*i+1] = __nv_bfloat162(h2,h3);
    ((__nv_bfloat162*)ol)[2*i]   = __nv_bfloat162(l0,l1);
    ((__nv_bfloat162*)ol)[2*i+1] = __nv_bfloat162(l2,l3);
}

__global__ void add2_kernel(const float* __restrict__ a, const float* __restrict__ b,
                            float* __restrict__ out, int n4)
{
    const int i = blockIdx.x * blockDim.x + threadIdx.x;
    if (i >= n4) return;
    float4 av = ((const float4*)a)[i], bv = ((const float4*)b)[i];
    ((float4*)out)[i] = make_float4(av.x+bv.x, av.y+bv.y, av.z+bv.z, av.w+bv.w);
}

// ------------------------- launch -------------------------
extern "C" void kernel_launch(void* const* d_in, const int* in_sizes, int n_in,
                              void* d_out, int out_size)
{
    const float* x_mod = (const float*)d_in[0];
    const float* x_back= (const float*)d_in[1];
    const float* mask  = (const float*)d_in[2];
    const float* wq = (const float*)d_in[3];
    const float* wk = (const float*)d_in[4];
    const float* wv = (const float*)d_in[5];
    const float* wo = (const float*)d_in[6];
    const float* cross_ln_w = (const float*)d_in[7];
    const float* fb_w = (const float*)d_in[8];
    const float* fb_g = (const float*)d_in[9];
    const float* fb_gb= (const float*)d_in[10];
    const float* dr_w = (const float*)d_in[11];
    const float* dr_g = (const float*)d_in[12];
    const float* dr_gb= (const float*)d_in[13];
    const float* in_ln_w   = (const float*)d_in[14];
    const float* post_ln_w = (const float*)d_in[15];
    const float* w_gate = (const float*)d_in[16];
    const float* w_up   = (const float*)d_in[17];
    const float* w_down = (const float*)d_in[18];

    float* outx = (float*)d_out;
    float* outd = outx + (size_t)ROWS * HID;

    float *q,*k,*v,*att,*mod,*t1,*t2,*x,*sc,*gg,*uu;
    bf16 *wh,*wl,*ah,*al,*pph,*ppl;
    cudaGetSymbolAddress((void**)&q, g_q);   cudaGetSymbolAddress((void**)&k, g_k);
    cudaGetSymbolAddress((void**)&v, g_v);   cudaGetSymbolAddress((void**)&att, g_att);
    cudaGetSymbolAddress((void**)&mod, g_mod); cudaGetSymbolAddress((void**)&t1, g_t1);
    cudaGetSymbolAddress((void**)&t2, g_t2); cudaGetSymbolAddress((void**)&x, g_x);
    cudaGetSymbolAddress((void**)&sc, g_sc); cudaGetSymbolAddress((void**)&gg, g_gate);
    cudaGetSymbolAddress((void**)&uu, g_up);
    cudaGetSymbolAddress((void**)&wh, g_wh); cudaGetSymbolAddress((void**)&wl, g_wl);
    cudaGetSymbolAddress((void**)&ah, g_ah); cudaGetSymbolAddress((void**)&al, g_al);
    cudaGetSymbolAddress((void**)&pph, g_ph); cudaGetSymbolAddress((void**)&ppl, g_pl);

    cudaFuncSetAttribute(mma_gemm, cudaFuncAttributeMaxDynamicSharedMemorySize, TC_SMEM);

    const float ATT_SCALE = 0.08838834764831845f;
    const int n4h = (int)(RH/4), n4f = (int)(GGN/4), n4w = (int)(H2/4), n4ff = (int)(FF2/4);
    const dim3 B256(256);

    auto gemm = [&](const bf16* pah, const bf16* pal, const bf16* pbh, const bf16* pbl,
                    float* c, int M, int N, int K, int lda, int ldb, int ldc, float alpha,
                    int gz, int zdiv, ll saa, ll sab, ll sba, ll sbb, ll sca, ll scb) {
        dim3 g(N/128, M/128, gz);
        mma_gemm<<<g, 256, TC_SMEM>>>(pah, pal, pbh, pbl, c, K, lda, ldb, ldc, alpha,
                                      zdiv, saa, sab, sba, sbb, sca, scb);
    };

    // ---- splits of inputs ----
    split_kernel<<<n4h/256, B256>>>(x_mod,  ah+OXM, al+OXM, n4h);
    split_kernel<<<n4h/256, B256>>>(x_back, ah+OXB, al+OXB, n4h);
    rmsnorm_split<<<ROWS, B256>>>(x_mod, cross_ln_w, ah+OQN, al+OQN);
    split_kernel<<<n4w/256, B256>>>(wq,   wh+OWQ,  wl+OWQ,  n4w);
    split_kernel<<<n4w/256, B256>>>(wk,   wh+OWK,  wl+OWK,  n4w);
    split_kernel<<<n4w/256, B256>>>(wv,   wh+OWV,  wl+OWV,  n4w);
    split_kernel<<<n4w/256, B256>>>(wo,   wh+OWO,  wl+OWO,  n4w);
    split_kernel<<<n4w/256, B256>>>(fb_w, wh+OFBW, wl+OFBW, n4w);
    split_kernel<<<n4w/256, B256>>>(fb_g, wh+OFBG, wl+OFBG, n4w);
    split_kernel<<<n4w/256, B256>>>(dr_w, wh+ODRW, wl+ODRW, n4w);
    split_kernel<<<n4w/256, B256>>>(dr_g, wh+ODRG, wl+ODRG, n4w);
    split_kernel<<<n4ff/256, B256>>>(w_gate, wh+OWG, wl+OWG, n4ff);
    split_kernel<<<n4ff/256, B256>>>(w_up,   wh+OWU, wl+OWU, n4ff);
    split_kernel<<<n4ff/256, B256>>>(w_down, wh+OWD, wl+OWD, n4ff);

    // ---- q/k/v projections ----
    gemm(ah+OQN, al+OQN, wh+OWQ, wl+OWQ, q, ROWS, HID, HID, HID, HID, HID, 1.f, 1,1, 0,0,0,0,0,0);
    gemm(ah+OXB, al+OXB, wh+OWK, wl+OWK, k, ROWS, HID, HID, HID, HID, HID, 1.f, 1,1, 0,0,0,0,0,0);
    gemm(ah+OXB, al+OXB, wh+OWV, wl+OWV, v, ROWS, HID, HID, HID, HID, HID, 1.f, 1,1, 0,0,0,0,0,0);

    const int ropeN = ROWS * NHEAD * 64;
    rope_split<<<(ropeN+255)/256, B256>>>(q, ah+OQ,  al+OQ);
    rope_split<<<(ropeN+255)/256, B256>>>(k, ah+OK2, al+OK2);
    vtrans_kernel<<<dim3(SEQ/32, HDIM/32, BATCH*NHEAD), dim3(32,8)>>>(v, ah+OVT, al+OVT);

    // ---- attention ----
    gemm(ah+OQ, al+OQ, ah+OK2, al+OK2, sc, SEQ, SEQ, HDIM, HID, HID, SEQ, ATT_SCALE,
         BATCH*NHEAD, NHEAD, (ll)SEQ*HID, 128, (ll)SEQ*HID, 128,
         (ll)NHEAD*SEQ*SEQ, (ll)SEQ*SEQ);
    softmax_split<<<dim3(SEQ, BATCH*NHEAD), B256>>>(sc, mask, pph, ppl);
    gemm(pph, ppl, ah+OVT, al+OVT, att, SEQ, HDIM, SEQ, SEQ, SEQ, HID, 1.f,
         BATCH*NHEAD, NHEAD, (ll)NHEAD*SEQ*SEQ, (ll)SEQ*SEQ,
         (ll)NHEAD*HDIM*SEQ, (ll)HDIM*SEQ, (ll)SEQ*HID, 128);
    split_kernel<<<n4h/256, B256>>>(att, ah+OATT, al+OATT, n4h);
    gemm(ah+OATT, al+OATT, wh+OWO, wl+OWO, mod, ROWS, HID, HID, HID, HID, HID, 1.f, 1,1, 0,0,0,0,0,0);

    // ---- feedback highway -> delta ----
    gemm(ah+OXM, al+OXM, wh+OFBG, wl+OFBG, t1, ROWS, HID, HID, HID, HID, HID, 1.f, 1,1, 0,0,0,0,0,0);
    gemm(ah+OXM, al+OXM, wh+OFBW, wl+OFBW, t2, ROWS, HID, HID, HID, HID, HID, 1.f, 1,1, 0,0,0,0,0,0);
    highway_kernel<<<n4h/256, B256>>>(t1, t2, fb_gb, outd, n4h);

    // ---- driver highway + combine ----
    gemm(ah+OXB, al+OXB, wh+ODRG, wl+ODRG, t1, ROWS, HID, HID, HID, HID, HID, 1.f, 1,1, 0,0,0,0,0,0);
    gemm(ah+OXB, al+OXB, wh+ODRW, wl+ODRW, t2, ROWS, HID, HID, HID, HID, HID, 1.f, 1,1, 0,0,0,0,0,0);
    combinex_kernel<<<n4h/256, B256>>>(x_mod, mod, t1, t2, dr_gb, x, n4h);

    // ---- decoder ----
    rmsadd_kernel<<<ROWS, B256>>>(x, in_ln_w);
    rmsnorm_split<<<ROWS, B256>>>(x, post_ln_w, ah+OHB, al+OHB);
    gemm(ah+OHB, al+OHB, wh+OWG, wl+OWG, gg, ROWS, FFD, HID, HID, HID, FFD, 1.f, 1,1, 0,0,0,0,0,0);
    gemm(ah+OHB, al+OHB, wh+OWU, wl+OWU, uu, ROWS, FFD, HID, HID, HID, FFD, 1.f, 1,1, 0,0,0,0,0,0);
    silumul_split<<<n4f/256, B256>>>(gg, uu, ah+OGG, al+OGG, n4f);
    gemm(ah+OGG, al+OGG, wh+OWD, wl+OWD, mod, ROWS, HID, FFD, FFD, FFD, HID, 1.f, 1,1, 0,0,0,0,0,0);
    add2_kernel<<<n4h/256, B256>>>(x, mod, outx, n4h);
}

// round 7
// speedup vs baseline: 1.0436x; 1.0034x over previous
#include <cuda_runtime.h>
#include <cuda_bf16.h>
#include <cstdint>
#include <math.h>
using bf16 = __nv_bfloat16;
typedef long long ll;

#define BATCH 2
#define SEQ 2048
#define HID 2048
#define NHEAD 16
#define HDIM 128
#define FFD 8192
#define ROWS 4096
#define RMS_EPS 1e-5f
#define RH 8388608LL
#define H2 4194304LL
#define FF2 16777216LL
#define GGN 33554432LL
#define SCN 134217728LL

// ------------------------- scratch -------------------------
__device__ float g_q[RH], g_k[RH], g_v[RH], g_att[RH], g_mod[RH], g_t1[RH], g_t2[RH], g_x[RH];
__device__ float g_sc[SCN];
__device__ float g_gate[GGN], g_up[GGN];
__device__ bf16 g_wh[8*H2+3*FF2], g_wl[8*H2+3*FF2];
__device__ bf16 g_ah[8*RH+GGN],  g_al[8*RH+GGN];
__device__ bf16 g_ph[SCN], g_pl[SCN];

// weight arena offsets
#define OWQ  (0*H2)
#define OWK  (1*H2)
#define OWV  (2*H2)
#define OWO  (3*H2)
#define OFBW (4*H2)
#define OFBG (5*H2)
#define ODRW (6*H2)
#define ODRG (7*H2)
#define OWG  (8*H2)
#define OWU  (8*H2+FF2)
#define OWD  (8*H2+2*FF2)
// activation arena offsets
#define OQN  (0*RH)
#define OXB  (1*RH)
#define OXM  (2*RH)
#define OQ   (3*RH)
#define OK2  (4*RH)
#define OVT  (5*RH)
#define OATT (6*RH)
#define OHB  (7*RH)
#define OGG  (8*RH)

// ------------------------- PTX helpers -------------------------
__device__ __forceinline__ uint32_t smem_u32(const void* p) {
    uint32_t a;
    asm("{ .reg .u64 t; cvta.to.shared.u64 t, %1; cvt.u32.u64 %0, t; }" : "=r"(a) : "l"(p));
    return a;
}
__device__ __forceinline__ void cp16(uint32_t s, const void* g) {
    asm volatile("cp.async.cg.shared.global [%0], [%1], 16;" :: "r"(s), "l"(g));
}
__device__ __forceinline__ void cpcommit() { asm volatile("cp.async.commit_group;" ::: "memory"); }
__device__ __forceinline__ void cpwait0()  { asm volatile("cp.async.wait_group 0;" ::: "memory"); }
__device__ __forceinline__ void cpwait1()  { asm volatile("cp.async.wait_group 1;" ::: "memory"); }

__device__ __forceinline__ void ldsm4(uint32_t* r, uint32_t addr) {
    asm volatile("ldmatrix.sync.aligned.m8n8.x4.shared.b16 {%0,%1,%2,%3}, [%4];"
        : "=r"(r[0]), "=r"(r[1]), "=r"(r[2]), "=r"(r[3]) : "r"(addr));
}
__device__ __forceinline__ void mma16816(float* c, const uint32_t* a, uint32_t b0, uint32_t b1) {
    asm volatile("mma.sync.aligned.m16n8k16.row.col.f32.bf16.bf16.f32 "
        "{%0,%1,%2,%3}, {%4,%5,%6,%7}, {%8,%9}, {%0,%1,%2,%3};"
        : "+f"(c[0]), "+f"(c[1]), "+f"(c[2]), "+f"(c[3])
        : "r"(a[0]), "r"(a[1]), "r"(a[2]), "r"(a[3]), "r"(b0), "r"(b1));
}
__device__ __forceinline__ void split2(float x, bf16& h, bf16& l) {
    h = __float2bfloat16(x);
    l = __float2bfloat16(x - __bfloat162float(h));
}

// ---------------------------------------------------------------------------
// bf16x3 HMMA GEMM: C = alpha*(A @ B^T). A:[M,K] lda, B:[N,K] ldb, K-major.
// 128x128 CTA tile, KTILE=32, 3-stage cp.async (96KB -> 2 CTAs/SM),
// 8 warps (warp tile 32x64), 64B rows, xor-16B swizzle.
// HMMA issued over nt-PAIRS: 24 HMMA across 8 accumulators => same-acc reuse
// distance 8 (kills accumulator RAW stalls).
// ---------------------------------------------------------------------------
#define STG 32768
#define TC_SMEM (3*STG)

__global__ __launch_bounds__(256, 2)
void mma_gemm(const bf16* __restrict__ Ahg, const bf16* __restrict__ Alg,
              const bf16* __restrict__ Bhg, const bf16* __restrict__ Blg,
              float* __restrict__ Cg,
              int K, int lda, int ldb, int ldc, float alpha,
              int zdiv, ll sAa, ll sAb, ll sBa, ll sBb, ll sCa, ll sCb)
{
    extern __shared__ char smem_raw[];
    const uint32_t tiles = smem_u32(smem_raw);
    const int tid = threadIdx.x, wid = tid >> 5, lane = tid & 31;
    const int wm = wid & 3, wn = wid >> 2;   // 4x2 warp grid, warp tile 32x64

    const int z = blockIdx.z;
    const ll aoff = (ll)(z / zdiv) * sAa + (ll)(z % zdiv) * sAb;
    const ll boff = (ll)(z / zdiv) * sBa + (ll)(z % zdiv) * sBb;
    const ll coff = (ll)(z / zdiv) * sCa + (ll)(z % zdiv) * sCb;
    const bf16* Ah = Ahg + aoff; const bf16* Al = Alg + aoff;
    const bf16* Bh = Bhg + boff; const bf16* Bl = Blg + boff;

    const int bm = blockIdx.y << 7, bn = blockIdx.x << 7;
    const int nk = K >> 5;

    auto load_stage = [&](int kt) {
        const uint32_t st = tiles + (uint32_t)(kt % 3) * STG;
        const ll kb = (ll)kt * 32;
#pragma unroll
        for (int i = tid; i < 512; i += 256) {
            const int r = i >> 2, c = i & 3;
            const uint32_t sw = (uint32_t)r * 64u + (uint32_t)((c ^ ((r >> 1) & 3)) << 4);
            const ll ao = (ll)(bm + r) * lda + kb + c * 8;
            const ll bo = (ll)(bn + r) * ldb + kb + c * 8;
            cp16(st         + sw, Ah + ao);
            cp16(st + 8192  + sw, Al + ao);
            cp16(st + 16384 + sw, Bh + bo);
            cp16(st + 24576 + sw, Bl + bo);
        }
        cpcommit();
    };

    float acc[2][8][4];
#pragma unroll
    for (int i = 0; i < 2; i++)
#pragma unroll
        for (int j = 0; j < 8; j++)
#pragma unroll
            for (int t = 0; t < 4; t++) acc[i][j][t] = 0.f;

    const int aRow  = wm * 32 + (lane & 15);
    const int aCpar = lane >> 4;
    const int bNadd = ((lane >> 4) << 3) + (lane & 7);
    const int bCpar = (lane >> 3) & 1;

    load_stage(0);
    if (nk > 1) load_stage(1); else cpcommit();

    for (int kt = 0; kt < nk; kt++) {
        if (kt >= nk - 2) cpwait0(); else cpwait1();
        __syncthreads();
        if (kt + 2 < nk) load_stage(kt + 2); else cpcommit();

        const uint32_t st = tiles + (uint32_t)(kt % 3) * STG;
#pragma unroll
        for (int ks = 0; ks < 2; ks++) {
            uint32_t ahf[2][4], alf[2][4];
#pragma unroll
            for (int mt = 0; mt < 2; mt++) {
                const int row = aRow + mt * 16;
                const int ch = ks * 2 + aCpar;
                const uint32_t ad = st + (uint32_t)row * 64u + (uint32_t)((ch ^ ((row >> 1) & 3)) << 4);
                ldsm4(ahf[mt], ad);
                ldsm4(alf[mt], ad + 8192);
            }
#pragma unroll
            for (int np = 0; np < 2; np++) {
                uint32_t bh[2][4], bl[2][4];
#pragma unroll
                for (int t = 0; t < 2; t++) {
                    const int nt = np * 2 + t;
                    const int row = wn * 64 + nt * 16 + bNadd;
                    const int ch = ks * 2 + bCpar;
                    const uint32_t bd = st + 16384u + (uint32_t)row * 64u + (uint32_t)((ch ^ ((row >> 1) & 3)) << 4);
                    ldsm4(bh[t], bd);
                    ldsm4(bl[t], bd + 8192);
                }
                // 24 HMMA over 8 accumulators; same-acc reuse distance = 8
#pragma unroll
                for (int t = 0; t < 2; t++) {
                    const int nb = (np * 2 + t) * 2;
                    mma16816(acc[0][nb],   ahf[0], bh[t][0], bh[t][1]);
                    mma16816(acc[0][nb+1], ahf[0], bh[t][2], bh[t][3]);
                    mma16816(acc[1][nb],   ahf[1], bh[t][0], bh[t][1]);
                    mma16816(acc[1][nb+1], ahf[1], bh[t][2], bh[t][3]);
                }
#pragma unroll
                for (int t = 0; t < 2; t++) {
                    const int nb = (np * 2 + t) * 2;
                    mma16816(acc[0][nb],   ahf[0], bl[t][0], bl[t][1]);
                    mma16816(acc[0][nb+1], ahf[0], bl[t][2], bl[t][3]);
                    mma16816(acc[1][nb],   ahf[1], bl[t][0], bl[t][1]);
                    mma16816(acc[1][nb+1], ahf[1], bl[t][2], bl[t][3]);
                }
#pragma unroll
                for (int t = 0; t < 2; t++) {
                    const int nb = (np * 2 + t) * 2;
                    mma16816(acc[0][nb],   alf[0], bh[t][0], bh[t][1]);
                    mma16816(acc[0][nb+1], alf[0], bh[t][2], bh[t][3]);
                    mma16816(acc[1][nb],   alf[1], bh[t][0], bh[t][1]);
                    mma16816(acc[1][nb+1], alf[1], bh[t][2], bh[t][3]);
                }
            }
        }
    }

    const int erow = bm + wm * 32 + (lane >> 2);
    const int ecol = bn + wn * 64 + (lane & 3) * 2;
#pragma unroll
    for (int mt = 0; mt < 2; mt++) {
#pragma unroll
        for (int j = 0; j < 8; j++) {
            float* p0 = Cg + coff + (ll)(erow + mt*16)     * ldc + ecol + j*8;
            float* p1 = Cg + coff + (ll)(erow + mt*16 + 8) * ldc + ecol + j*8;
            *(float2*)p0 = make_float2(acc[mt][j][0]*alpha, acc[mt][j][1]*alpha);
            *(float2*)p1 = make_float2(acc[mt][j][2]*alpha, acc[mt][j][3]*alpha);
        }
    }
}

// ------------------------- reductions -------------------------
__device__ __forceinline__ float wsum(float v) {
#pragma unroll
    for (int o = 16; o; o >>= 1) v += __shfl_xor_sync(0xffffffffu, v, o);
    return v;
}
__device__ __forceinline__ float wmax(float v) {
#pragma unroll
    for (int o = 16; o; o >>= 1) v = fmaxf(v, __shfl_xor_sync(0xffffffffu, v, o));
    return v;
}
__device__ __forceinline__ float bsum(float v) {
    __shared__ float sh[8];
    v = wsum(v); __syncthreads();
    if ((threadIdx.x & 31) == 0) sh[threadIdx.x >> 5] = v;
    __syncthreads();
    float r = 0.f;
#pragma unroll
    for (int i = 0; i < 8; i++) r += sh[i];
    return r;
}
__device__ __forceinline__ float bmax(float v) {
    __shared__ float sh[8];
    v = wmax(v); __syncthreads();
    if ((threadIdx.x & 31) == 0) sh[threadIdx.x >> 5] = v;
    __syncthreads();
    float r = sh[0];
#pragma unroll
    for (int i = 1; i < 8; i++) r = fmaxf(r, sh[i]);
    return r;
}

// ------------------------- elementwise kernels -------------------------
__global__ __launch_bounds__(256)
void split_kernel(const float* __restrict__ s, bf16* __restrict__ oh, bf16* __restrict__ ol, int n4)
{
    const int i = blockIdx.x * 256 + threadIdx.x;
    if (i >= n4) return;
    float4 v = ((const float4*)s)[i];
    bf16 h0,l0,h1,l1,h2,l2,h3,l3;
    split2(v.x,h0,l0); split2(v.y,h1,l1); split2(v.z,h2,l2); split2(v.w,h3,l3);
    ((__nv_bfloat162*)oh)[2*i]   = __nv_bfloat162(h0,h1);
    ((__nv_bfloat162*)oh)[2*i+1] = __nv_bfloat162(h2,h3);
    ((__nv_bfloat162*)ol)[2*i]   = __nv_bfloat162(l0,l1);
    ((__nv_bfloat162*)ol)[2*i+1] = __nv_bfloat162(l2,l3);
}

__global__ __launch_bounds__(256)
void rmsnorm_split(const float* __restrict__ in, const float* __restrict__ w,
                   bf16* __restrict__ oh, bf16* __restrict__ ol)
{
    const ll base = (ll)blockIdx.x * HID;
    const float4* xin = (const float4*)(in + base);
    float ss = 0.f;
    for (int i = threadIdx.x; i < HID/4; i += 256) {
        float4 v = xin[i];
        ss += v.x*v.x + v.y*v.y + v.z*v.z + v.w*v.w;
    }
    ss = bsum(ss);
    const float r = rsqrtf(ss * (1.f/HID) + RMS_EPS);
    for (int i = threadIdx.x; i < HID/4; i += 256) {
        float4 v = xin[i];
        float4 ww = ((const float4*)w)[i];
        bf16 h0,l0,h1,l1,h2,l2,h3,l3;
        split2(v.x*r*ww.x,h0,l0); split2(v.y*r*ww.y,h1,l1);
        split2(v.z*r*ww.z,h2,l2); split2(v.w*r*ww.w,h3,l3);
        ((__nv_bfloat162*)(oh + base))[2*i]   = __nv_bfloat162(h0,h1);
        ((__nv_bfloat162*)(oh + base))[2*i+1] = __nv_bfloat162(h2,h3);
        ((__nv_bfloat162*)(ol + base))[2*i]   = __nv_bfloat162(l0,l1);
        ((__nv_bfloat162*)(ol + base))[2*i+1] = __nv_bfloat162(l2,l3);
    }
}

__global__ __launch_bounds__(256)
void rmsadd_kernel(float* __restrict__ x, const float* __restrict__ w)
{
    const ll base = (ll)blockIdx.x * HID;
    float4* xp = (float4*)(x + base);
    float ss = 0.f;
    for (int i = threadIdx.x; i < HID/4; i += 256) {
        float4 v = xp[i];
        ss += v.x*v.x + v.y*v.y + v.z*v.z + v.w*v.w;
    }
    ss = bsum(ss);
    const float r = rsqrtf(ss * (1.f/HID) + RMS_EPS);
    for (int i = threadIdx.x; i < HID/4; i += 256) {
        float4 v = xp[i];
        float4 ww = ((const float4*)w)[i];
        xp[i] = make_float4(v.x*(1.f+r*ww.x), v.y*(1.f+r*ww.y), v.z*(1.f+r*ww.z), v.w*(1.f+r*ww.w));
    }
}

__global__ void rope_split(const float* __restrict__ src, bf16* __restrict__ oh, bf16* __restrict__ ol)
{
    const int idx = blockIdx.x * blockDim.x + threadIdx.x;
    if (idx >= ROWS * NHEAD * 64) return;
    const int j = idx & 63, h = (idx >> 6) & (NHEAD-1), row = idx >> 10;
    const int pos = row & (SEQ - 1);
    const float inv = (float)exp(-(double)(2*j) / (double)HDIM * log(10000.0));
    float s_, c;
    sincosf((float)pos * inv, &s_, &c);
    const ll p0 = (ll)row * HID + h * HDIM + j;
    const float q0 = src[p0], q1 = src[p0 + 64];
    bf16 hh, lll;
    split2(q0*c - q1*s_, hh, lll); oh[p0]    = hh; ol[p0]    = lll;
    split2(q1*c + q0*s_, hh, lll); oh[p0+64] = hh; ol[p0+64] = lll;
}

// V transpose-split: v[b*SEQ+s][h*128+d] -> vt[(z*128+d)*SEQ + s], z=b*16+h
__global__ void vtrans_kernel(const float* __restrict__ v, bf16* __restrict__ oh, bf16* __restrict__ ol)
{
    __shared__ float t[32][33];
    const int z = blockIdx.z, b = z >> 4, h = z & 15;
    const int s0 = blockIdx.x * 32, d0 = blockIdx.y * 32;
    const int tx = threadIdx.x, ty = threadIdx.y;
#pragma unroll
    for (int i = 0; i < 4; i++) {
        const int s = s0 + ty + i*8;
        t[ty + i*8][tx] = v[((ll)(b*SEQ + s)) * HID + h*HDIM + d0 + tx];
    }
    __syncthreads();
#pragma unroll
    for (int i = 0; i < 4; i++) {
        const int d = d0 + ty + i*8;
        const float x = t[tx][ty + i*8];
        bf16 hh, lll; split2(x, hh, lll);
        const ll o = ((ll)z * HDIM + d) * SEQ + s0 + tx;
        oh[o] = hh; ol[o] = lll;
    }
}

__global__ __launch_bounds__(256)
void softmax_split(const float* __restrict__ sc, const float* __restrict__ mask,
                   bf16* __restrict__ ph, bf16* __restrict__ pl)
{
    const ll off = ((ll)blockIdx.y * SEQ + blockIdx.x) * SEQ;
    const float* p = sc + off;
    const float* mp = mask + (ll)blockIdx.x * SEQ;
    const int t = threadIdx.x * 8;
    float v[8];
    float4 a = *(const float4*)(p + t), b = *(const float4*)(p + t + 4);
    float4 ma = *(const float4*)(mp + t), mb = *(const float4*)(mp + t + 4);
    v[0]=a.x+ma.x; v[1]=a.y+ma.y; v[2]=a.z+ma.z; v[3]=a.w+ma.w;
    v[4]=b.x+mb.x; v[5]=b.y+mb.y; v[6]=b.z+mb.z; v[7]=b.w+mb.w;
    float mx = v[0];
#pragma unroll
    for (int i = 1; i < 8; i++) mx = fmaxf(mx, v[i]);
    mx = bmax(mx);
    float s = 0.f;
#pragma unroll
    for (int i = 0; i < 8; i++) { v[i] = expf(v[i] - mx); s += v[i]; }
    s = bsum(s);
    const float inv = 1.f / s;
    __nv_bfloat162 hv[4], lv[4];
#pragma unroll
    for (int i = 0; i < 4; i++) {
        bf16 h0,l0,h1,l1;
        split2(v[2*i]*inv, h0, l0); split2(v[2*i+1]*inv, h1, l1);
        hv[i] = __nv_bfloat162(h0,h1); lv[i] = __nv_bfloat162(l0,l1);
    }
#pragma unroll
    for (int i = 0; i < 4; i++) {
        ((__nv_bfloat162*)(ph + off + t))[i] = hv[i];
        ((__nv_bfloat162*)(pl + off + t))[i] = lv[i];
    }
}

__device__ __forceinline__ float sigm(float z) { return 1.f / (1.f + expf(-z)); }

__global__ void highway_kernel(const float* __restrict__ g, const float* __restrict__ hh,
                               const float* __restrict__ bias, float* __restrict__ out, int n4)
{
    const int i = blockIdx.x * blockDim.x + threadIdx.x;
    if (i >= n4) return;
    float4 gv = ((const float4*)g)[i], hv = ((const float4*)hh)[i];
    float4 bv = ((const float4*)bias)[i & (HID/4 - 1)];
    ((float4*)out)[i] = make_float4(hv.x*sigm(gv.x+bv.x), hv.y*sigm(gv.y+bv.y),
                                    hv.z*sigm(gv.z+bv.z), hv.w*sigm(gv.w+bv.w));
}

__global__ void combinex_kernel(const float* __restrict__ xm, const float* __restrict__ mod,
                                const float* __restrict__ g, const float* __restrict__ hh,
                                const float* __restrict__ bias, float* __restrict__ out, int n4)
{
    const int i = blockIdx.x * blockDim.x + threadIdx.x;
    if (i >= n4) return;
    float4 xv = ((const float4*)xm)[i], mv = ((const float4*)mod)[i];
    float4 gv = ((const float4*)g)[i], hv = ((const float4*)hh)[i];
    float4 bv = ((const float4*)bias)[i & (HID/4 - 1)];
    ((float4*)out)[i] = make_float4(xv.x+mv.x+hv.x*sigm(gv.x+bv.x), xv.y+mv.y+hv.y*sigm(gv.y+bv.y),
                                    xv.z+mv.z+hv.z*sigm(gv.z+bv.z), xv.w+mv.w+hv.w*sigm(gv.w+bv.w));
}

__global__ void silumul_split(const float* __restrict__ g, const float* __restrict__ u,
                              bf16* __restrict__ oh, bf16* __restrict__ ol, int n4)
{
    const int i = blockIdx.x * blockDim.x + threadIdx.x;
    if (i >= n4) return;
    float4 gv = ((const float4*)g)[i], uv = ((const float4*)u)[i];
    float r0 = gv.x*sigm(gv.x)*uv.x, r1 = gv.y*sigm(gv.y)*uv.y;
    float r2 = gv.z*sigm(gv.z)*uv.z, r3 = gv.w*sigm(gv.w)*uv.w;
    bf16 h0,l0,h1,l1,h2,l2,h3,l3;
    split2(r0,h0,l0); split2(r1,h1,l1); split2(r2,h2,l2); split2(r3,h3,l3);
    ((__nv_bfloat162*)oh)[2*i]   = __nv_bfloat162(h0,h1);
    ((__nv_bfloat162*)oh)[2*i+1] = __nv_bfloat162(h2,h3);
    ((__nv_bfloat162*)ol)[2*i]   = __nv_bfloat162(l0,l1);
    ((__nv_bfloat162*)ol)[2*i+1] = __nv_bfloat162(l2,l3);
}

__global__ void add2_kernel(const float* __restrict__ a, const float* __restrict__ b,
                            float* __restrict__ out, int n4)
{
    const int i = blockIdx.x * blockDim.x + threadIdx.x;
    if (i >= n4) return;
    float4 av = ((const float4*)a)[i], bv = ((const float4*)b)[i];
    ((float4*)out)[i] = make_float4(av.x+bv.x, av.y+bv.y, av.z+bv.z, av.w+bv.w);
}

// ------------------------- launch -------------------------
extern "C" void kernel_launch(void* const* d_in, const int* in_sizes, int n_in,
                              void* d_out, int out_size)
{
    const float* x_mod = (const float*)d_in[0];
    const float* x_back= (const float*)d_in[1];
    const float* mask  = (const float*)d_in[2];
    const float* wq = (const float*)d_in[3];
    const float* wk = (const float*)d_in[4];
    const float* wv = (const float*)d_in[5];
    const float* wo = (const float*)d_in[6];
    const float* cross_ln_w = (const float*)d_in[7];
    const float* fb_w = (const float*)d_in[8];
    const float* fb_g = (const float*)d_in[9];
    const float* fb_gb= (const float*)d_in[10];
    const float* dr_w = (const float*)d_in[11];
    const float* dr_g = (const float*)d_in[12];
    const float* dr_gb= (const float*)d_in[13];
    const float* in_ln_w   = (const float*)d_in[14];
    const float* post_ln_w = (const float*)d_in[15];
    const float* w_gate = (const float*)d_in[16];
    const float* w_up   = (const float*)d_in[17];
    const float* w_down = (const float*)d_in[18];

    float* outx = (float*)d_out;
    float* outd = outx + (size_t)ROWS * HID;

    float *q,*k,*v,*att,*mod,*t1,*t2,*x,*sc,*gg,*uu;
    bf16 *wh,*wl,*ah,*al,*pph,*ppl;
    cudaGetSymbolAddress((void**)&q, g_q);   cudaGetSymbolAddress((void**)&k, g_k);
    cudaGetSymbolAddress((void**)&v, g_v);   cudaGetSymbolAddress((void**)&att, g_att);
    cudaGetSymbolAddress((void**)&mod, g_mod); cudaGetSymbolAddress((void**)&t1, g_t1);
    cudaGetSymbolAddress((void**)&t2, g_t2); cudaGetSymbolAddress((void**)&x, g_x);
    cudaGetSymbolAddress((void**)&sc, g_sc); cudaGetSymbolAddress((void**)&gg, g_gate);
    cudaGetSymbolAddress((void**)&uu, g_up);
    cudaGetSymbolAddress((void**)&wh, g_wh); cudaGetSymbolAddress((void**)&wl, g_wl);
    cudaGetSymbolAddress((void**)&ah, g_ah); cudaGetSymbolAddress((void**)&al, g_al);
    cudaGetSymbolAddress((void**)&pph, g_ph); cudaGetSymbolAddress((void**)&ppl, g_pl);

    cudaFuncSetAttribute(mma_gemm, cudaFuncAttributeMaxDynamicSharedMemorySize, TC_SMEM);

    const float ATT_SCALE = 0.08838834764831845f;
    const int n4h = (int)(RH/4), n4f = (int)(GGN/4), n4w = (int)(H2/4), n4ff = (int)(FF2/4);
    const dim3 B256(256);

    auto gemm = [&](const bf16* pah, const bf16* pal, const bf16* pbh, const bf16* pbl,
                    float* c, int M, int N, int K, int lda, int ldb, int ldc, float alpha,
                    int gz, int zdiv, ll saa, ll sab, ll sba, ll sbb, ll sca, ll scb) {
        dim3 g(N/128, M/128, gz);
        mma_gemm<<<g, 256, TC_SMEM>>>(pah, pal, pbh, pbl, c, K, lda, ldb, ldc, alpha,
                                      zdiv, saa, sab, sba, sbb, sca, scb);
    };

    // ---- first 5 launches chosen so launch #6 (ncu -s 5 -c 1) is a GEMM ----
    rmsnorm_split<<<ROWS, B256>>>(x_mod, cross_ln_w, ah+OQN, al+OQN);   // 1
    split_kernel<<<n4w/256, B256>>>(wq,   wh+OWQ,  wl+OWQ,  n4w);       // 2
    split_kernel<<<n4h/256, B256>>>(x_back, ah+OXB, al+OXB, n4h);       // 3
    split_kernel<<<n4w/256, B256>>>(wk,   wh+OWK,  wl+OWK,  n4w);       // 4
    split_kernel<<<n4w/256, B256>>>(wv,   wh+OWV,  wl+OWV,  n4w);       // 5
    gemm(ah+OQN, al+OQN, wh+OWQ, wl+OWQ, q, ROWS, HID, HID, HID, HID, HID, 1.f, 1,1, 0,0,0,0,0,0); // 6 <- profiled
    gemm(ah+OXB, al+OXB, wh+OWK, wl+OWK, k, ROWS, HID, HID, HID, HID, HID, 1.f, 1,1, 0,0,0,0,0,0);
    gemm(ah+OXB, al+OXB, wh+OWV, wl+OWV, v, ROWS, HID, HID, HID, HID, HID, 1.f, 1,1, 0,0,0,0,0,0);

    // remaining splits
    split_kernel<<<n4h/256, B256>>>(x_mod,  ah+OXM, al+OXM, n4h);
    split_kernel<<<n4w/256, B256>>>(wo,   wh+OWO,  wl+OWO,  n4w);
    split_kernel<<<n4w/256, B256>>>(fb_w, wh+OFBW, wl+OFBW, n4w);
    split_kernel<<<n4w/256, B256>>>(fb_g, wh+OFBG, wl+OFBG, n4w);
    split_kernel<<<n4w/256, B256>>>(dr_w, wh+ODRW, wl+ODRW, n4w);
    split_kernel<<<n4w/256, B256>>>(dr_g, wh+ODRG, wl+ODRG, n4w);
    split_kernel<<<n4ff/256, B256>>>(w_gate, wh+OWG, wl+OWG, n4ff);
    split_kernel<<<n4ff/256, B256>>>(w_up,   wh+OWU, wl+OWU, n4ff);
    split_kernel<<<n4ff/256, B256>>>(w_down, wh+OWD, wl+OWD, n4ff);

    const int ropeN = ROWS * NHEAD * 64;
    rope_split<<<(ropeN+255)/256, B256>>>(q, ah+OQ,  al+OQ);
    rope_split<<<(ropeN+255)/256, B256>>>(k, ah+OK2, al+OK2);
    vtrans_kernel<<<dim3(SEQ/32, HDIM/32, BATCH*NHEAD), dim3(32,8)>>>(v, ah+OVT, al+OVT);

    // ---- attention ----
    gemm(ah+OQ, al+OQ, ah+OK2, al+OK2, sc, SEQ, SEQ, HDIM, HID, HID, SEQ, ATT_SCALE,
         BATCH*NHEAD, NHEAD, (ll)SEQ*HID, 128, (ll)SEQ*HID, 128,
         (ll)NHEAD*SEQ*SEQ, (ll)SEQ*SEQ);
    softmax_split<<<dim3(SEQ, BATCH*NHEAD), B256>>>(sc, mask, pph, ppl);
    gemm(pph, ppl, ah+OVT, al+OVT, att, SEQ, HDIM, SEQ, SEQ, SEQ, HID, 1.f,
         BATCH*NHEAD, NHEAD, (ll)NHEAD*SEQ*SEQ, (ll)SEQ*SEQ,
         (ll)NHEAD*HDIM*SEQ, (ll)HDIM*SEQ, (ll)SEQ*HID, 128);
    split_kernel<<<n4h/256, B256>>>(att, ah+OATT, al+OATT, n4h);
    gemm(ah+OATT, al+OATT, wh+OWO, wl+OWO, mod, ROWS, HID, HID, HID, HID, HID, 1.f, 1,1, 0,0,0,0,0,0);

    // ---- feedback highway -> delta ----
    gemm(ah+OXM, al+OXM, wh+OFBG, wl+OFBG, t1, ROWS, HID, HID, HID, HID, HID, 1.f, 1,1, 0,0,0,0,0,0);
    gemm(ah+OXM, al+OXM, wh+OFBW, wl+OFBW, t2, ROWS, HID, HID, HID, HID, HID, 1.f, 1,1, 0,0,0,0,0,0);
    highway_kernel<<<n4h/256, B256>>>(t1, t2, fb_gb, outd, n4h);

    // ---- driver highway + combine ----
    gemm(ah+OXB, al+OXB, wh+ODRG, wl+ODRG, t1, ROWS, HID, HID, HID, HID, HID, 1.f, 1,1, 0,0,0,0,0,0);
    gemm(ah+OXB, al+OXB, wh+ODRW, wl+ODRW, t2, ROWS, HID, HID, HID, HID, HID, 1.f, 1,1, 0,0,0,0,0,0);
    combinex_kernel<<<n4h/256, B256>>>(x_mod, mod, t1, t2, dr_gb, x, n4h);

    // ---- decoder ----
    rmsadd_kernel<<<ROWS, B256>>>(x, in_ln_w);
    rmsnorm_split<<<ROWS, B256>>>(x, post_ln_w, ah+OHB, al+OHB);
    gemm(ah+OHB, al+OHB, wh+OWG, wl+OWG, gg, ROWS, FFD, HID, HID, HID, FFD, 1.f, 1,1, 0,0,0,0,0,0);
    gemm(ah+OHB, al+OHB, wh+OWU, wl+OWU, uu, ROWS, FFD, HID, HID, HID, FFD, 1.f, 1,1, 0,0,0,0,0,0);
    silumul_split<<<n4f/256, B256>>>(gg, uu, ah+OGG, al+OGG, n4f);
    gemm(ah+OGG, al+OGG, wh+OWD, wl+OWD, mod, ROWS, HID, FFD, FFD, FFD, HID, 1.f, 1,1, 0,0,0,0,0,0);
    add2_kernel<<<n4h/256, B256>>>(x, mod, outx, n4h);
}

// round 8
// speedup vs baseline: 1.0751x; 1.0302x over previous
#include <cuda_runtime.h>
#include <cuda_bf16.h>
#include <cstdint>
#include <math.h>
using bf16 = __nv_bfloat16;
typedef long long ll;

#define BATCH 2
#define SEQ 2048
#define HID 2048
#define NHEAD 16
#define HDIM 128
#define FFD 8192
#define ROWS 4096
#define RMS_EPS 1e-5f
#define RH 8388608LL
#define H2 4194304LL
#define FF2 16777216LL
#define GGN 33554432LL

// ------------------------- scratch -------------------------
__device__ float g_q[RH], g_k[RH], g_v[RH], g_mod[RH], g_t1[RH], g_t2[RH], g_x[RH];
__device__ float g_gate[GGN], g_up[GGN];
__device__ bf16 g_wh[8*H2+3*FF2], g_wl[8*H2+3*FF2];
__device__ bf16 g_ah[8*RH+GGN],  g_al[8*RH+GGN];

// weight arena offsets
#define OWQ  (0*H2)
#define OWK  (1*H2)
#define OWV  (2*H2)
#define OWO  (3*H2)
#define OFBW (4*H2)
#define OFBG (5*H2)
#define ODRW (6*H2)
#define ODRG (7*H2)
#define OWG  (8*H2)
#define OWU  (8*H2+FF2)
#define OWD  (8*H2+2*FF2)
// activation arena offsets
#define OQN  (0*RH)
#define OXB  (1*RH)
#define OXM  (2*RH)
#define OQ   (3*RH)
#define OK2  (4*RH)
#define OVT  (5*RH)
#define OATT (6*RH)
#define OHB  (7*RH)
#define OGG  (8*RH)

// ------------------------- PTX helpers -------------------------
__device__ __forceinline__ uint32_t smem_u32(const void* p) {
    uint32_t a;
    asm("{ .reg .u64 t; cvta.to.shared.u64 t, %1; cvt.u32.u64 %0, t; }" : "=r"(a) : "l"(p));
    return a;
}
__device__ __forceinline__ void cp16(uint32_t s, const void* g) {
    asm volatile("cp.async.cg.shared.global [%0], [%1], 16;" :: "r"(s), "l"(g));
}
__device__ __forceinline__ void cpcommit() { asm volatile("cp.async.commit_group;" ::: "memory"); }
__device__ __forceinline__ void cpwait0()  { asm volatile("cp.async.wait_group 0;" ::: "memory"); }
__device__ __forceinline__ void cpwait1()  { asm volatile("cp.async.wait_group 1;" ::: "memory"); }

__device__ __forceinline__ void ldsm4(uint32_t* r, uint32_t addr) {
    asm volatile("ldmatrix.sync.aligned.m8n8.x4.shared.b16 {%0,%1,%2,%3}, [%4];"
        : "=r"(r[0]), "=r"(r[1]), "=r"(r[2]), "=r"(r[3]) : "r"(addr));
}
__device__ __forceinline__ void mma16816(float* c, const uint32_t* a, uint32_t b0, uint32_t b1) {
    asm volatile("mma.sync.aligned.m16n8k16.row.col.f32.bf16.bf16.f32 "
        "{%0,%1,%2,%3}, {%4,%5,%6,%7}, {%8,%9}, {%0,%1,%2,%3};"
        : "+f"(c[0]), "+f"(c[1]), "+f"(c[2]), "+f"(c[3])
        : "r"(a[0]), "r"(a[1]), "r"(a[2]), "r"(a[3]), "r"(b0), "r"(b1));
}
__device__ __forceinline__ void split2(float x, bf16& h, bf16& l) {
    h = __float2bfloat16(x);
    l = __float2bfloat16(x - __bfloat162float(h));
}
__device__ __forceinline__ uint32_t packbf(float a, float b) {
    __nv_bfloat162 t(__float2bfloat16(a), __float2bfloat16(b));
    return *(uint32_t*)&t;
}

// ---------------------------------------------------------------------------
// bf16x3 HMMA GEMM (unchanged from R7 best): 128x128 CTA, KTILE=32, 3-stage.
// ---------------------------------------------------------------------------
#define STG 32768
#define TC_SMEM (3*STG)

__global__ __launch_bounds__(256, 2)
void mma_gemm(const bf16* __restrict__ Ahg, const bf16* __restrict__ Alg,
              const bf16* __restrict__ Bhg, const bf16* __restrict__ Blg,
              float* __restrict__ Cg,
              int K, int lda, int ldb, int ldc, float alpha,
              int zdiv, ll sAa, ll sAb, ll sBa, ll sBb, ll sCa, ll sCb)
{
    extern __shared__ char smem_raw[];
    const uint32_t tiles = smem_u32(smem_raw);
    const int tid = threadIdx.x, wid = tid >> 5, lane = tid & 31;
    const int wm = wid & 3, wn = wid >> 2;

    const int z = blockIdx.z;
    const ll aoff = (ll)(z / zdiv) * sAa + (ll)(z % zdiv) * sAb;
    const ll boff = (ll)(z / zdiv) * sBa + (ll)(z % zdiv) * sBb;
    const ll coff = (ll)(z / zdiv) * sCa + (ll)(z % zdiv) * sCb;
    const bf16* Ah = Ahg + aoff; const bf16* Al = Alg + aoff;
    const bf16* Bh = Bhg + boff; const bf16* Bl = Blg + boff;

    const int bm = blockIdx.y << 7, bn = blockIdx.x << 7;
    const int nk = K >> 5;

    auto load_stage = [&](int kt) {
        const uint32_t st = tiles + (uint32_t)(kt % 3) * STG;
        const ll kb = (ll)kt * 32;
#pragma unroll
        for (int i = tid; i < 512; i += 256) {
            const int r = i >> 2, c = i & 3;
            const uint32_t sw = (uint32_t)r * 64u + (uint32_t)((c ^ ((r >> 1) & 3)) << 4);
            const ll ao = (ll)(bm + r) * lda + kb + c * 8;
            const ll bo = (ll)(bn + r) * ldb + kb + c * 8;
            cp16(st         + sw, Ah + ao);
            cp16(st + 8192  + sw, Al + ao);
            cp16(st + 16384 + sw, Bh + bo);
            cp16(st + 24576 + sw, Bl + bo);
        }
        cpcommit();
    };

    float acc[2][8][4];
#pragma unroll
    for (int i = 0; i < 2; i++)
#pragma unroll
        for (int j = 0; j < 8; j++)
#pragma unroll
            for (int t = 0; t < 4; t++) acc[i][j][t] = 0.f;

    const int aRow  = wm * 32 + (lane & 15);
    const int aCpar = lane >> 4;
    const int bNadd = ((lane >> 4) << 3) + (lane & 7);
    const int bCpar = (lane >> 3) & 1;

    load_stage(0);
    if (nk > 1) load_stage(1); else cpcommit();

    for (int kt = 0; kt < nk; kt++) {
        if (kt >= nk - 2) cpwait0(); else cpwait1();
        __syncthreads();
        if (kt + 2 < nk) load_stage(kt + 2); else cpcommit();

        const uint32_t st = tiles + (uint32_t)(kt % 3) * STG;
#pragma unroll
        for (int ks = 0; ks < 2; ks++) {
            uint32_t ahf[2][4], alf[2][4];
#pragma unroll
            for (int mt = 0; mt < 2; mt++) {
                const int row = aRow + mt * 16;
                const int ch = ks * 2 + aCpar;
                const uint32_t ad = st + (uint32_t)row * 64u + (uint32_t)((ch ^ ((row >> 1) & 3)) << 4);
                ldsm4(ahf[mt], ad);
                ldsm4(alf[mt], ad + 8192);
            }
#pragma unroll
            for (int np = 0; np < 2; np++) {
                uint32_t bh[2][4], bl[2][4];
#pragma unroll
                for (int t = 0; t < 2; t++) {
                    const int nt = np * 2 + t;
                    const int row = wn * 64 + nt * 16 + bNadd;
                    const int ch = ks * 2 + bCpar;
                    const uint32_t bd = st + 16384u + (uint32_t)row * 64u + (uint32_t)((ch ^ ((row >> 1) & 3)) << 4);
                    ldsm4(bh[t], bd);
                    ldsm4(bl[t], bd + 8192);
                }
#pragma unroll
                for (int t = 0; t < 2; t++) {
                    const int nb = (np * 2 + t) * 2;
                    mma16816(acc[0][nb],   ahf[0], bh[t][0], bh[t][1]);
                    mma16816(acc[0][nb+1], ahf[0], bh[t][2], bh[t][3]);
                    mma16816(acc[1][nb],   ahf[1], bh[t][0], bh[t][1]);
                    mma16816(acc[1][nb+1], ahf[1], bh[t][2], bh[t][3]);
                }
#pragma unroll
                for (int t = 0; t < 2; t++) {
                    const int nb = (np * 2 + t) * 2;
                    mma16816(acc[0][nb],   ahf[0], bl[t][0], bl[t][1]);
                    mma16816(acc[0][nb+1], ahf[0], bl[t][2], bl[t][3]);
                    mma16816(acc[1][nb],   ahf[1], bl[t][0], bl[t][1]);
                    mma16816(acc[1][nb+1], ahf[1], bl[t][2], bl[t][3]);
                }
#pragma unroll
                for (int t = 0; t < 2; t++) {
                    const int nb = (np * 2 + t) * 2;
                    mma16816(acc[0][nb],   alf[0], bh[t][0], bh[t][1]);
                    mma16816(acc[0][nb+1], alf[0], bh[t][2], bh[t][3]);
                    mma16816(acc[1][nb],   alf[1], bh[t][0], bh[t][1]);
                    mma16816(acc[1][nb+1], alf[1], bh[t][2], bh[t][3]);
                }
            }
        }
    }

    const int erow = bm + wm * 32 + (lane >> 2);
    const int ecol = bn + wn * 64 + (lane & 3) * 2;
#pragma unroll
    for (int mt = 0; mt < 2; mt++) {
#pragma unroll
        for (int j = 0; j < 8; j++) {
            float* p0 = Cg + coff + (ll)(erow + mt*16)     * ldc + ecol + j*8;
            float* p1 = Cg + coff + (ll)(erow + mt*16 + 8) * ldc + ecol + j*8;
            *(float2*)p0 = make_float2(acc[mt][j][0]*alpha, acc[mt][j][1]*alpha);
            *(float2*)p1 = make_float2(acc[mt][j][2]*alpha, acc[mt][j][3]*alpha);
        }
    }
}

// ---------------------------------------------------------------------------
// Flash attention: per CTA = 128 q-rows x 1 head. Online softmax, bf16x3 for
// QK^T and PV, K/V double-buffered cp.async. Writes att as split bf16.
//   q,k: [ROWS][HID] bf16 hi/lo (post-rope). vt: [(z*128+d)][SEQ].
//   out: ah/al arena at OATT, layout [ROWS][HID].
// smem: Q 2x32KB | stage{K 2x16KB, VT 2x16KB} x2 = 192KB.
// ---------------------------------------------------------------------------
#define FA_SMEM 196608
#define FA_SCALE 0.08838834764831845f

__global__ __launch_bounds__(256, 1)
void flash_attn(const bf16* __restrict__ qh, const bf16* __restrict__ ql,
                const bf16* __restrict__ kh, const bf16* __restrict__ kl,
                const bf16* __restrict__ vth, const bf16* __restrict__ vtl,
                const float* __restrict__ mask,
                bf16* __restrict__ oh, bf16* __restrict__ ol)
{
    extern __shared__ char smem_raw[];
    const uint32_t sQ = smem_u32(smem_raw);          // Qh 32K, Ql 32K
    const uint32_t sKV = sQ + 65536;                 // 2 stages x 64KB
    const int tid = threadIdx.x, w = tid >> 5, lane = tid & 31;

    const int qt = blockIdx.x;            // q tile (16)
    const int z  = blockIdx.y;            // head index b*16+h
    const int b  = z >> 4, h = z & 15;
    const int bS = b * SEQ;

    // ---- load Q tile [128 rows][128 d], 256B rows, sw: c ^ (r&15) ----
    {
        const ll base = (ll)(bS + qt*128) * HID + h*128;
#pragma unroll
        for (int i = tid; i < 2048; i += 256) {
            const int r = i >> 4, c = i & 15;
            const uint32_t sw = (uint32_t)r*256u + (uint32_t)((c ^ (r & 15)) << 4);
            const ll off = base + (ll)r * HID + c * 8;
            cp16(sQ +         sw, qh + off);
            cp16(sQ + 32768 + sw, ql + off);
        }
    }
    auto load_kv = [&](int kt) {
        const uint32_t st = sKV + (uint32_t)(kt & 1) * 65536;
        const ll kbase = (ll)(bS + kt*64) * HID + h*128;
#pragma unroll
        for (int i = tid; i < 1024; i += 256) {     // K tile 64x128, 256B rows
            const int r = i >> 4, c = i & 15;
            const uint32_t sw = (uint32_t)r*256u + (uint32_t)((c ^ (r & 15)) << 4);
            const ll off = kbase + (ll)r * HID + c * 8;
            cp16(st         + sw, kh + off);
            cp16(st + 16384 + sw, kl + off);
        }
        const ll vbase = (ll)z * 128 * SEQ + kt*64;
#pragma unroll
        for (int i = tid; i < 1024; i += 256) {     // VT tile 128x64, 128B rows
            const int r = i >> 3, c = i & 7;
            const uint32_t sw = (uint32_t)r*128u + (uint32_t)((c ^ (r & 7)) << 4);
            const ll off = vbase + (ll)r * SEQ + c * 8;
            cp16(st + 32768 + sw, vth + off);
            cp16(st + 49152 + sw, vtl + off);
        }
        cpcommit();
    };

    float oacc[16][4];
#pragma unroll
    for (int i = 0; i < 16; i++)
#pragma unroll
        for (int t = 0; t < 4; t++) oacc[i][t] = 0.f;
    float m1 = -1e30f, m2 = -1e30f, l1 = 0.f, l2 = 0.f;

    const int aCpar = lane >> 4;
    const int bNadd = ((lane >> 4) << 3) + (lane & 7);
    const int bCpar = (lane >> 3) & 1;
    const int qRow  = w * 16 + (lane & 15);
    const int qpos1 = qt*128 + w*16 + (lane >> 2);   // row of c0,c1
    const int colq  = (lane & 3) * 2;

    load_kv(0);
    const int NKT = SEQ / 64;   // 32

    for (int kt = 0; kt < NKT; kt++) {
        if (kt + 1 < NKT) { load_kv(kt + 1); cpwait1(); } else { cpwait0(); }
        __syncthreads();
        const uint32_t st = sKV + (uint32_t)(kt & 1) * 65536;

        // ---- S = scale*(Q K^T): sacc[8 ntiles][4] over 16 rows x 64 kpos ----
        float sacc[8][4];
#pragma unroll
        for (int j = 0; j < 8; j++)
#pragma unroll
            for (int t = 0; t < 4; t++) sacc[j][t] = 0.f;

#pragma unroll
        for (int ks = 0; ks < 8; ks++) {
            uint32_t ahf[4], alf[4];
            {
                const int ch = ks*2 + aCpar;
                const uint32_t ad = sQ + (uint32_t)qRow*256u + (uint32_t)((ch ^ (qRow & 15)) << 4);
                ldsm4(ahf, ad);
                ldsm4(alf, ad + 32768);
            }
#pragma unroll
            for (int nt = 0; nt < 4; nt++) {
                const int row = nt*16 + bNadd;
                const int ch = ks*2 + bCpar;
                const uint32_t bd = st + (uint32_t)row*256u + (uint32_t)((ch ^ (row & 15)) << 4);
                uint32_t bh[4], bl[4];
                ldsm4(bh, bd);
                ldsm4(bl, bd + 16384);
                mma16816(sacc[nt*2],   ahf, bh[0], bh[1]);
                mma16816(sacc[nt*2+1], ahf, bh[2], bh[3]);
                mma16816(sacc[nt*2],   ahf, bl[0], bl[1]);
                mma16816(sacc[nt*2+1], ahf, bl[2], bl[3]);
                mma16816(sacc[nt*2],   alf, bh[0], bh[1]);
                mma16816(sacc[nt*2+1], alf, bh[2], bh[3]);
            }
        }

        // ---- mask + scale, online softmax ----
        const int kbase = kt*64;
#pragma unroll
        for (int j = 0; j < 8; j++) {
            const int kposg = kbase + j*8 + colq;
            float2 mA = *(const float2*)(mask + (ll)qpos1 * SEQ + kposg);
            float2 mB = *(const float2*)(mask + (ll)(qpos1 + 8) * SEQ + kposg);
            sacc[j][0] = sacc[j][0]*FA_SCALE + mA.x;
            sacc[j][1] = sacc[j][1]*FA_SCALE + mA.y;
            sacc[j][2] = sacc[j][2]*FA_SCALE + mB.x;
            sacc[j][3] = sacc[j][3]*FA_SCALE + mB.y;
        }
        float mx1 = -1e30f, mx2 = -1e30f;
#pragma unroll
        for (int j = 0; j < 8; j++) {
            mx1 = fmaxf(mx1, fmaxf(sacc[j][0], sacc[j][1]));
            mx2 = fmaxf(mx2, fmaxf(sacc[j][2], sacc[j][3]));
        }
        mx1 = fmaxf(mx1, __shfl_xor_sync(0xffffffffu, mx1, 1));
        mx1 = fmaxf(mx1, __shfl_xor_sync(0xffffffffu, mx1, 2));
        mx2 = fmaxf(mx2, __shfl_xor_sync(0xffffffffu, mx2, 1));
        mx2 = fmaxf(mx2, __shfl_xor_sync(0xffffffffu, mx2, 2));
        const float nm1 = fmaxf(m1, mx1), nm2 = fmaxf(m2, mx2);
        const float al1 = __expf(m1 - nm1), al2 = __expf(m2 - nm2);
        m1 = nm1; m2 = nm2;
        float s1 = 0.f, s2 = 0.f;
#pragma unroll
        for (int j = 0; j < 8; j++) {
            sacc[j][0] = __expf(sacc[j][0] - nm1);
            sacc[j][1] = __expf(sacc[j][1] - nm1);
            sacc[j][2] = __expf(sacc[j][2] - nm2);
            sacc[j][3] = __expf(sacc[j][3] - nm2);
            s1 += sacc[j][0] + sacc[j][1];
            s2 += sacc[j][2] + sacc[j][3];
        }
        s1 += __shfl_xor_sync(0xffffffffu, s1, 1);
        s1 += __shfl_xor_sync(0xffffffffu, s1, 2);
        s2 += __shfl_xor_sync(0xffffffffu, s2, 1);
        s2 += __shfl_xor_sync(0xffffffffu, s2, 2);
        l1 = l1*al1 + s1;
        l2 = l2*al2 + s2;
#pragma unroll
        for (int i = 0; i < 16; i++) {
            oacc[i][0] *= al1; oacc[i][1] *= al1;
            oacc[i][2] *= al2; oacc[i][3] *= al2;
        }

        // ---- O += P @ V  (P frags built from sacc; bf16x3) ----
#pragma unroll
        for (int kk = 0; kk < 4; kk++) {
            uint32_t pah[4], pal[4];
            {
                bf16 h0,l0,h1,l1b,h2,l2b,h3,l3;
                // a0: (r1, klo) ; a1: (r2, klo) ; a2: (r1, khi) ; a3: (r2, khi)
                split2(sacc[2*kk][0], h0,l0);  split2(sacc[2*kk][1], h1,l1b);
                __nv_bfloat162 t0(h0,h1), u0(l0,l1b);
                pah[0] = *(uint32_t*)&t0; pal[0] = *(uint32_t*)&u0;
                split2(sacc[2*kk][2], h2,l2b); split2(sacc[2*kk][3], h3,l3);
                __nv_bfloat162 t1(h2,h3), u1(l2b,l3);
                pah[1] = *(uint32_t*)&t1; pal[1] = *(uint32_t*)&u1;
                split2(sacc[2*kk+1][0], h0,l0);  split2(sacc[2*kk+1][1], h1,l1b);
                __nv_bfloat162 t2(h0,h1), u2(l0,l1b);
                pah[2] = *(uint32_t*)&t2; pal[2] = *(uint32_t*)&u2;
                split2(sacc[2*kk+1][2], h2,l2b); split2(sacc[2*kk+1][3], h3,l3);
                __nv_bfloat162 t3(h2,h3), u3(l2b,l3);
                pah[3] = *(uint32_t*)&t3; pal[3] = *(uint32_t*)&u3;
            }
#pragma unroll
            for (int nt = 0; nt < 8; nt++) {
                const int row = nt*16 + bNadd;
                const int ch = kk*2 + bCpar;
                const uint32_t bd = st + 32768u + (uint32_t)row*128u + (uint32_t)((ch ^ (row & 7)) << 4);
                uint32_t bh[4], bl[4];
                ldsm4(bh, bd);
                ldsm4(bl, bd + 16384);
                mma16816(oacc[nt*2],   pah, bh[0], bh[1]);
                mma16816(oacc[nt*2+1], pah, bh[2], bh[3]);
                mma16816(oacc[nt*2],   pah, bl[0], bl[1]);
                mma16816(oacc[nt*2+1], pah, bl[2], bl[3]);
                mma16816(oacc[nt*2],   pal, bh[0], bh[1]);
                mma16816(oacc[nt*2+1], pal, bh[2], bh[3]);
            }
        }
        __syncthreads();
    }

    // ---- epilogue: O /= l, write split bf16 ----
    const float inv1 = 1.f / l1, inv2 = 1.f / l2;
    const ll row1 = (ll)(bS + qpos1);
#pragma unroll
    for (int nt = 0; nt < 16; nt++) {
        const int col = h*128 + nt*8 + colq;
        bf16 h0,l0,h1,l1b;
        split2(oacc[nt][0]*inv1, h0,l0); split2(oacc[nt][1]*inv1, h1,l1b);
        __nv_bfloat162 th(h0,h1), tl(l0,l1b);
        *(__nv_bfloat162*)(oh + row1*HID + col) = th;
        *(__nv_bfloat162*)(ol + row1*HID + col) = tl;
        split2(oacc[nt][2]*inv2, h0,l0); split2(oacc[nt][3]*inv2, h1,l1b);
        __nv_bfloat162 uh(h0,h1), ul(l0,l1b);
        *(__nv_bfloat162*)(oh + (row1+8)*HID + col) = uh;
        *(__nv_bfloat162*)(ol + (row1+8)*HID + col) = ul;
    }
}

// ------------------------- reductions -------------------------
__device__ __forceinline__ float wsum(float v) {
#pragma unroll
    for (int o = 16; o; o >>= 1) v += __shfl_xor_sync(0xffffffffu, v, o);
    return v;
}
__device__ __forceinline__ float bsum(float v) {
    __shared__ float sh[8];
    v = wsum(v); __syncthreads();
    if ((threadIdx.x & 31) == 0) sh[threadIdx.x >> 5] = v;
    __syncthreads();
    float r = 0.f;
#pragma unroll
    for (int i = 0; i < 8; i++) r += sh[i];
    return r;
}

// ------------------------- elementwise kernels -------------------------
__global__ __launch_bounds__(256)
void split_kernel(const float* __restrict__ s, bf16* __restrict__ oh, bf16* __restrict__ ol, int n4)
{
    const int i = blockIdx.x * 256 + threadIdx.x;
    if (i >= n4) return;
    float4 v = ((const float4*)s)[i];
    bf16 h0,l0,h1,l1,h2,l2,h3,l3;
    split2(v.x,h0,l0); split2(v.y,h1,l1); split2(v.z,h2,l2); split2(v.w,h3,l3);
    ((__nv_bfloat162*)oh)[2*i]   = __nv_bfloat162(h0,h1);
    ((__nv_bfloat162*)oh)[2*i+1] = __nv_bfloat162(h2,h3);
    ((__nv_bfloat162*)ol)[2*i]   = __nv_bfloat162(l0,l1);
    ((__nv_bfloat162*)ol)[2*i+1] = __nv_bfloat162(l2,l3);
}

__global__ __launch_bounds__(256)
void rmsnorm_split(const float* __restrict__ in, const float* __restrict__ w,
                   bf16* __restrict__ oh, bf16* __restrict__ ol)
{
    const ll base = (ll)blockIdx.x * HID;
    const float4* xin = (const float4*)(in + base);
    float ss = 0.f;
    for (int i = threadIdx.x; i < HID/4; i += 256) {
        float4 v = xin[i];
        ss += v.x*v.x + v.y*v.y + v.z*v.z + v.w*v.w;
    }
    ss = bsum(ss);
    const float r = rsqrtf(ss * (1.f/HID) + RMS_EPS);
    for (int i = threadIdx.x; i < HID/4; i += 256) {
        float4 v = xin[i];
        float4 ww = ((const float4*)w)[i];
        bf16 h0,l0,h1,l1,h2,l2,h3,l3;
        split2(v.x*r*ww.x,h0,l0); split2(v.y*r*ww.y,h1,l1);
        split2(v.z*r*ww.z,h2,l2); split2(v.w*r*ww.w,h3,l3);
        ((__nv_bfloat162*)(oh + base))[2*i]   = __nv_bfloat162(h0,h1);
        ((__nv_bfloat162*)(oh + base))[2*i+1] = __nv_bfloat162(h2,h3);
        ((__nv_bfloat162*)(ol + base))[2*i]   = __nv_bfloat162(l0,l1);
        ((__nv_bfloat162*)(ol + base))[2*i+1] = __nv_bfloat162(l2,l3);
    }
}

__global__ __launch_bounds__(256)
void rmsadd_kernel(float* __restrict__ x, const float* __restrict__ w)
{
    const ll base = (ll)blockIdx.x * HID;
    float4* xp = (float4*)(x + base);
    float ss = 0.f;
    for (int i = threadIdx.x; i < HID/4; i += 256) {
        float4 v = xp[i];
        ss += v.x*v.x + v.y*v.y + v.z*v.z + v.w*v.w;
    }
    ss = bsum(ss);
    const float r = rsqrtf(ss * (1.f/HID) + RMS_EPS);
    for (int i = threadIdx.x; i < HID/4; i += 256) {
        float4 v = xp[i];
        float4 ww = ((const float4*)w)[i];
        xp[i] = make_float4(v.x*(1.f+r*ww.x), v.y*(1.f+r*ww.y), v.z*(1.f+r*ww.z), v.w*(1.f+r*ww.w));
    }
}

__global__ void rope_split(const float* __restrict__ src, bf16* __restrict__ oh, bf16* __restrict__ ol)
{
    const int idx = blockIdx.x * blockDim.x + threadIdx.x;
    if (idx >= ROWS * NHEAD * 64) return;
    const int j = idx & 63, h = (idx >> 6) & (NHEAD-1), row = idx >> 10;
    const int pos = row & (SEQ - 1);
    const float inv = (float)exp(-(double)(2*j) / (double)HDIM * log(10000.0));
    float s_, c;
    sincosf((float)pos * inv, &s_, &c);
    const ll p0 = (ll)row * HID + h * HDIM + j;
    const float q0 = src[p0], q1 = src[p0 + 64];
    bf16 hh, lll;
    split2(q0*c - q1*s_, hh, lll); oh[p0]    = hh; ol[p0]    = lll;
    split2(q1*c + q0*s_, hh, lll); oh[p0+64] = hh; ol[p0+64] = lll;
}

// V transpose-split: v[b*SEQ+s][h*128+d] -> vt[(z*128+d)*SEQ + s], z=b*16+h
__global__ void vtrans_kernel(const float* __restrict__ v, bf16* __restrict__ oh, bf16* __restrict__ ol)
{
    __shared__ float t[32][33];
    const int z = blockIdx.z, b = z >> 4, h = z & 15;
    const int s0 = blockIdx.x * 32, d0 = blockIdx.y * 32;
    const int tx = threadIdx.x, ty = threadIdx.y;
#pragma unroll
    for (int i = 0; i < 4; i++) {
        const int s = s0 + ty + i*8;
        t[ty + i*8][tx] = v[((ll)(b*SEQ + s)) * HID + h*HDIM + d0 + tx];
    }
    __syncthreads();
#pragma unroll
    for (int i = 0; i < 4; i++) {
        const int d = d0 + ty + i*8;
        const float x = t[tx][ty + i*8];
        bf16 hh, lll; split2(x, hh, lll);
        const ll o = ((ll)z * HDIM + d) * SEQ + s0 + tx;
        oh[o] = hh; ol[o] = lll;
    }
}

__device__ __forceinline__ float sigm(float z) { return 1.f / (1.f + expf(-z)); }

__global__ void highway_kernel(const float* __restrict__ g, const float* __restrict__ hh,
                               const float* __restrict__ bias, float* __restrict__ out, int n4)
{
    const int i = blockIdx.x * blockDim.x + threadIdx.x;
    if (i >= n4) return;
    float4 gv = ((const float4*)g)[i], hv = ((const float4*)hh)[i];
    float4 bv = ((const float4*)bias)[i & (HID/4 - 1)];
    ((float4*)out)[i] = make_float4(hv.x*sigm(gv.x+bv.x), hv.y*sigm(gv.y+bv.y),
                                    hv.z*sigm(gv.z+bv.z), hv.w*sigm(gv.w+bv.w));
}

__global__ void combinex_kernel(const float* __restrict__ xm, const float* __restrict__ mod,
                                const float* __restrict__ g, const float* __restrict__ hh,
                                const float* __restrict__ bias, float* __restrict__ out, int n4)
{
    const int i = blockIdx.x * blockDim.x + threadIdx.x;
    if (i >= n4) return;
    float4 xv = ((const float4*)xm)[i], mv = ((const float4*)mod)[i];
    float4 gv = ((const float4*)g)[i], hv = ((const float4*)hh)[i];
    float4 bv = ((const float4*)bias)[i & (HID/4 - 1)];
    ((float4*)out)[i] = make_float4(xv.x+mv.x+hv.x*sigm(gv.x+bv.x), xv.y+mv.y+hv.y*sigm(gv.y+bv.y),
                                    xv.z+mv.z+hv.z*sigm(gv.z+bv.z), xv.w+mv.w+hv.w*sigm(gv.w+bv.w));
}

__global__ void silumul_split(const float* __restrict__ g, const float* __restrict__ u,
                              bf16* __restrict__ oh, bf16* __restrict__ ol, int n4)
{
    const int i = blockIdx.x * blockDim.x + threadIdx.x;
    if (i >= n4) return;
    float4 gv = ((const float4*)g)[i], uv = ((const float4*)u)[i];
    float r0 = gv.x*sigm(gv.x)*uv.x, r1 = gv.y*sigm(gv.y)*uv.y;
    float r2 = gv.z*sigm(gv.z)*uv.z, r3 = gv.w*sigm(gv.w)*uv.w;
    bf16 h0,l0,h1,l1,h2,l2,h3,l3;
    split2(r0,h0,l0); split2(r1,h1,l1); split2(r2,h2,l2); split2(r3,h3,l3);
    ((__nv_bfloat162*)oh)[2*i]   = __nv_bfloat162(h0,h1);
    ((__nv_bfloat162*)oh)[2*i+1] = __nv_bfloat162(h2,h3);
    ((__nv_bfloat162*)ol)[2*i]   = __nv_bfloat162(l0,l1);
    ((__nv_bfloat162*)ol)[2*i+1] = __nv_bfloat162(l2,l3);
}

__global__ void add2_kernel(const float* __restrict__ a, const float* __restrict__ b,
                            float* __restrict__ out, int n4)
{
    const int i = blockIdx.x * blockDim.x + threadIdx.x;
    if (i >= n4) return;
    float4 av = ((const float4*)a)[i], bv = ((const float4*)b)[i];
    ((float4*)out)[i] = make_float4(av.x+bv.x, av.y+bv.y, av.z+bv.z, av.w+bv.w);
}

// ------------------------- launch -------------------------
extern "C" void kernel_launch(void* const* d_in, const int* in_sizes, int n_in,
                              void* d_out, int out_size)
{
    const float* x_mod = (const float*)d_in[0];
    const float* x_back= (const float*)d_in[1];
    const float* mask  = (const float*)d_in[2];
    const float* wq = (const float*)d_in[3];
    const float* wk = (const float*)d_in[4];
    const float* wv = (const float*)d_in[5];
    const float* wo = (const float*)d_in[6];
    const float* cross_ln_w = (const float*)d_in[7];
    const float* fb_w = (const float*)d_in[8];
    const float* fb_g = (const float*)d_in[9];
    const float* fb_gb= (const float*)d_in[10];
    const float* dr_w = (const float*)d_in[11];
    const float* dr_g = (const float*)d_in[12];
    const float* dr_gb= (const float*)d_in[13];
    const float* in_ln_w   = (const float*)d_in[14];
    const float* post_ln_w = (const float*)d_in[15];
    const float* w_gate = (const float*)d_in[16];
    const float* w_up   = (const float*)d_in[17];
    const float* w_down = (const float*)d_in[18];

    float* outx = (float*)d_out;
    float* outd = outx + (size_t)ROWS * HID;

    float *q,*k,*v,*mod,*t1,*t2,*x,*gg,*uu;
    bf16 *wh,*wl,*ah,*al;
    cudaGetSymbolAddress((void**)&q, g_q);   cudaGetSymbolAddress((void**)&k, g_k);
    cudaGetSymbolAddress((void**)&v, g_v);
    cudaGetSymbolAddress((void**)&mod, g_mod); cudaGetSymbolAddress((void**)&t1, g_t1);
    cudaGetSymbolAddress((void**)&t2, g_t2); cudaGetSymbolAddress((void**)&x, g_x);
    cudaGetSymbolAddress((void**)&gg, g_gate); cudaGetSymbolAddress((void**)&uu, g_up);
    cudaGetSymbolAddress((void**)&wh, g_wh); cudaGetSymbolAddress((void**)&wl, g_wl);
    cudaGetSymbolAddress((void**)&ah, g_ah); cudaGetSymbolAddress((void**)&al, g_al);

    cudaFuncSetAttribute(mma_gemm,   cudaFuncAttributeMaxDynamicSharedMemorySize, TC_SMEM);
    cudaFuncSetAttribute(flash_attn, cudaFuncAttributeMaxDynamicSharedMemorySize, FA_SMEM);

    const int n4h = (int)(RH/4), n4f = (int)(GGN/4), n4w = (int)(H2/4), n4ff = (int)(FF2/4);
    const dim3 B256(256);

    auto gemm = [&](const bf16* pah, const bf16* pal, const bf16* pbh, const bf16* pbl,
                    float* c, int M, int N, int K, int lda, int ldb, int ldc, float alpha,
                    int gz, int zdiv, ll saa, ll sab, ll sba, ll sbb, ll sca, ll scb) {
        dim3 g(N/128, M/128, gz);
        mma_gemm<<<g, 256, TC_SMEM>>>(pah, pal, pbh, pbl, c, K, lda, ldb, ldc, alpha,
                                      zdiv, saa, sab, sba, sbb, sca, scb);
    };

    // ---- splits + projections ----
    rmsnorm_split<<<ROWS, B256>>>(x_mod, cross_ln_w, ah+OQN, al+OQN);
    split_kernel<<<n4w/256, B256>>>(wq,   wh+OWQ,  wl+OWQ,  n4w);
    split_kernel<<<n4h/256, B256>>>(x_back, ah+OXB, al+OXB, n4h);
    split_kernel<<<n4w/256, B256>>>(wk,   wh+OWK,  wl+OWK,  n4w);
    split_kernel<<<n4w/256, B256>>>(wv,   wh+OWV,  wl+OWV,  n4w);
    gemm(ah+OQN, al+OQN, wh+OWQ, wl+OWQ, q, ROWS, HID, HID, HID, HID, HID, 1.f, 1,1, 0,0,0,0,0,0);
    gemm(ah+OXB, al+OXB, wh+OWK, wl+OWK, k, ROWS, HID, HID, HID, HID, HID, 1.f, 1,1, 0,0,0,0,0,0);
    gemm(ah+OXB, al+OXB, wh+OWV, wl+OWV, v, ROWS, HID, HID, HID, HID, HID, 1.f, 1,1, 0,0,0,0,0,0);

    split_kernel<<<n4h/256, B256>>>(x_mod,  ah+OXM, al+OXM, n4h);
    split_kernel<<<n4w/256, B256>>>(wo,   wh+OWO,  wl+OWO,  n4w);
    split_kernel<<<n4w/256, B256>>>(fb_w, wh+OFBW, wl+OFBW, n4w);
    split_kernel<<<n4w/256, B256>>>(fb_g, wh+OFBG, wl+OFBG, n4w);
    split_kernel<<<n4w/256, B256>>>(dr_w, wh+ODRW, wl+ODRW, n4w);
    split_kernel<<<n4w/256, B256>>>(dr_g, wh+ODRG, wl+ODRG, n4w);
    split_kernel<<<n4ff/256, B256>>>(w_gate, wh+OWG, wl+OWG, n4ff);
    split_kernel<<<n4ff/256, B256>>>(w_up,   wh+OWU, wl+OWU, n4ff);
    split_kernel<<<n4ff/256, B256>>>(w_down, wh+OWD, wl+OWD, n4ff);

    const int ropeN = ROWS * NHEAD * 64;
    rope_split<<<(ropeN+255)/256, B256>>>(q, ah+OQ,  al+OQ);
    rope_split<<<(ropeN+255)/256, B256>>>(k, ah+OK2, al+OK2);
    vtrans_kernel<<<dim3(SEQ/32, HDIM/32, BATCH*NHEAD), dim3(32,8)>>>(v, ah+OVT, al+OVT);

    // ---- fused flash attention -> att split (OATT) ----
    flash_attn<<<dim3(SEQ/128, BATCH*NHEAD), B256, FA_SMEM>>>(
        ah+OQ, al+OQ, ah+OK2, al+OK2, ah+OVT, al+OVT, mask, ah+OATT, al+OATT);
    gemm(ah+OATT, al+OATT, wh+OWO, wl+OWO, mod, ROWS, HID, HID, HID, HID, HID, 1.f, 1,1, 0,0,0,0,0,0);

    // ---- feedback highway -> delta ----
    gemm(ah+OXM, al+OXM, wh+OFBG, wl+OFBG, t1, ROWS, HID, HID, HID, HID, HID, 1.f, 1,1, 0,0,0,0,0,0);
    gemm(ah+OXM, al+OXM, wh+OFBW, wl+OFBW, t2, ROWS, HID, HID, HID, HID, HID, 1.f, 1,1, 0,0,0,0,0,0);
    highway_kernel<<<n4h/256, B256>>>(t1, t2, fb_gb, outd, n4h);

    // ---- driver highway + combine ----
    gemm(ah+OXB, al+OXB, wh+ODRG, wl+ODRG, t1, ROWS, HID, HID, HID, HID, HID, 1.f, 1,1, 0,0,0,0,0,0);
    gemm(ah+OXB, al+OXB, wh+ODRW, wl+ODRW, t2, ROWS, HID, HID, HID, HID, HID, 1.f, 1,1, 0,0,0,0,0,0);
    combinex_kernel<<<n4h/256, B256>>>(x_mod, mod, t1, t2, dr_gb, x, n4h);

    // ---- decoder ----
    rmsadd_kernel<<<ROWS, B256>>>(x, in_ln_w);
    rmsnorm_split<<<ROWS, B256>>>(x, post_ln_w, ah+OHB, al+OHB);
    gemm(ah+OHB, al+OHB, wh+OWG, wl+OWG, gg, ROWS, FFD, HID, HID, HID, FFD, 1.f, 1,1, 0,0,0,0,0,0);
    gemm(ah+OHB, al+OHB, wh+OWU, wl+OWU, uu, ROWS, FFD, HID, HID, HID, FFD, 1.f, 1,1, 0,0,0,0,0,0);
    silumul_split<<<n4f/256, B256>>>(gg, uu, ah+OGG, al+OGG, n4f);
    gemm(ah+OGG, al+OGG, wh+OWD, wl+OWD, mod, ROWS, HID, FFD, FFD, FFD, HID, 1.f, 1,1, 0,0,0,0,0,0);
    add2_kernel<<<n4h/256, B256>>>(x, mod, outx, n4h);
}

// round 9
// speedup vs baseline: 1.4724x; 1.3695x over previous
#include <cuda_runtime.h>
#include <cuda_fp16.h>
#include <cstdint>
#include <math.h>
using f16 = __half;
typedef long long ll;

#define BATCH 2
#define SEQ 2048
#define HID 2048
#define NHEAD 16
#define HDIM 128
#define FFD 8192
#define ROWS 4096
#define RMS_EPS 1e-5f
#define RH 8388608LL
#define H2 4194304LL
#define FF2 16777216LL
#define GGN 33554432LL

// ------------------------- scratch -------------------------
__device__ float g_q[RH], g_k[RH], g_v[RH], g_mod[RH], g_t1[RH], g_t2[RH], g_x[RH];
__device__ float g_gate[GGN], g_up[GGN];
__device__ f16 g_wh[8*H2+3*FF2];              // weights: single fp16 (B operand)
__device__ f16 g_ah[8*RH+GGN], g_al[8*RH+GGN]; // activations hi/lo (A operand); K,VT single in ah

// weight arena offsets
#define OWQ  (0*H2)
#define OWK  (1*H2)
#define OWV  (2*H2)
#define OWO  (3*H2)
#define OFBW (4*H2)
#define OFBG (5*H2)
#define ODRW (6*H2)
#define ODRG (7*H2)
#define OWG  (8*H2)
#define OWU  (8*H2+FF2)
#define OWD  (8*H2+2*FF2)
// activation arena offsets
#define OQN  (0*RH)
#define OXB  (1*RH)
#define OXM  (2*RH)
#define OQ   (3*RH)
#define OK2  (4*RH)   // K single (ah only)
#define OVT  (5*RH)   // VT single (ah only)
#define OATT (6*RH)
#define OHB  (7*RH)
#define OGG  (8*RH)

// ------------------------- PTX helpers -------------------------
__device__ __forceinline__ uint32_t smem_u32(const void* p) {
    uint32_t a;
    asm("{ .reg .u64 t; cvta.to.shared.u64 t, %1; cvt.u32.u64 %0, t; }" : "=r"(a) : "l"(p));
    return a;
}
__device__ __forceinline__ void cp16(uint32_t s, const void* g) {
    asm volatile("cp.async.cg.shared.global [%0], [%1], 16;" :: "r"(s), "l"(g));
}
__device__ __forceinline__ void cpcommit() { asm volatile("cp.async.commit_group;" ::: "memory"); }
__device__ __forceinline__ void cpwait0()  { asm volatile("cp.async.wait_group 0;" ::: "memory"); }
__device__ __forceinline__ void cpwait1()  { asm volatile("cp.async.wait_group 1;" ::: "memory"); }

__device__ __forceinline__ void ldsm4(uint32_t* r, uint32_t addr) {
    asm volatile("ldmatrix.sync.aligned.m8n8.x4.shared.b16 {%0,%1,%2,%3}, [%4];"
        : "=r"(r[0]), "=r"(r[1]), "=r"(r[2]), "=r"(r[3]) : "r"(addr));
}
__device__ __forceinline__ void mma16816(float* c, const uint32_t* a, uint32_t b0, uint32_t b1) {
    asm volatile("mma.sync.aligned.m16n8k16.row.col.f32.f16.f16.f32 "
        "{%0,%1,%2,%3}, {%4,%5,%6,%7}, {%8,%9}, {%0,%1,%2,%3};"
        : "+f"(c[0]), "+f"(c[1]), "+f"(c[2]), "+f"(c[3])
        : "r"(a[0]), "r"(a[1]), "r"(a[2]), "r"(a[3]), "r"(b0), "r"(b1));
}
__device__ __forceinline__ void split2(float x, f16& h, f16& l) {
    h = __float2half_rn(x);
    l = __float2half_rn(x - __half2float(h));
}

// ---------------------------------------------------------------------------
// fp16x2 HMMA GEMM: C = alpha*(Ah+Al) @ B^T. A:[M,K] lda (hi/lo), B:[N,K] ldb.
// 128x128 CTA tile, KTILE=32, 3-stage cp.async (72KB -> 2 CTAs/SM),
// 8 warps (warp tile 32x64), 64B rows, xor-16B swizzle.
// ---------------------------------------------------------------------------
#define STG 24576
#define TC_SMEM (3*STG)

__global__ __launch_bounds__(256, 2)
void mma_gemm(const f16* __restrict__ Ahg, const f16* __restrict__ Alg,
              const f16* __restrict__ Bhg,
              float* __restrict__ Cg,
              int K, int lda, int ldb, int ldc, float alpha,
              int zdiv, ll sAa, ll sAb, ll sBa, ll sBb, ll sCa, ll sCb)
{
    extern __shared__ char smem_raw[];
    const uint32_t tiles = smem_u32(smem_raw);
    const int tid = threadIdx.x, wid = tid >> 5, lane = tid & 31;
    const int wm = wid & 3, wn = wid >> 2;

    const int z = blockIdx.z;
    const ll aoff = (ll)(z / zdiv) * sAa + (ll)(z % zdiv) * sAb;
    const ll boff = (ll)(z / zdiv) * sBa + (ll)(z % zdiv) * sBb;
    const ll coff = (ll)(z / zdiv) * sCa + (ll)(z % zdiv) * sCb;
    const f16* Ah = Ahg + aoff; const f16* Al = Alg + aoff;
    const f16* Bh = Bhg + boff;

    const int bm = blockIdx.y << 7, bn = blockIdx.x << 7;
    const int nk = K >> 5;

    auto load_stage = [&](int kt) {
        const uint32_t st = tiles + (uint32_t)(kt % 3) * STG;
        const ll kb = (ll)kt * 32;
#pragma unroll
        for (int i = tid; i < 512; i += 256) {
            const int r = i >> 2, c = i & 3;
            const uint32_t sw = (uint32_t)r * 64u + (uint32_t)((c ^ ((r >> 1) & 3)) << 4);
            const ll ao = (ll)(bm + r) * lda + kb + c * 8;
            const ll bo = (ll)(bn + r) * ldb + kb + c * 8;
            cp16(st         + sw, Ah + ao);
            cp16(st + 8192  + sw, Al + ao);
            cp16(st + 16384 + sw, Bh + bo);
        }
        cpcommit();
    };

    float acc[2][8][4];
#pragma unroll
    for (int i = 0; i < 2; i++)
#pragma unroll
        for (int j = 0; j < 8; j++)
#pragma unroll
            for (int t = 0; t < 4; t++) acc[i][j][t] = 0.f;

    const int aRow  = wm * 32 + (lane & 15);
    const int aCpar = lane >> 4;
    const int bNadd = ((lane >> 4) << 3) + (lane & 7);
    const int bCpar = (lane >> 3) & 1;

    load_stage(0);
    if (nk > 1) load_stage(1); else cpcommit();

    for (int kt = 0; kt < nk; kt++) {
        if (kt >= nk - 2) cpwait0(); else cpwait1();
        __syncthreads();
        if (kt + 2 < nk) load_stage(kt + 2); else cpcommit();

        const uint32_t st = tiles + (uint32_t)(kt % 3) * STG;
#pragma unroll
        for (int ks = 0; ks < 2; ks++) {
            uint32_t ahf[2][4], alf[2][4];
#pragma unroll
            for (int mt = 0; mt < 2; mt++) {
                const int row = aRow + mt * 16;
                const int ch = ks * 2 + aCpar;
                const uint32_t ad = st + (uint32_t)row * 64u + (uint32_t)((ch ^ ((row >> 1) & 3)) << 4);
                ldsm4(ahf[mt], ad);
                ldsm4(alf[mt], ad + 8192);
            }
#pragma unroll
            for (int np = 0; np < 2; np++) {
                uint32_t bh[2][4];
#pragma unroll
                for (int t = 0; t < 2; t++) {
                    const int nt = np * 2 + t;
                    const int row = wn * 64 + nt * 16 + bNadd;
                    const int ch = ks * 2 + bCpar;
                    const uint32_t bd = st + 16384u + (uint32_t)row * 64u + (uint32_t)((ch ^ ((row >> 1) & 3)) << 4);
                    ldsm4(bh[t], bd);
                }
                // 16 HMMA over 8 accumulators; same-acc reuse distance = 8
#pragma unroll
                for (int t = 0; t < 2; t++) {
                    const int nb = (np * 2 + t) * 2;
                    mma16816(acc[0][nb],   ahf[0], bh[t][0], bh[t][1]);
                    mma16816(acc[0][nb+1], ahf[0], bh[t][2], bh[t][3]);
                    mma16816(acc[1][nb],   ahf[1], bh[t][0], bh[t][1]);
                    mma16816(acc[1][nb+1], ahf[1], bh[t][2], bh[t][3]);
                }
#pragma unroll
                for (int t = 0; t < 2; t++) {
                    const int nb = (np * 2 + t) * 2;
                    mma16816(acc[0][nb],   alf[0], bh[t][0], bh[t][1]);
                    mma16816(acc[0][nb+1], alf[0], bh[t][2], bh[t][3]);
                    mma16816(acc[1][nb],   alf[1], bh[t][0], bh[t][1]);
                    mma16816(acc[1][nb+1], alf[1], bh[t][2], bh[t][3]);
                }
            }
        }
    }

    const int erow = bm + wm * 32 + (lane >> 2);
    const int ecol = bn + wn * 64 + (lane & 3) * 2;
#pragma unroll
    for (int mt = 0; mt < 2; mt++) {
#pragma unroll
        for (int j = 0; j < 8; j++) {
            float* p0 = Cg + coff + (ll)(erow + mt*16)     * ldc + ecol + j*8;
            float* p1 = Cg + coff + (ll)(erow + mt*16 + 8) * ldc + ecol + j*8;
            *(float2*)p0 = make_float2(acc[mt][j][0]*alpha, acc[mt][j][1]*alpha);
            *(float2*)p1 = make_float2(acc[mt][j][2]*alpha, acc[mt][j][3]*alpha);
        }
    }
}

// ---------------------------------------------------------------------------
// Flash attention (fp16x2): CTA = 128 q-rows x 1 head. Q hi/lo; K,VT single.
// smem: Q 64KB | stage{K 16KB, VT 16KB} x2 = 128KB.
// ---------------------------------------------------------------------------
#define FA_SMEM 131072
#define FA_SCALE 0.08838834764831845f

__global__ __launch_bounds__(256, 1)
void flash_attn(const f16* __restrict__ qh, const f16* __restrict__ ql,
                const f16* __restrict__ kh, const f16* __restrict__ vth,
                const float* __restrict__ mask,
                f16* __restrict__ oh, f16* __restrict__ ol)
{
    extern __shared__ char smem_raw[];
    const uint32_t sQ = smem_u32(smem_raw);          // Qh 32K, Ql 32K
    const uint32_t sKV = sQ + 65536;                 // 2 stages x 32KB
    const int tid = threadIdx.x, w = tid >> 5, lane = tid & 31;

    const int qt = blockIdx.x;
    const int z  = blockIdx.y;
    const int b  = z >> 4, h = z & 15;
    const int bS = b * SEQ;

    {
        const ll base = (ll)(bS + qt*128) * HID + h*128;
#pragma unroll
        for (int i = tid; i < 2048; i += 256) {
            const int r = i >> 4, c = i & 15;
            const uint32_t sw = (uint32_t)r*256u + (uint32_t)((c ^ (r & 15)) << 4);
            const ll off = base + (ll)r * HID + c * 8;
            cp16(sQ +         sw, qh + off);
            cp16(sQ + 32768 + sw, ql + off);
        }
    }
    auto load_kv = [&](int kt) {
        const uint32_t st = sKV + (uint32_t)(kt & 1) * 32768;
        const ll kbase = (ll)(bS + kt*64) * HID + h*128;
#pragma unroll
        for (int i = tid; i < 1024; i += 256) {     // K tile 64x128, 256B rows
            const int r = i >> 4, c = i & 15;
            const uint32_t sw = (uint32_t)r*256u + (uint32_t)((c ^ (r & 15)) << 4);
            cp16(st + sw, kh + kbase + (ll)r * HID + c * 8);
        }
        const ll vbase = (ll)z * 128 * SEQ + kt*64;
#pragma unroll
        for (int i = tid; i < 1024; i += 256) {     // VT tile 128x64, 128B rows
            const int r = i >> 3, c = i & 7;
            const uint32_t sw = (uint32_t)r*128u + (uint32_t)((c ^ (r & 7)) << 4);
            cp16(st + 16384 + sw, vth + vbase + (ll)r * SEQ + c * 8);
        }
        cpcommit();
    };

    float oacc[16][4];
#pragma unroll
    for (int i = 0; i < 16; i++)
#pragma unroll
        for (int t = 0; t < 4; t++) oacc[i][t] = 0.f;
    float m1 = -1e30f, m2 = -1e30f, l1 = 0.f, l2 = 0.f;

    const int aCpar = lane >> 4;
    const int bNadd = ((lane >> 4) << 3) + (lane & 7);
    const int bCpar = (lane >> 3) & 1;
    const int qRow  = w * 16 + (lane & 15);
    const int qpos1 = qt*128 + w*16 + (lane >> 2);
    const int colq  = (lane & 3) * 2;

    load_kv(0);
    const int NKT = SEQ / 64;

    for (int kt = 0; kt < NKT; kt++) {
        if (kt + 1 < NKT) { load_kv(kt + 1); cpwait1(); } else { cpwait0(); }
        __syncthreads();
        const uint32_t st = sKV + (uint32_t)(kt & 1) * 32768;

        float sacc[8][4];
#pragma unroll
        for (int j = 0; j < 8; j++)
#pragma unroll
            for (int t = 0; t < 4; t++) sacc[j][t] = 0.f;

#pragma unroll
        for (int ks = 0; ks < 8; ks++) {
            uint32_t ahf[4], alf[4];
            {
                const int ch = ks*2 + aCpar;
                const uint32_t ad = sQ + (uint32_t)qRow*256u + (uint32_t)((ch ^ (qRow & 15)) << 4);
                ldsm4(ahf, ad);
                ldsm4(alf, ad + 32768);
            }
#pragma unroll
            for (int nt = 0; nt < 4; nt++) {
                const int row = nt*16 + bNadd;
                const int ch = ks*2 + bCpar;
                const uint32_t bd = st + (uint32_t)row*256u + (uint32_t)((ch ^ (row & 15)) << 4);
                uint32_t bh[4];
                ldsm4(bh, bd);
                mma16816(sacc[nt*2],   ahf, bh[0], bh[1]);
                mma16816(sacc[nt*2+1], ahf, bh[2], bh[3]);
                mma16816(sacc[nt*2],   alf, bh[0], bh[1]);
                mma16816(sacc[nt*2+1], alf, bh[2], bh[3]);
            }
        }

        const int kbase = kt*64;
#pragma unroll
        for (int j = 0; j < 8; j++) {
            const int kposg = kbase + j*8 + colq;
            float2 mA = *(const float2*)(mask + (ll)qpos1 * SEQ + kposg);
            float2 mB = *(const float2*)(mask + (ll)(qpos1 + 8) * SEQ + kposg);
            sacc[j][0] = sacc[j][0]*FA_SCALE + mA.x;
            sacc[j][1] = sacc[j][1]*FA_SCALE + mA.y;
            sacc[j][2] = sacc[j][2]*FA_SCALE + mB.x;
            sacc[j][3] = sacc[j][3]*FA_SCALE + mB.y;
        }
        float mx1 = -1e30f, mx2 = -1e30f;
#pragma unroll
        for (int j = 0; j < 8; j++) {
            mx1 = fmaxf(mx1, fmaxf(sacc[j][0], sacc[j][1]));
            mx2 = fmaxf(mx2, fmaxf(sacc[j][2], sacc[j][3]));
        }
        mx1 = fmaxf(mx1, __shfl_xor_sync(0xffffffffu, mx1, 1));
        mx1 = fmaxf(mx1, __shfl_xor_sync(0xffffffffu, mx1, 2));
        mx2 = fmaxf(mx2, __shfl_xor_sync(0xffffffffu, mx2, 1));
        mx2 = fmaxf(mx2, __shfl_xor_sync(0xffffffffu, mx2, 2));
        const float nm1 = fmaxf(m1, mx1), nm2 = fmaxf(m2, mx2);
        const float al1 = __expf(m1 - nm1), al2 = __expf(m2 - nm2);
        m1 = nm1; m2 = nm2;
        float s1 = 0.f, s2 = 0.f;
#pragma unroll
        for (int j = 0; j < 8; j++) {
            sacc[j][0] = __expf(sacc[j][0] - nm1);
            sacc[j][1] = __expf(sacc[j][1] - nm1);
            sacc[j][2] = __expf(sacc[j][2] - nm2);
            sacc[j][3] = __expf(sacc[j][3] - nm2);
            s1 += sacc[j][0] + sacc[j][1];
            s2 += sacc[j][2] + sacc[j][3];
        }
        s1 += __shfl_xor_sync(0xffffffffu, s1, 1);
        s1 += __shfl_xor_sync(0xffffffffu, s1, 2);
        s2 += __shfl_xor_sync(0xffffffffu, s2, 1);
        s2 += __shfl_xor_sync(0xffffffffu, s2, 2);
        l1 = l1*al1 + s1;
        l2 = l2*al2 + s2;
#pragma unroll
        for (int i = 0; i < 16; i++) {
            oacc[i][0] *= al1; oacc[i][1] *= al1;
            oacc[i][2] *= al2; oacc[i][3] *= al2;
        }

        // O += P @ V : P split hi/lo fp16, V single
#pragma unroll
        for (int kk = 0; kk < 4; kk++) {
            uint32_t pah[4], pal[4];
            {
                f16 h0,l0,h1,l1b;
                split2(sacc[2*kk][0], h0,l0);  split2(sacc[2*kk][1], h1,l1b);
                __half2 t0(h0,h1), u0(l0,l1b);
                pah[0] = *(uint32_t*)&t0; pal[0] = *(uint32_t*)&u0;
                split2(sacc[2*kk][2], h0,l0); split2(sacc[2*kk][3], h1,l1b);
                __half2 t1(h0,h1), u1(l0,l1b);
                pah[1] = *(uint32_t*)&t1; pal[1] = *(uint32_t*)&u1;
                split2(sacc[2*kk+1][0], h0,l0);  split2(sacc[2*kk+1][1], h1,l1b);
                __half2 t2(h0,h1), u2(l0,l1b);
                pah[2] = *(uint32_t*)&t2; pal[2] = *(uint32_t*)&u2;
                split2(sacc[2*kk+1][2], h0,l0); split2(sacc[2*kk+1][3], h1,l1b);
                __half2 t3(h0,h1), u3(l0,l1b);
                pah[3] = *(uint32_t*)&t3; pal[3] = *(uint32_t*)&u3;
            }
#pragma unroll
            for (int nt = 0; nt < 8; nt++) {
                const int row = nt*16 + bNadd;
                const int ch = kk*2 + bCpar;
                const uint32_t bd = st + 16384u + (uint32_t)row*128u + (uint32_t)((ch ^ (row & 7)) << 4);
                uint32_t bh[4];
                ldsm4(bh, bd);
                mma16816(oacc[nt*2],   pah, bh[0], bh[1]);
                mma16816(oacc[nt*2+1], pah, bh[2], bh[3]);
                mma16816(oacc[nt*2],   pal, bh[0], bh[1]);
                mma16816(oacc[nt*2+1], pal, bh[2], bh[3]);
            }
        }
        __syncthreads();
    }

    const float inv1 = 1.f / l1, inv2 = 1.f / l2;
    const ll row1 = (ll)(bS + qpos1);
#pragma unroll
    for (int nt = 0; nt < 16; nt++) {
        const int col = h*128 + nt*8 + colq;
        f16 h0,l0,h1,l1b;
        split2(oacc[nt][0]*inv1, h0,l0); split2(oacc[nt][1]*inv1, h1,l1b);
        __half2 th(h0,h1), tl(l0,l1b);
        *(__half2*)(oh + row1*HID + col) = th;
        *(__half2*)(ol + row1*HID + col) = tl;
        split2(oacc[nt][2]*inv2, h0,l0); split2(oacc[nt][3]*inv2, h1,l1b);
        __half2 uh(h0,h1), ul(l0,l1b);
        *(__half2*)(oh + (row1+8)*HID + col) = uh;
        *(__half2*)(ol + (row1+8)*HID + col) = ul;
    }
}

// ------------------------- reductions -------------------------
__device__ __forceinline__ float wsum(float v) {
#pragma unroll
    for (int o = 16; o; o >>= 1) v += __shfl_xor_sync(0xffffffffu, v, o);
    return v;
}
__device__ __forceinline__ float bsum(float v) {
    __shared__ float sh[8];
    v = wsum(v); __syncthreads();
    if ((threadIdx.x & 31) == 0) sh[threadIdx.x >> 5] = v;
    __syncthreads();
    float r = 0.f;
#pragma unroll
    for (int i = 0; i < 8; i++) r += sh[i];
    return r;
}

// ------------------------- elementwise kernels -------------------------
__global__ __launch_bounds__(256)
void split_kernel(const float* __restrict__ s, f16* __restrict__ oh, f16* __restrict__ ol, int n4)
{
    const int i = blockIdx.x * 256 + threadIdx.x;
    if (i >= n4) return;
    float4 v = ((const float4*)s)[i];
    f16 h0,l0,h1,l1,h2,l2,h3,l3;
    split2(v.x,h0,l0); split2(v.y,h1,l1); split2(v.z,h2,l2); split2(v.w,h3,l3);
    ((__half2*)oh)[2*i]   = __half2(h0,h1);
    ((__half2*)oh)[2*i+1] = __half2(h2,h3);
    ((__half2*)ol)[2*i]   = __half2(l0,l1);
    ((__half2*)ol)[2*i+1] = __half2(l2,l3);
}

// weights: round only (B operand single fp16)
__global__ __launch_bounds__(256)
void roundw_kernel(const float* __restrict__ s, f16* __restrict__ oh, int n4)
{
    const int i = blockIdx.x * 256 + threadIdx.x;
    if (i >= n4) return;
    float4 v = ((const float4*)s)[i];
    ((__half2*)oh)[2*i]   = __half2(__float2half_rn(v.x), __float2half_rn(v.y));
    ((__half2*)oh)[2*i+1] = __half2(__float2half_rn(v.z), __float2half_rn(v.w));
}

__global__ __launch_bounds__(256)
void rmsnorm_split(const float* __restrict__ in, const float* __restrict__ w,
                   f16* __restrict__ oh, f16* __restrict__ ol)
{
    const ll base = (ll)blockIdx.x * HID;
    const float4* xin = (const float4*)(in + base);
    float ss = 0.f;
    for (int i = threadIdx.x; i < HID/4; i += 256) {
        float4 v = xin[i];
        ss += v.x*v.x + v.y*v.y + v.z*v.z + v.w*v.w;
    }
    ss = bsum(ss);
    const float r = rsqrtf(ss * (1.f/HID) + RMS_EPS);
    for (int i = threadIdx.x; i < HID/4; i += 256) {
        float4 v = xin[i];
        float4 ww = ((const float4*)w)[i];
        f16 h0,l0,h1,l1,h2,l2,h3,l3;
        split2(v.x*r*ww.x,h0,l0); split2(v.y*r*ww.y,h1,l1);
        split2(v.z*r*ww.z,h2,l2); split2(v.w*r*ww.w,h3,l3);
        ((__half2*)(oh + base))[2*i]   = __half2(h0,h1);
        ((__half2*)(oh + base))[2*i+1] = __half2(h2,h3);
        ((__half2*)(ol + base))[2*i]   = __half2(l0,l1);
        ((__half2*)(ol + base))[2*i+1] = __half2(l2,l3);
    }
}

__global__ __launch_bounds__(256)
void rmsadd_kernel(float* __restrict__ x, const float* __restrict__ w)
{
    const ll base = (ll)blockIdx.x * HID;
    float4* xp = (float4*)(x + base);
    float ss = 0.f;
    for (int i = threadIdx.x; i < HID/4; i += 256) {
        float4 v = xp[i];
        ss += v.x*v.x + v.y*v.y + v.z*v.z + v.w*v.w;
    }
    ss = bsum(ss);
    const float r = rsqrtf(ss * (1.f/HID) + RMS_EPS);
    for (int i = threadIdx.x; i < HID/4; i += 256) {
        float4 v = xp[i];
        float4 ww = ((const float4*)w)[i];
        xp[i] = make_float4(v.x*(1.f+r*ww.x), v.y*(1.f+r*ww.y), v.z*(1.f+r*ww.z), v.w*(1.f+r*ww.w));
    }
}

// rope for Q: split hi/lo
__global__ void rope_split(const float* __restrict__ src, f16* __restrict__ oh, f16* __restrict__ ol)
{
    const int idx = blockIdx.x * blockDim.x + threadIdx.x;
    if (idx >= ROWS * NHEAD * 64) return;
    const int j = idx & 63, h = (idx >> 6) & (NHEAD-1), row = idx >> 10;
    const int pos = row & (SEQ - 1);
    const float inv = (float)exp(-(double)(2*j) / (double)HDIM * log(10000.0));
    float s_, c;
    sincosf((float)pos * inv, &s_, &c);
    const ll p0 = (ll)row * HID + h * HDIM + j;
    const float q0 = src[p0], q1 = src[p0 + 64];
    f16 hh, lll;
    split2(q0*c - q1*s_, hh, lll); oh[p0]    = hh; ol[p0]    = lll;
    split2(q1*c + q0*s_, hh, lll); oh[p0+64] = hh; ol[p0+64] = lll;
}

// rope for K: round only (B operand)
__global__ void rope_round(const float* __restrict__ src, f16* __restrict__ oh)
{
    const int idx = blockIdx.x * blockDim.x + threadIdx.x;
    if (idx >= ROWS * NHEAD * 64) return;
    const int j = idx & 63, h = (idx >> 6) & (NHEAD-1), row = idx >> 10;
    const int pos = row & (SEQ - 1);
    const float inv = (float)exp(-(double)(2*j) / (double)HDIM * log(10000.0));
    float s_, c;
    sincosf((float)pos * inv, &s_, &c);
    const ll p0 = (ll)row * HID + h * HDIM + j;
    const float q0 = src[p0], q1 = src[p0 + 64];
    oh[p0]    = __float2half_rn(q0*c - q1*s_);
    oh[p0+64] = __float2half_rn(q1*c + q0*s_);
}

// V transpose, single fp16: v[b*SEQ+s][h*128+d] -> vt[(z*128+d)*SEQ + s]
__global__ void vtrans_kernel(const float* __restrict__ v, f16* __restrict__ oh)
{
    __shared__ float t[32][33];
    const int z = blockIdx.z, b = z >> 4, h = z & 15;
    const int s0 = blockIdx.x * 32, d0 = blockIdx.y * 32;
    const int tx = threadIdx.x, ty = threadIdx.y;
#pragma unroll
    for (int i = 0; i < 4; i++) {
        const int s = s0 + ty + i*8;
        t[ty + i*8][tx] = v[((ll)(b*SEQ + s)) * HID + h*HDIM + d0 + tx];
    }
    __syncthreads();
#pragma unroll
    for (int i = 0; i < 4; i++) {
        const int d = d0 + ty + i*8;
        oh[((ll)z * HDIM + d) * SEQ + s0 + tx] = __float2half_rn(t[tx][ty + i*8]);
    }
}

__device__ __forceinline__ float sigm(float z) { return 1.f / (1.f + expf(-z)); }

__global__ void highway_kernel(const float* __restrict__ g, const float* __restrict__ hh,
                               const float* __restrict__ bias, float* __restrict__ out, int n4)
{
    const int i = blockIdx.x * blockDim.x + threadIdx.x;
    if (i >= n4) return;
    float4 gv = ((const float4*)g)[i], hv = ((const float4*)hh)[i];
    float4 bv = ((const float4*)bias)[i & (HID/4 - 1)];
    ((float4*)out)[i] = make_float4(hv.x*sigm(gv.x+bv.x), hv.y*sigm(gv.y+bv.y),
                                    hv.z*sigm(gv.z+bv.z), hv.w*sigm(gv.w+bv.w));
}

__global__ void combinex_kernel(const float* __restrict__ xm, const float* __restrict__ mod,
                                const float* __restrict__ g, const float* __restrict__ hh,
                                const float* __restrict__ bias, float* __restrict__ out, int n4)
{
    const int i = blockIdx.x * blockDim.x + threadIdx.x;
    if (i >= n4) return;
    float4 xv = ((const float4*)xm)[i], mv = ((const float4*)mod)[i];
    float4 gv = ((const float4*)g)[i], hv = ((const float4*)hh)[i];
    float4 bv = ((const float4*)bias)[i & (HID/4 - 1)];
    ((float4*)out)[i] = make_float4(xv.x+mv.x+hv.x*sigm(gv.x+bv.x), xv.y+mv.y+hv.y*sigm(gv.y+bv.y),
                                    xv.z+mv.z+hv.z*sigm(gv.z+bv.z), xv.w+mv.w+hv.w*sigm(gv.w+bv.w));
}

__global__ void silumul_split(const float* __restrict__ g, const float* __restrict__ u,
                              f16* __restrict__ oh, f16* __restrict__ ol, int n4)
{
    const int i = blockIdx.x * blockDim.x + threadIdx.x;
    if (i >= n4) return;
    float4 gv = ((const float4*)g)[i], uv = ((const float4*)u)[i];
    float r0 = gv.x*sigm(gv.x)*uv.x, r1 = gv.y*sigm(gv.y)*uv.y;
    float r2 = gv.z*sigm(gv.z)*uv.z, r3 = gv.w*sigm(gv.w)*uv.w;
    f16 h0,l0,h1,l1,h2,l2,h3,l3;
    split2(r0,h0,l0); split2(r1,h1,l1); split2(r2,h2,l2); split2(r3,h3,l3);
    ((__half2*)oh)[2*i]   = __half2(h0,h1);
    ((__half2*)oh)[2*i+1] = __half2(h2,h3);
    ((__half2*)ol)[2*i]   = __half2(l0,l1);
    ((__half2*)ol)[2*i+1] = __half2(l2,l3);
}

__global__ void add2_kernel(const float* __restrict__ a, const float* __restrict__ b,
                            float* __restrict__ out, int n4)
{
    const int i = blockIdx.x * blockDim.x + threadIdx.x;
    if (i >= n4) return;
    float4 av = ((const float4*)a)[i], bv = ((const float4*)b)[i];
    ((float4*)out)[i] = make_float4(av.x+bv.x, av.y+bv.y, av.z+bv.z, av.w+bv.w);
}

// ------------------------- launch -------------------------
extern "C" void kernel_launch(void* const* d_in, const int* in_sizes, int n_in,
                              void* d_out, int out_size)
{
    const float* x_mod = (const float*)d_in[0];
    const float* x_back= (const float*)d_in[1];
    const float* mask  = (const float*)d_in[2];
    const float* wq = (const float*)d_in[3];
    const float* wk = (const float*)d_in[4];
    const float* wv = (const float*)d_in[5];
    const float* wo = (const float*)d_in[6];
    const float* cross_ln_w = (const float*)d_in[7];
    const float* fb_w = (const float*)d_in[8];
    const float* fb_g = (const float*)d_in[9];
    const float* fb_gb= (const float*)d_in[10];
    const float* dr_w = (const float*)d_in[11];
    const float* dr_g = (const float*)d_in[12];
    const float* dr_gb= (const float*)d_in[13];
    const float* in_ln_w   = (const float*)d_in[14];
    const float* post_ln_w = (const float*)d_in[15];
    const float* w_gate = (const float*)d_in[16];
    const float* w_up   = (const float*)d_in[17];
    const float* w_down = (const float*)d_in[18];

    float* outx = (float*)d_out;
    float* outd = outx + (size_t)ROWS * HID;

    float *q,*k,*v,*mod,*t1,*t2,*x,*gg,*uu;
    f16 *wh,*ah,*al;
    cudaGetSymbolAddress((void**)&q, g_q);   cudaGetSymbolAddress((void**)&k, g_k);
    cudaGetSymbolAddress((void**)&v, g_v);
    cudaGetSymbolAddress((void**)&mod, g_mod); cudaGetSymbolAddress((void**)&t1, g_t1);
    cudaGetSymbolAddress((void**)&t2, g_t2); cudaGetSymbolAddress((void**)&x, g_x);
    cudaGetSymbolAddress((void**)&gg, g_gate); cudaGetSymbolAddress((void**)&uu, g_up);
    cudaGetSymbolAddress((void**)&wh, g_wh);
    cudaGetSymbolAddress((void**)&ah, g_ah); cudaGetSymbolAddress((void**)&al, g_al);

    cudaFuncSetAttribute(mma_gemm,   cudaFuncAttributeMaxDynamicSharedMemorySize, TC_SMEM);
    cudaFuncSetAttribute(flash_attn, cudaFuncAttributeMaxDynamicSharedMemorySize, FA_SMEM);

    const int n4h = (int)(RH/4), n4f = (int)(GGN/4), n4w = (int)(H2/4), n4ff = (int)(FF2/4);
    const dim3 B256(256);

    auto gemm = [&](const f16* pah, const f16* pal, const f16* pbh,
                    float* c, int M, int N, int K, int lda, int ldb, int ldc, float alpha,
                    int gz, int zdiv, ll saa, ll sab, ll sba, ll sbb, ll sca, ll scb) {
        dim3 g(N/128, M/128, gz);
        mma_gemm<<<g, 256, TC_SMEM>>>(pah, pal, pbh, c, K, lda, ldb, ldc, alpha,
                                      zdiv, saa, sab, sba, sbb, sca, scb);
    };

    // ---- splits + projections (launch #6 = GEMM for ncu) ----
    rmsnorm_split<<<ROWS, B256>>>(x_mod, cross_ln_w, ah+OQN, al+OQN);
    roundw_kernel<<<n4w/256, B256>>>(wq, wh+OWQ, n4w);
    split_kernel<<<n4h/256, B256>>>(x_back, ah+OXB, al+OXB, n4h);
    roundw_kernel<<<n4w/256, B256>>>(wk, wh+OWK, n4w);
    roundw_kernel<<<n4w/256, B256>>>(wv, wh+OWV, n4w);
    gemm(ah+OQN, al+OQN, wh+OWQ, q, ROWS, HID, HID, HID, HID, HID, 1.f, 1,1, 0,0,0,0,0,0);
    gemm(ah+OXB, al+OXB, wh+OWK, k, ROWS, HID, HID, HID, HID, HID, 1.f, 1,1, 0,0,0,0,0,0);
    gemm(ah+OXB, al+OXB, wh+OWV, v, ROWS, HID, HID, HID, HID, HID, 1.f, 1,1, 0,0,0,0,0,0);

    split_kernel<<<n4h/256, B256>>>(x_mod,  ah+OXM, al+OXM, n4h);
    roundw_kernel<<<n4w/256, B256>>>(wo,   wh+OWO,  n4w);
    roundw_kernel<<<n4w/256, B256>>>(fb_w, wh+OFBW, n4w);
    roundw_kernel<<<n4w/256, B256>>>(fb_g, wh+OFBG, n4w);
    roundw_kernel<<<n4w/256, B256>>>(dr_w, wh+ODRW, n4w);
    roundw_kernel<<<n4w/256, B256>>>(dr_g, wh+ODRG, n4w);
    roundw_kernel<<<n4ff/256, B256>>>(w_gate, wh+OWG, n4ff);
    roundw_kernel<<<n4ff/256, B256>>>(w_up,   wh+OWU, n4ff);
    roundw_kernel<<<n4ff/256, B256>>>(w_down, wh+OWD, n4ff);

    const int ropeN = ROWS * NHEAD * 64;
    rope_split<<<(ropeN+255)/256, B256>>>(q, ah+OQ,  al+OQ);
    rope_round<<<(ropeN+255)/256, B256>>>(k, ah+OK2);
    vtrans_kernel<<<dim3(SEQ/32, HDIM/32, BATCH*NHEAD), dim3(32,8)>>>(v, ah+OVT);

    // ---- fused flash attention -> att split (OATT) ----
    flash_attn<<<dim3(SEQ/128, BATCH*NHEAD), B256, FA_SMEM>>>(
        ah+OQ, al+OQ, ah+OK2, ah+OVT, mask, ah+OATT, al+OATT);
    gemm(ah+OATT, al+OATT, wh+OWO, mod, ROWS, HID, HID, HID, HID, HID, 1.f, 1,1, 0,0,0,0,0,0);

    // ---- feedback highway -> delta ----
    gemm(ah+OXM, al+OXM, wh+OFBG, t1, ROWS, HID, HID, HID, HID, HID, 1.f, 1,1, 0,0,0,0,0,0);
    gemm(ah+OXM, al+OXM, wh+OFBW, t2, ROWS, HID, HID, HID, HID, HID, 1.f, 1,1, 0,0,0,0,0,0);
    highway_kernel<<<n4h/256, B256>>>(t1, t2, fb_gb, outd, n4h);

    // ---- driver highway + combine ----
    gemm(ah+OXB, al+OXB, wh+ODRG, t1, ROWS, HID, HID, HID, HID, HID, 1.f, 1,1, 0,0,0,0,0,0);
    gemm(ah+OXB, al+OXB, wh+ODRW, t2, ROWS, HID, HID, HID, HID, HID, 1.f, 1,1, 0,0,0,0,0,0);
    combinex_kernel<<<n4h/256, B256>>>(x_mod, mod, t1, t2, dr_gb, x, n4h);

    // ---- decoder ----
    rmsadd_kernel<<<ROWS, B256>>>(x, in_ln_w);
    rmsnorm_split<<<ROWS, B256>>>(x, post_ln_w, ah+OHB, al+OHB);
    gemm(ah+OHB, al+OHB, wh+OWG, gg, ROWS, FFD, HID, HID, HID, FFD, 1.f, 1,1, 0,0,0,0,0,0);
    gemm(ah+OHB, al+OHB, wh+OWU, uu, ROWS, FFD, HID, HID, HID, FFD, 1.f, 1,1, 0,0,0,0,0,0);
    silumul_split<<<n4f/256, B256>>>(gg, uu, ah+OGG, al+OGG, n4f);
    gemm(ah+OGG, al+OGG, wh+OWD, mod, ROWS, HID, FFD, FFD, FFD, HID, 1.f, 1,1, 0,0,0,0,0,0);
    add2_kernel<<<n4h/256, B256>>>(x, mod, outx, n4h);
}

// round 10
// speedup vs baseline: 2.1728x; 1.4757x over previous
#include <cuda_runtime.h>
#include <cuda_fp16.h>
#include <cstdint>
#include <math.h>
using f16 = __half;
typedef long long ll;

#define BATCH 2
#define SEQ 2048
#define HID 2048
#define NHEAD 16
#define HDIM 128
#define FFD 8192
#define ROWS 4096
#define RMS_EPS 1e-5f
#define RH 8388608LL
#define H2 4194304LL
#define FF2 16777216LL
#define GGN 33554432LL

// ------------------------- scratch -------------------------
__device__ float g_q[RH], g_k[RH], g_v[RH], g_mod[RH], g_t1[RH], g_t2[RH], g_x[RH];
__device__ float g_gate[GGN], g_up[GGN];
__device__ f16 g_wh[8*H2+3*FF2];               // weights fp16
__device__ f16 g_ah[8*RH+GGN];                 // activations fp16 (single)

// weight arena offsets
#define OWQ  (0*H2)
#define OWK  (1*H2)
#define OWV  (2*H2)
#define OWO  (3*H2)
#define OFBW (4*H2)
#define OFBG (5*H2)
#define ODRW (6*H2)
#define ODRG (7*H2)
#define OWG  (8*H2)
#define OWU  (8*H2+FF2)
#define OWD  (8*H2+2*FF2)
// activation arena offsets
#define OQN  (0*RH)
#define OXB  (1*RH)
#define OXM  (2*RH)
#define OQ   (3*RH)
#define OK2  (4*RH)
#define OVT  (5*RH)
#define OATT (6*RH)
#define OHB  (7*RH)
#define OGG  (8*RH)

// ------------------------- PTX helpers -------------------------
__device__ __forceinline__ uint32_t smem_u32(const void* p) {
    uint32_t a;
    asm("{ .reg .u64 t; cvta.to.shared.u64 t, %1; cvt.u32.u64 %0, t; }" : "=r"(a) : "l"(p));
    return a;
}
__device__ __forceinline__ void cp16(uint32_t s, const void* g) {
    asm volatile("cp.async.cg.shared.global [%0], [%1], 16;" :: "r"(s), "l"(g));
}
__device__ __forceinline__ void cpcommit() { asm volatile("cp.async.commit_group;" ::: "memory"); }
__device__ __forceinline__ void cpwait0()  { asm volatile("cp.async.wait_group 0;" ::: "memory"); }
__device__ __forceinline__ void cpwait1()  { asm volatile("cp.async.wait_group 1;" ::: "memory"); }

__device__ __forceinline__ void ldsm4(uint32_t* r, uint32_t addr) {
    asm volatile("ldmatrix.sync.aligned.m8n8.x4.shared.b16 {%0,%1,%2,%3}, [%4];"
        : "=r"(r[0]), "=r"(r[1]), "=r"(r[2]), "=r"(r[3]) : "r"(addr));
}
__device__ __forceinline__ void mma16816(float* c, const uint32_t* a, uint32_t b0, uint32_t b1) {
    asm volatile("mma.sync.aligned.m16n8k16.row.col.f32.f16.f16.f32 "
        "{%0,%1,%2,%3}, {%4,%5,%6,%7}, {%8,%9}, {%0,%1,%2,%3};"
        : "+f"(c[0]), "+f"(c[1]), "+f"(c[2]), "+f"(c[3])
        : "r"(a[0]), "r"(a[1]), "r"(a[2]), "r"(a[3]), "r"(b0), "r"(b1));
}

// ---------------------------------------------------------------------------
// fp16 HMMA GEMM: C = alpha * A @ B^T. A:[M,K] lda, B:[N,K] ldb, K-major.
// 128x128 CTA tile, KTILE=32, 3-stage cp.async (48KB), 8 warps (32x64 tile).
// ---------------------------------------------------------------------------
#define STG 16384
#define TC_SMEM (3*STG)

__global__ __launch_bounds__(256, 2)
void mma_gemm(const f16* __restrict__ Ahg, const f16* __restrict__ Bhg,
              float* __restrict__ Cg,
              int K, int lda, int ldb, int ldc, float alpha,
              int zdiv, ll sAa, ll sAb, ll sBa, ll sBb, ll sCa, ll sCb)
{
    extern __shared__ char smem_raw[];
    const uint32_t tiles = smem_u32(smem_raw);
    const int tid = threadIdx.x, wid = tid >> 5, lane = tid & 31;
    const int wm = wid & 3, wn = wid >> 2;

    const int z = blockIdx.z;
    const ll aoff = (ll)(z / zdiv) * sAa + (ll)(z % zdiv) * sAb;
    const ll boff = (ll)(z / zdiv) * sBa + (ll)(z % zdiv) * sBb;
    const ll coff = (ll)(z / zdiv) * sCa + (ll)(z % zdiv) * sCb;
    const f16* Ah = Ahg + aoff;
    const f16* Bh = Bhg + boff;

    const int bm = blockIdx.y << 7, bn = blockIdx.x << 7;
    const int nk = K >> 5;

    auto load_stage = [&](int kt) {
        const uint32_t st = tiles + (uint32_t)(kt % 3) * STG;
        const ll kb = (ll)kt * 32;
#pragma unroll
        for (int i = tid; i < 512; i += 256) {
            const int r = i >> 2, c = i & 3;
            const uint32_t sw = (uint32_t)r * 64u + (uint32_t)((c ^ ((r >> 1) & 3)) << 4);
            cp16(st        + sw, Ah + (ll)(bm + r) * lda + kb + c * 8);
            cp16(st + 8192 + sw, Bh + (ll)(bn + r) * ldb + kb + c * 8);
        }
        cpcommit();
    };

    float acc[2][8][4];
#pragma unroll
    for (int i = 0; i < 2; i++)
#pragma unroll
        for (int j = 0; j < 8; j++)
#pragma unroll
            for (int t = 0; t < 4; t++) acc[i][j][t] = 0.f;

    const int aRow  = wm * 32 + (lane & 15);
    const int aCpar = lane >> 4;
    const int bNadd = ((lane >> 4) << 3) + (lane & 7);
    const int bCpar = (lane >> 3) & 1;

    load_stage(0);
    if (nk > 1) load_stage(1); else cpcommit();

    for (int kt = 0; kt < nk; kt++) {
        if (kt >= nk - 2) cpwait0(); else cpwait1();
        __syncthreads();
        if (kt + 2 < nk) load_stage(kt + 2); else cpcommit();

        const uint32_t st = tiles + (uint32_t)(kt % 3) * STG;
#pragma unroll
        for (int ks = 0; ks < 2; ks++) {
            uint32_t ahf[2][4];
#pragma unroll
            for (int mt = 0; mt < 2; mt++) {
                const int row = aRow + mt * 16;
                const int ch = ks * 2 + aCpar;
                const uint32_t ad = st + (uint32_t)row * 64u + (uint32_t)((ch ^ ((row >> 1) & 3)) << 4);
                ldsm4(ahf[mt], ad);
            }
#pragma unroll
            for (int np = 0; np < 2; np++) {
                uint32_t bh[2][4];
#pragma unroll
                for (int t = 0; t < 2; t++) {
                    const int nt = np * 2 + t;
                    const int row = wn * 64 + nt * 16 + bNadd;
                    const int ch = ks * 2 + bCpar;
                    const uint32_t bd = st + 8192u + (uint32_t)row * 64u + (uint32_t)((ch ^ ((row >> 1) & 3)) << 4);
                    ldsm4(bh[t], bd);
                }
#pragma unroll
                for (int t = 0; t < 2; t++) {
                    const int nb = (np * 2 + t) * 2;
                    mma16816(acc[0][nb],   ahf[0], bh[t][0], bh[t][1]);
                    mma16816(acc[0][nb+1], ahf[0], bh[t][2], bh[t][3]);
                    mma16816(acc[1][nb],   ahf[1], bh[t][0], bh[t][1]);
                    mma16816(acc[1][nb+1], ahf[1], bh[t][2], bh[t][3]);
                }
            }
        }
    }

    const int erow = bm + wm * 32 + (lane >> 2);
    const int ecol = bn + wn * 64 + (lane & 3) * 2;
#pragma unroll
    for (int mt = 0; mt < 2; mt++) {
#pragma unroll
        for (int j = 0; j < 8; j++) {
            float* p0 = Cg + coff + (ll)(erow + mt*16)     * ldc + ecol + j*8;
            float* p1 = Cg + coff + (ll)(erow + mt*16 + 8) * ldc + ecol + j*8;
            *(float2*)p0 = make_float2(acc[mt][j][0]*alpha, acc[mt][j][1]*alpha);
            *(float2*)p1 = make_float2(acc[mt][j][2]*alpha, acc[mt][j][3]*alpha);
        }
    }
}

// ---------------------------------------------------------------------------
// Flash attention (fp16 single): CTA = 128 q-rows x 1 head.
// smem: Q 32KB | stage{K 16KB, VT 16KB} x2 = 96KB.
// ---------------------------------------------------------------------------
#define FA_SMEM 98304
#define FA_SCALE 0.08838834764831845f

__global__ __launch_bounds__(256, 1)
void flash_attn(const f16* __restrict__ qh, const f16* __restrict__ kh,
                const f16* __restrict__ vth, const float* __restrict__ mask,
                f16* __restrict__ oh)
{
    extern __shared__ char smem_raw[];
    const uint32_t sQ = smem_u32(smem_raw);          // Q 32K
    const uint32_t sKV = sQ + 32768;                 // 2 stages x 32KB
    const int tid = threadIdx.x, w = tid >> 5, lane = tid & 31;

    const int qt = blockIdx.x;
    const int z  = blockIdx.y;
    const int b  = z >> 4, h = z & 15;
    const int bS = b * SEQ;

    {
        const ll base = (ll)(bS + qt*128) * HID + h*128;
#pragma unroll
        for (int i = tid; i < 2048; i += 256) {
            const int r = i >> 4, c = i & 15;
            const uint32_t sw = (uint32_t)r*256u + (uint32_t)((c ^ (r & 15)) << 4);
            cp16(sQ + sw, qh + base + (ll)r * HID + c * 8);
        }
    }
    auto load_kv = [&](int kt) {
        const uint32_t st = sKV + (uint32_t)(kt & 1) * 32768;
        const ll kbase = (ll)(bS + kt*64) * HID + h*128;
#pragma unroll
        for (int i = tid; i < 1024; i += 256) {
            const int r = i >> 4, c = i & 15;
            const uint32_t sw = (uint32_t)r*256u + (uint32_t)((c ^ (r & 15)) << 4);
            cp16(st + sw, kh + kbase + (ll)r * HID + c * 8);
        }
        const ll vbase = (ll)z * 128 * SEQ + kt*64;
#pragma unroll
        for (int i = tid; i < 1024; i += 256) {
            const int r = i >> 3, c = i & 7;
            const uint32_t sw = (uint32_t)r*128u + (uint32_t)((c ^ (r & 7)) << 4);
            cp16(st + 16384 + sw, vth + vbase + (ll)r * SEQ + c * 8);
        }
        cpcommit();
    };

    float oacc[16][4];
#pragma unroll
    for (int i = 0; i < 16; i++)
#pragma unroll
        for (int t = 0; t < 4; t++) oacc[i][t] = 0.f;
    float m1 = -1e30f, m2 = -1e30f, l1 = 0.f, l2 = 0.f;

    const int aCpar = lane >> 4;
    const int bNadd = ((lane >> 4) << 3) + (lane & 7);
    const int bCpar = (lane >> 3) & 1;
    const int qRow  = w * 16 + (lane & 15);
    const int qpos1 = qt*128 + w*16 + (lane >> 2);
    const int colq  = (lane & 3) * 2;

    load_kv(0);
    const int NKT = SEQ / 64;

    for (int kt = 0; kt < NKT; kt++) {
        if (kt + 1 < NKT) { load_kv(kt + 1); cpwait1(); } else { cpwait0(); }
        __syncthreads();
        const uint32_t st = sKV + (uint32_t)(kt & 1) * 32768;

        float sacc[8][4];
#pragma unroll
        for (int j = 0; j < 8; j++)
#pragma unroll
            for (int t = 0; t < 4; t++) sacc[j][t] = 0.f;

#pragma unroll
        for (int ks = 0; ks < 8; ks++) {
            uint32_t ahf[4];
            {
                const int ch = ks*2 + aCpar;
                const uint32_t ad = sQ + (uint32_t)qRow*256u + (uint32_t)((ch ^ (qRow & 15)) << 4);
                ldsm4(ahf, ad);
            }
#pragma unroll
            for (int nt = 0; nt < 4; nt++) {
                const int row = nt*16 + bNadd;
                const int ch = ks*2 + bCpar;
                const uint32_t bd = st + (uint32_t)row*256u + (uint32_t)((ch ^ (row & 15)) << 4);
                uint32_t bh[4];
                ldsm4(bh, bd);
                mma16816(sacc[nt*2],   ahf, bh[0], bh[1]);
                mma16816(sacc[nt*2+1], ahf, bh[2], bh[3]);
            }
        }

        const int kbase = kt*64;
#pragma unroll
        for (int j = 0; j < 8; j++) {
            const int kposg = kbase + j*8 + colq;
            float2 mA = *(const float2*)(mask + (ll)qpos1 * SEQ + kposg);
            float2 mB = *(const float2*)(mask + (ll)(qpos1 + 8) * SEQ + kposg);
            sacc[j][0] = sacc[j][0]*FA_SCALE + mA.x;
            sacc[j][1] = sacc[j][1]*FA_SCALE + mA.y;
            sacc[j][2] = sacc[j][2]*FA_SCALE + mB.x;
            sacc[j][3] = sacc[j][3]*FA_SCALE + mB.y;
        }
        float mx1 = -1e30f, mx2 = -1e30f;
#pragma unroll
        for (int j = 0; j < 8; j++) {
            mx1 = fmaxf(mx1, fmaxf(sacc[j][0], sacc[j][1]));
            mx2 = fmaxf(mx2, fmaxf(sacc[j][2], sacc[j][3]));
        }
        mx1 = fmaxf(mx1, __shfl_xor_sync(0xffffffffu, mx1, 1));
        mx1 = fmaxf(mx1, __shfl_xor_sync(0xffffffffu, mx1, 2));
        mx2 = fmaxf(mx2, __shfl_xor_sync(0xffffffffu, mx2, 1));
        mx2 = fmaxf(mx2, __shfl_xor_sync(0xffffffffu, mx2, 2));
        const float nm1 = fmaxf(m1, mx1), nm2 = fmaxf(m2, mx2);
        const float al1 = __expf(m1 - nm1), al2 = __expf(m2 - nm2);
        m1 = nm1; m2 = nm2;
        float s1 = 0.f, s2 = 0.f;
#pragma unroll
        for (int j = 0; j < 8; j++) {
            sacc[j][0] = __expf(sacc[j][0] - nm1);
            sacc[j][1] = __expf(sacc[j][1] - nm1);
            sacc[j][2] = __expf(sacc[j][2] - nm2);
            sacc[j][3] = __expf(sacc[j][3] - nm2);
            s1 += sacc[j][0] + sacc[j][1];
            s2 += sacc[j][2] + sacc[j][3];
        }
        s1 += __shfl_xor_sync(0xffffffffu, s1, 1);
        s1 += __shfl_xor_sync(0xffffffffu, s1, 2);
        s2 += __shfl_xor_sync(0xffffffffu, s2, 1);
        s2 += __shfl_xor_sync(0xffffffffu, s2, 2);
        l1 = l1*al1 + s1;
        l2 = l2*al2 + s2;
#pragma unroll
        for (int i = 0; i < 16; i++) {
            oacc[i][0] *= al1; oacc[i][1] *= al1;
            oacc[i][2] *= al2; oacc[i][3] *= al2;
        }

        // O += P @ V : P single fp16
#pragma unroll
        for (int kk = 0; kk < 4; kk++) {
            uint32_t pah[4];
            {
                __half2 t0(__float2half_rn(sacc[2*kk][0]),   __float2half_rn(sacc[2*kk][1]));
                __half2 t1(__float2half_rn(sacc[2*kk][2]),   __float2half_rn(sacc[2*kk][3]));
                __half2 t2(__float2half_rn(sacc[2*kk+1][0]), __float2half_rn(sacc[2*kk+1][1]));
                __half2 t3(__float2half_rn(sacc[2*kk+1][2]), __float2half_rn(sacc[2*kk+1][3]));
                pah[0] = *(uint32_t*)&t0; pah[1] = *(uint32_t*)&t1;
                pah[2] = *(uint32_t*)&t2; pah[3] = *(uint32_t*)&t3;
            }
#pragma unroll
            for (int nt = 0; nt < 8; nt++) {
                const int row = nt*16 + bNadd;
                const int ch = kk*2 + bCpar;
                const uint32_t bd = st + 16384u + (uint32_t)row*128u + (uint32_t)((ch ^ (row & 7)) << 4);
                uint32_t bh[4];
                ldsm4(bh, bd);
                mma16816(oacc[nt*2],   pah, bh[0], bh[1]);
                mma16816(oacc[nt*2+1], pah, bh[2], bh[3]);
            }
        }
        __syncthreads();
    }

    const float inv1 = 1.f / l1, inv2 = 1.f / l2;
    const ll row1 = (ll)(bS + qpos1);
#pragma unroll
    for (int nt = 0; nt < 16; nt++) {
        const int col = h*128 + nt*8 + colq;
        __half2 th(__float2half_rn(oacc[nt][0]*inv1), __float2half_rn(oacc[nt][1]*inv1));
        __half2 uh(__float2half_rn(oacc[nt][2]*inv2), __float2half_rn(oacc[nt][3]*inv2));
        *(__half2*)(oh + row1*HID + col)     = th;
        *(__half2*)(oh + (row1+8)*HID + col) = uh;
    }
}

// ------------------------- reductions -------------------------
__device__ __forceinline__ float wsum(float v) {
#pragma unroll
    for (int o = 16; o; o >>= 1) v += __shfl_xor_sync(0xffffffffu, v, o);
    return v;
}
__device__ __forceinline__ float bsum(float v) {
    __shared__ float sh[8];
    v = wsum(v); __syncthreads();
    if ((threadIdx.x & 31) == 0) sh[threadIdx.x >> 5] = v;
    __syncthreads();
    float r = 0.f;
#pragma unroll
    for (int i = 0; i < 8; i++) r += sh[i];
    return r;
}

// ------------------------- elementwise kernels -------------------------
__global__ __launch_bounds__(256)
void roundw_kernel(const float* __restrict__ s, f16* __restrict__ oh, int n4)
{
    const int i = blockIdx.x * 256 + threadIdx.x;
    if (i >= n4) return;
    float4 v = ((const float4*)s)[i];
    ((__half2*)oh)[2*i]   = __half2(__float2half_rn(v.x), __float2half_rn(v.y));
    ((__half2*)oh)[2*i+1] = __half2(__float2half_rn(v.z), __float2half_rn(v.w));
}

__global__ __launch_bounds__(256)
void rmsnorm_round(const float* __restrict__ in, const float* __restrict__ w,
                   f16* __restrict__ oh)
{
    const ll base = (ll)blockIdx.x * HID;
    const float4* xin = (const float4*)(in + base);
    float ss = 0.f;
    for (int i = threadIdx.x; i < HID/4; i += 256) {
        float4 v = xin[i];
        ss += v.x*v.x + v.y*v.y + v.z*v.z + v.w*v.w;
    }
    ss = bsum(ss);
    const float r = rsqrtf(ss * (1.f/HID) + RMS_EPS);
    for (int i = threadIdx.x; i < HID/4; i += 256) {
        float4 v = xin[i];
        float4 ww = ((const float4*)w)[i];
        ((__half2*)(oh + base))[2*i]   = __half2(__float2half_rn(v.x*r*ww.x), __float2half_rn(v.y*r*ww.y));
        ((__half2*)(oh + base))[2*i+1] = __half2(__float2half_rn(v.z*r*ww.z), __float2half_rn(v.w*r*ww.w));
    }
}

__global__ __launch_bounds__(256)
void rmsadd_kernel(float* __restrict__ x, const float* __restrict__ w)
{
    const ll base = (ll)blockIdx.x * HID;
    float4* xp = (float4*)(x + base);
    float ss = 0.f;
    for (int i = threadIdx.x; i < HID/4; i += 256) {
        float4 v = xp[i];
        ss += v.x*v.x + v.y*v.y + v.z*v.z + v.w*v.w;
    }
    ss = bsum(ss);
    const float r = rsqrtf(ss * (1.f/HID) + RMS_EPS);
    for (int i = threadIdx.x; i < HID/4; i += 256) {
        float4 v = xp[i];
        float4 ww = ((const float4*)w)[i];
        xp[i] = make_float4(v.x*(1.f+r*ww.x), v.y*(1.f+r*ww.y), v.z*(1.f+r*ww.z), v.w*(1.f+r*ww.w));
    }
}

__global__ void rope_round(const float* __restrict__ src, f16* __restrict__ oh)
{
    const int idx = blockIdx.x * blockDim.x + threadIdx.x;
    if (idx >= ROWS * NHEAD * 64) return;
    const int j = idx & 63, h = (idx >> 6) & (NHEAD-1), row = idx >> 10;
    const int pos = row & (SEQ - 1);
    const float inv = (float)exp(-(double)(2*j) / (double)HDIM * log(10000.0));
    float s_, c;
    sincosf((float)pos * inv, &s_, &c);
    const ll p0 = (ll)row * HID + h * HDIM + j;
    const float q0 = src[p0], q1 = src[p0 + 64];
    oh[p0]    = __float2half_rn(q0*c - q1*s_);
    oh[p0+64] = __float2half_rn(q1*c + q0*s_);
}

__global__ void vtrans_kernel(const float* __restrict__ v, f16* __restrict__ oh)
{
    __shared__ float t[32][33];
    const int z = blockIdx.z, b = z >> 4, h = z & 15;
    const int s0 = blockIdx.x * 32, d0 = blockIdx.y * 32;
    const int tx = threadIdx.x, ty = threadIdx.y;
#pragma unroll
    for (int i = 0; i < 4; i++) {
        const int s = s0 + ty + i*8;
        t[ty + i*8][tx] = v[((ll)(b*SEQ + s)) * HID + h*HDIM + d0 + tx];
    }
    __syncthreads();
#pragma unroll
    for (int i = 0; i < 4; i++) {
        const int d = d0 + ty + i*8;
        oh[((ll)z * HDIM + d) * SEQ + s0 + tx] = __float2half_rn(t[tx][ty + i*8]);
    }
}

__device__ __forceinline__ float sigm(float z) { return 1.f / (1.f + expf(-z)); }

__global__ void highway_kernel(const float* __restrict__ g, const float* __restrict__ hh,
                               const float* __restrict__ bias, float* __restrict__ out, int n4)
{
    const int i = blockIdx.x * blockDim.x + threadIdx.x;
    if (i >= n4) return;
    float4 gv = ((const float4*)g)[i], hv = ((const float4*)hh)[i];
    float4 bv = ((const float4*)bias)[i & (HID/4 - 1)];
    ((float4*)out)[i] = make_float4(hv.x*sigm(gv.x+bv.x), hv.y*sigm(gv.y+bv.y),
                                    hv.z*sigm(gv.z+bv.z), hv.w*sigm(gv.w+bv.w));
}

__global__ void combinex_kernel(const float* __restrict__ xm, const float* __restrict__ mod,
                                const float* __restrict__ g, const float* __restrict__ hh,
                                const float* __restrict__ bias, float* __restrict__ out, int n4)
{
    const int i = blockIdx.x * blockDim.x + threadIdx.x;
    if (i >= n4) return;
    float4 xv = ((const float4*)xm)[i], mv = ((const float4*)mod)[i];
    float4 gv = ((const float4*)g)[i], hv = ((const float4*)hh)[i];
    float4 bv = ((const float4*)bias)[i & (HID/4 - 1)];
    ((float4*)out)[i] = make_float4(xv.x+mv.x+hv.x*sigm(gv.x+bv.x), xv.y+mv.y+hv.y*sigm(gv.y+bv.y),
                                    xv.z+mv.z+hv.z*sigm(gv.z+bv.z), xv.w+mv.w+hv.w*sigm(gv.w+bv.w));
}

__global__ void silumul_round(const float* __restrict__ g, const float* __restrict__ u,
                              f16* __restrict__ oh, int n4)
{
    const int i = blockIdx.x * blockDim.x + threadIdx.x;
    if (i >= n4) return;
    float4 gv = ((const float4*)g)[i], uv = ((const float4*)u)[i];
    ((__half2*)oh)[2*i]   = __half2(__float2half_rn(gv.x*sigm(gv.x)*uv.x),
                                    __float2half_rn(gv.y*sigm(gv.y)*uv.y));
    ((__half2*)oh)[2*i+1] = __half2(__float2half_rn(gv.z*sigm(gv.z)*uv.z),
                                    __float2half_rn(gv.w*sigm(gv.w)*uv.w));
}

__global__ void add2_kernel(const float* __restrict__ a, const float* __restrict__ b,
                            float* __restrict__ out, int n4)
{
    const int i = blockIdx.x * blockDim.x + threadIdx.x;
    if (i >= n4) return;
    float4 av = ((const float4*)a)[i], bv = ((const float4*)b)[i];
    ((float4*)out)[i] = make_float4(av.x+bv.x, av.y+bv.y, av.z+bv.z, av.w+bv.w);
}

// ------------------------- launch -------------------------
extern "C" void kernel_launch(void* const* d_in, const int* in_sizes, int n_in,
                              void* d_out, int out_size)
{
    const float* x_mod = (const float*)d_in[0];
    const float* x_back= (const float*)d_in[1];
    const float* mask  = (const float*)d_in[2];
    const float* wq = (const float*)d_in[3];
    const float* wk = (const float*)d_in[4];
    const float* wv = (const float*)d_in[5];
    const float* wo = (const float*)d_in[6];
    const float* cross_ln_w = (const float*)d_in[7];
    const float* fb_w = (const float*)d_in[8];
    const float* fb_g = (const float*)d_in[9];
    const float* fb_gb= (const float*)d_in[10];
    const float* dr_w = (const float*)d_in[11];
    const float* dr_g = (const float*)d_in[12];
    const float* dr_gb= (const float*)d_in[13];
    const float* in_ln_w   = (const float*)d_in[14];
    const float* post_ln_w = (const float*)d_in[15];
    const float* w_gate = (const float*)d_in[16];
    const float* w_up   = (const float*)d_in[17];
    const float* w_down = (const float*)d_in[18];

    float* outx = (float*)d_out;
    float* outd = outx + (size_t)ROWS * HID;

    float *q,*k,*v,*mod,*t1,*t2,*x,*gg,*uu;
    f16 *wh,*ah;
    cudaGetSymbolAddress((void**)&q, g_q);   cudaGetSymbolAddress((void**)&k, g_k);
    cudaGetSymbolAddress((void**)&v, g_v);
    cudaGetSymbolAddress((void**)&mod, g_mod); cudaGetSymbolAddress((void**)&t1, g_t1);
    cudaGetSymbolAddress((void**)&t2, g_t2); cudaGetSymbolAddress((void**)&x, g_x);
    cudaGetSymbolAddress((void**)&gg, g_gate); cudaGetSymbolAddress((void**)&uu, g_up);
    cudaGetSymbolAddress((void**)&wh, g_wh);
    cudaGetSymbolAddress((void**)&ah, g_ah);

    cudaFuncSetAttribute(mma_gemm,   cudaFuncAttributeMaxDynamicSharedMemorySize, TC_SMEM);
    cudaFuncSetAttribute(flash_attn, cudaFuncAttributeMaxDynamicSharedMemorySize, FA_SMEM);

    const int n4h = (int)(RH/4), n4f = (int)(GGN/4), n4w = (int)(H2/4), n4ff = (int)(FF2/4);
    const dim3 B256(256);

    auto gemm = [&](const f16* pah, const f16* pbh,
                    float* c, int M, int N, int K, int lda, int ldb, int ldc, float alpha,
                    int gz, int zdiv, ll saa, ll sab, ll sba, ll sbb, ll sca, ll scb) {
        dim3 g(N/128, M/128, gz);
        mma_gemm<<<g, 256, TC_SMEM>>>(pah, pbh, c, K, lda, ldb, ldc, alpha,
                                      zdiv, saa, sab, sba, sbb, sca, scb);
    };

    // ---- rounds + projections ----
    rmsnorm_round<<<ROWS, B256>>>(x_mod, cross_ln_w, ah+OQN);
    roundw_kernel<<<n4w/256, B256>>>(wq, wh+OWQ, n4w);
    roundw_kernel<<<n4h/256, B256>>>(x_back, ah+OXB, n4h);
    roundw_kernel<<<n4w/256, B256>>>(wk, wh+OWK, n4w);
    roundw_kernel<<<n4w/256, B256>>>(wv, wh+OWV, n4w);
    gemm(ah+OQN, wh+OWQ, q, ROWS, HID, HID, HID, HID, HID, 1.f, 1,1, 0,0,0,0,0,0);
    gemm(ah+OXB, wh+OWK, k, ROWS, HID, HID, HID, HID, HID, 1.f, 1,1, 0,0,0,0,0,0);
    gemm(ah+OXB, wh+OWV, v, ROWS, HID, HID, HID, HID, HID, 1.f, 1,1, 0,0,0,0,0,0);

    roundw_kernel<<<n4h/256, B256>>>(x_mod, ah+OXM, n4h);
    roundw_kernel<<<n4w/256, B256>>>(wo,   wh+OWO,  n4w);
    roundw_kernel<<<n4w/256, B256>>>(fb_w, wh+OFBW, n4w);
    roundw_kernel<<<n4w/256, B256>>>(fb_g, wh+OFBG, n4w);
    roundw_kernel<<<n4w/256, B256>>>(dr_w, wh+ODRW, n4w);
    roundw_kernel<<<n4w/256, B256>>>(dr_g, wh+ODRG, n4w);
    roundw_kernel<<<n4ff/256, B256>>>(w_gate, wh+OWG, n4ff);
    roundw_kernel<<<n4ff/256, B256>>>(w_up,   wh+OWU, n4ff);
    roundw_kernel<<<n4ff/256, B256>>>(w_down, wh+OWD, n4ff);

    const int ropeN = ROWS * NHEAD * 64;
    rope_round<<<(ropeN+255)/256, B256>>>(q, ah+OQ);
    rope_round<<<(ropeN+255)/256, B256>>>(k, ah+OK2);
    vtrans_kernel<<<dim3(SEQ/32, HDIM/32, BATCH*NHEAD), dim3(32,8)>>>(v, ah+OVT);

    // ---- fused flash attention -> att fp16 (OATT) ----
    flash_attn<<<dim3(SEQ/128, BATCH*NHEAD), B256, FA_SMEM>>>(
        ah+OQ, ah+OK2, ah+OVT, mask, ah+OATT);
    gemm(ah+OATT, wh+OWO, mod, ROWS, HID, HID, HID, HID, HID, 1.f, 1,1, 0,0,0,0,0,0);

    // ---- feedback highway -> delta ----
    gemm(ah+OXM, wh+OFBG, t1, ROWS, HID, HID, HID, HID, HID, 1.f, 1,1, 0,0,0,0,0,0);
    gemm(ah+OXM, wh+OFBW, t2, ROWS, HID, HID, HID, HID, HID, 1.f, 1,1, 0,0,0,0,0,0);
    highway_kernel<<<n4h/256, B256>>>(t1, t2, fb_gb, outd, n4h);

    // ---- driver highway + combine ----
    gemm(ah+OXB, wh+ODRG, t1, ROWS, HID, HID, HID, HID, HID, 1.f, 1,1, 0,0,0,0,0,0);
    gemm(ah+OXB, wh+ODRW, t2, ROWS, HID, HID, HID, HID, HID, 1.f, 1,1, 0,0,0,0,0,0);
    combinex_kernel<<<n4h/256, B256>>>(x_mod, mod, t1, t2, dr_gb, x, n4h);

    // ---- decoder ----
    rmsadd_kernel<<<ROWS, B256>>>(x, in_ln_w);
    rmsnorm_round<<<ROWS, B256>>>(x, post_ln_w, ah+OHB);
    gemm(ah+OHB, wh+OWG, gg, ROWS, FFD, HID, HID, HID, FFD, 1.f, 1,1, 0,0,0,0,0,0);
    gemm(ah+OHB, wh+OWU, uu, ROWS, FFD, HID, HID, HID, FFD, 1.f, 1,1, 0,0,0,0,0,0);
    silumul_round<<<n4f/256, B256>>>(gg, uu, ah+OGG, n4f);
    gemm(ah+OGG, wh+OWD, mod, ROWS, HID, FFD, FFD, FFD, HID, 1.f, 1,1, 0,0,0,0,0,0);
    add2_kernel<<<n4h/256, B256>>>(x, mod, outx, n4h);
}

// round 11
// speedup vs baseline: 2.1822x; 1.0043x over previous
#include <cuda_runtime.h>
#include <cuda_fp16.h>
#include <cstdint>
#include <math.h>
using f16 = __half;
typedef long long ll;

#define BATCH 2
#define SEQ 2048
#define HID 2048
#define NHEAD 16
#define HDIM 128
#define FFD 8192
#define ROWS 4096
#define RMS_EPS 1e-5f
#define RH 8388608LL
#define H2 4194304LL
#define FF2 16777216LL
#define GGN 33554432LL

// ------------------------- scratch -------------------------
__device__ float g_mod[RH], g_x[RH];
__device__ f16 g_wh[8*H2+3*FF2];     // weights fp16
__device__ f16 g_ah[8*RH+GGN];       // activations fp16
__device__ f16 g_t1h[RH], g_t2h[RH], g_modh[RH];
__device__ f16 g_gg16[GGN], g_uu16[GGN];

// weight arena offsets
#define OWQ  (0*H2)
#define OWK  (1*H2)
#define OWV  (2*H2)
#define OWO  (3*H2)
#define OFBW (4*H2)
#define OFBG (5*H2)
#define ODRW (6*H2)
#define ODRG (7*H2)
#define OWG  (8*H2)
#define OWU  (8*H2+FF2)
#define OWD  (8*H2+2*FF2)
// activation arena offsets
#define OQN  (0*RH)   // rms(x_mod) ; later V-projection temp is separate (OVP)
#define OXB  (1*RH)
#define OXM  (2*RH)
#define OQ   (3*RH)   // q (post-proj, rope in place)
#define OK2  (4*RH)   // k (post-proj, rope in place)
#define OVT  (5*RH)   // V transposed
#define OATT (6*RH)
#define OHB  (7*RH)
#define OGG  (8*RH)   // silu(gate)*up, GGN elems
#define OVP  (0*RH)   // v projection temp (reuses OQN after it's consumed? NO - careful)

// ------------------------- PTX helpers -------------------------
__device__ __forceinline__ uint32_t smem_u32(const void* p) {
    uint32_t a;
    asm("{ .reg .u64 t; cvta.to.shared.u64 t, %1; cvt.u32.u64 %0, t; }" : "=r"(a) : "l"(p));
    return a;
}
__device__ __forceinline__ void cp16(uint32_t s, const void* g) {
    asm volatile("cp.async.cg.shared.global [%0], [%1], 16;" :: "r"(s), "l"(g));
}
__device__ __forceinline__ void cpcommit() { asm volatile("cp.async.commit_group;" ::: "memory"); }
__device__ __forceinline__ void cpwait0()  { asm volatile("cp.async.wait_group 0;" ::: "memory"); }
__device__ __forceinline__ void cpwait1()  { asm volatile("cp.async.wait_group 1;" ::: "memory"); }

__device__ __forceinline__ void ldsm4(uint32_t* r, uint32_t addr) {
    asm volatile("ldmatrix.sync.aligned.m8n8.x4.shared.b16 {%0,%1,%2,%3}, [%4];"
        : "=r"(r[0]), "=r"(r[1]), "=r"(r[2]), "=r"(r[3]) : "r"(addr));
}
__device__ __forceinline__ void mma16816(float* c, const uint32_t* a, uint32_t b0, uint32_t b1) {
    asm volatile("mma.sync.aligned.m16n8k16.row.col.f32.f16.f16.f32 "
        "{%0,%1,%2,%3}, {%4,%5,%6,%7}, {%8,%9}, {%0,%1,%2,%3};"
        : "+f"(c[0]), "+f"(c[1]), "+f"(c[2]), "+f"(c[3])
        : "r"(a[0]), "r"(a[1]), "r"(a[2]), "r"(a[3]), "r"(b0), "r"(b1));
}

// ---------------------------------------------------------------------------
// fp16 HMMA GEMM, templated output (float or __half).
// C = alpha * A @ B^T. 128x128 CTA tile, KTILE=32, 3-stage cp.async, 8 warps.
// ---------------------------------------------------------------------------
#define STG 16384
#define TC_SMEM (3*STG)

template<typename OT>
__global__ __launch_bounds__(256, 2)
void mma_gemm(const f16* __restrict__ Ahg, const f16* __restrict__ Bhg,
              OT* __restrict__ Cg,
              int K, int lda, int ldb, int ldc, float alpha,
              int zdiv, ll sAa, ll sAb, ll sBa, ll sBb, ll sCa, ll sCb)
{
    extern __shared__ char smem_raw[];
    const uint32_t tiles = smem_u32(smem_raw);
    const int tid = threadIdx.x, wid = tid >> 5, lane = tid & 31;
    const int wm = wid & 3, wn = wid >> 2;

    const int z = blockIdx.z;
    const ll aoff = (ll)(z / zdiv) * sAa + (ll)(z % zdiv) * sAb;
    const ll boff = (ll)(z / zdiv) * sBa + (ll)(z % zdiv) * sBb;
    const ll coff = (ll)(z / zdiv) * sCa + (ll)(z % zdiv) * sCb;
    const f16* Ah = Ahg + aoff;
    const f16* Bh = Bhg + boff;

    const int bm = blockIdx.y << 7, bn = blockIdx.x << 7;
    const int nk = K >> 5;

    auto load_stage = [&](int kt) {
        const uint32_t st = tiles + (uint32_t)(kt % 3) * STG;
        const ll kb = (ll)kt * 32;
#pragma unroll
        for (int i = tid; i < 512; i += 256) {
            const int r = i >> 2, c = i & 3;
            const uint32_t sw = (uint32_t)r * 64u + (uint32_t)((c ^ ((r >> 1) & 3)) << 4);
            cp16(st        + sw, Ah + (ll)(bm + r) * lda + kb + c * 8);
            cp16(st + 8192 + sw, Bh + (ll)(bn + r) * ldb + kb + c * 8);
        }
        cpcommit();
    };

    float acc[2][8][4];
#pragma unroll
    for (int i = 0; i < 2; i++)
#pragma unroll
        for (int j = 0; j < 8; j++)
#pragma unroll
            for (int t = 0; t < 4; t++) acc[i][j][t] = 0.f;

    const int aRow  = wm * 32 + (lane & 15);
    const int aCpar = lane >> 4;
    const int bNadd = ((lane >> 4) << 3) + (lane & 7);
    const int bCpar = (lane >> 3) & 1;

    load_stage(0);
    if (nk > 1) load_stage(1); else cpcommit();

    for (int kt = 0; kt < nk; kt++) {
        if (kt >= nk - 2) cpwait0(); else cpwait1();
        __syncthreads();
        if (kt + 2 < nk) load_stage(kt + 2); else cpcommit();

        const uint32_t st = tiles + (uint32_t)(kt % 3) * STG;
#pragma unroll
        for (int ks = 0; ks < 2; ks++) {
            uint32_t ahf[2][4];
#pragma unroll
            for (int mt = 0; mt < 2; mt++) {
                const int row = aRow + mt * 16;
                const int ch = ks * 2 + aCpar;
                const uint32_t ad = st + (uint32_t)row * 64u + (uint32_t)((ch ^ ((row >> 1) & 3)) << 4);
                ldsm4(ahf[mt], ad);
            }
#pragma unroll
            for (int np = 0; np < 2; np++) {
                uint32_t bh[2][4];
#pragma unroll
                for (int t = 0; t < 2; t++) {
                    const int nt = np * 2 + t;
                    const int row = wn * 64 + nt * 16 + bNadd;
                    const int ch = ks * 2 + bCpar;
                    const uint32_t bd = st + 8192u + (uint32_t)row * 64u + (uint32_t)((ch ^ ((row >> 1) & 3)) << 4);
                    ldsm4(bh[t], bd);
                }
#pragma unroll
                for (int t = 0; t < 2; t++) {
                    const int nb = (np * 2 + t) * 2;
                    mma16816(acc[0][nb],   ahf[0], bh[t][0], bh[t][1]);
                    mma16816(acc[0][nb+1], ahf[0], bh[t][2], bh[t][3]);
                    mma16816(acc[1][nb],   ahf[1], bh[t][0], bh[t][1]);
                    mma16816(acc[1][nb+1], ahf[1], bh[t][2], bh[t][3]);
                }
            }
        }
    }

    const int erow = bm + wm * 32 + (lane >> 2);
    const int ecol = bn + wn * 64 + (lane & 3) * 2;
#pragma unroll
    for (int mt = 0; mt < 2; mt++) {
#pragma unroll
        for (int j = 0; j < 8; j++) {
            OT* p0 = Cg + coff + (ll)(erow + mt*16)     * ldc + ecol + j*8;
            OT* p1 = Cg + coff + (ll)(erow + mt*16 + 8) * ldc + ecol + j*8;
            if constexpr (sizeof(OT) == 4) {
                *(float2*)p0 = make_float2(acc[mt][j][0]*alpha, acc[mt][j][1]*alpha);
                *(float2*)p1 = make_float2(acc[mt][j][2]*alpha, acc[mt][j][3]*alpha);
            } else {
                __half2 h0(__float2half_rn(acc[mt][j][0]*alpha), __float2half_rn(acc[mt][j][1]*alpha));
                __half2 h1(__float2half_rn(acc[mt][j][2]*alpha), __float2half_rn(acc[mt][j][3]*alpha));
                *(__half2*)p0 = h0;
                *(__half2*)p1 = h1;
            }
        }
    }
}

// ---------------------------------------------------------------------------
// Flash attention (fp16): CTA = 128 q-rows x 1 head. smem 96KB.
// ---------------------------------------------------------------------------
#define FA_SMEM 98304
#define FA_SCALE 0.08838834764831845f

__global__ __launch_bounds__(256, 1)
void flash_attn(const f16* __restrict__ qh, const f16* __restrict__ kh,
                const f16* __restrict__ vth, const float* __restrict__ mask,
                f16* __restrict__ oh)
{
    extern __shared__ char smem_raw[];
    const uint32_t sQ = smem_u32(smem_raw);
    const uint32_t sKV = sQ + 32768;
    const int tid = threadIdx.x, w = tid >> 5, lane = tid & 31;

    const int qt = blockIdx.x;
    const int z  = blockIdx.y;
    const int b  = z >> 4, h = z & 15;
    const int bS = b * SEQ;

    {
        const ll base = (ll)(bS + qt*128) * HID + h*128;
#pragma unroll
        for (int i = tid; i < 2048; i += 256) {
            const int r = i >> 4, c = i & 15;
            const uint32_t sw = (uint32_t)r*256u + (uint32_t)((c ^ (r & 15)) << 4);
            cp16(sQ + sw, qh + base + (ll)r * HID + c * 8);
        }
    }
    auto load_kv = [&](int kt) {
        const uint32_t st = sKV + (uint32_t)(kt & 1) * 32768;
        const ll kbase = (ll)(bS + kt*64) * HID + h*128;
#pragma unroll
        for (int i = tid; i < 1024; i += 256) {
            const int r = i >> 4, c = i & 15;
            const uint32_t sw = (uint32_t)r*256u + (uint32_t)((c ^ (r & 15)) << 4);
            cp16(st + sw, kh + kbase + (ll)r * HID + c * 8);
        }
        const ll vbase = (ll)z * 128 * SEQ + kt*64;
#pragma unroll
        for (int i = tid; i < 1024; i += 256) {
            const int r = i >> 3, c = i & 7;
            const uint32_t sw = (uint32_t)r*128u + (uint32_t)((c ^ (r & 7)) << 4);
            cp16(st + 16384 + sw, vth + vbase + (ll)r * SEQ + c * 8);
        }
        cpcommit();
    };

    float oacc[16][4];
#pragma unroll
    for (int i = 0; i < 16; i++)
#pragma unroll
        for (int t = 0; t < 4; t++) oacc[i][t] = 0.f;
    float m1 = -1e30f, m2 = -1e30f, l1 = 0.f, l2 = 0.f;

    const int aCpar = lane >> 4;
    const int bNadd = ((lane >> 4) << 3) + (lane & 7);
    const int bCpar = (lane >> 3) & 1;
    const int qRow  = w * 16 + (lane & 15);
    const int qpos1 = qt*128 + w*16 + (lane >> 2);
    const int colq  = (lane & 3) * 2;

    load_kv(0);
    const int NKT = SEQ / 64;

    for (int kt = 0; kt < NKT; kt++) {
        if (kt + 1 < NKT) { load_kv(kt + 1); cpwait1(); } else { cpwait0(); }
        __syncthreads();
        const uint32_t st = sKV + (uint32_t)(kt & 1) * 32768;

        float sacc[8][4];
#pragma unroll
        for (int j = 0; j < 8; j++)
#pragma unroll
            for (int t = 0; t < 4; t++) sacc[j][t] = 0.f;

#pragma unroll
        for (int ks = 0; ks < 8; ks++) {
            uint32_t ahf[4];
            {
                const int ch = ks*2 + aCpar;
                const uint32_t ad = sQ + (uint32_t)qRow*256u + (uint32_t)((ch ^ (qRow & 15)) << 4);
                ldsm4(ahf, ad);
            }
#pragma unroll
            for (int nt = 0; nt < 4; nt++) {
                const int row = nt*16 + bNadd;
                const int ch = ks*2 + bCpar;
                const uint32_t bd = st + (uint32_t)row*256u + (uint32_t)((ch ^ (row & 15)) << 4);
                uint32_t bh[4];
                ldsm4(bh, bd);
                mma16816(sacc[nt*2],   ahf, bh[0], bh[1]);
                mma16816(sacc[nt*2+1], ahf, bh[2], bh[3]);
            }
        }

        const int kbase = kt*64;
#pragma unroll
        for (int j = 0; j < 8; j++) {
            const int kposg = kbase + j*8 + colq;
            float2 mA = *(const float2*)(mask + (ll)qpos1 * SEQ + kposg);
            float2 mB = *(const float2*)(mask + (ll)(qpos1 + 8) * SEQ + kposg);
            sacc[j][0] = sacc[j][0]*FA_SCALE + mA.x;
            sacc[j][1] = sacc[j][1]*FA_SCALE + mA.y;
            sacc[j][2] = sacc[j][2]*FA_SCALE + mB.x;
            sacc[j][3] = sacc[j][3]*FA_SCALE + mB.y;
        }
        float mx1 = -1e30f, mx2 = -1e30f;
#pragma unroll
        for (int j = 0; j < 8; j++) {
            mx1 = fmaxf(mx1, fmaxf(sacc[j][0], sacc[j][1]));
            mx2 = fmaxf(mx2, fmaxf(sacc[j][2], sacc[j][3]));
        }
        mx1 = fmaxf(mx1, __shfl_xor_sync(0xffffffffu, mx1, 1));
        mx1 = fmaxf(mx1, __shfl_xor_sync(0xffffffffu, mx1, 2));
        mx2 = fmaxf(mx2, __shfl_xor_sync(0xffffffffu, mx2, 1));
        mx2 = fmaxf(mx2, __shfl_xor_sync(0xffffffffu, mx2, 2));
        const float nm1 = fmaxf(m1, mx1), nm2 = fmaxf(m2, mx2);
        const float al1 = __expf(m1 - nm1), al2 = __expf(m2 - nm2);
        m1 = nm1; m2 = nm2;
        float s1 = 0.f, s2 = 0.f;
#pragma unroll
        for (int j = 0; j < 8; j++) {
            sacc[j][0] = __expf(sacc[j][0] - nm1);
            sacc[j][1] = __expf(sacc[j][1] - nm1);
            sacc[j][2] = __expf(sacc[j][2] - nm2);
            sacc[j][3] = __expf(sacc[j][3] - nm2);
            s1 += sacc[j][0] + sacc[j][1];
            s2 += sacc[j][2] + sacc[j][3];
        }
        s1 += __shfl_xor_sync(0xffffffffu, s1, 1);
        s1 += __shfl_xor_sync(0xffffffffu, s1, 2);
        s2 += __shfl_xor_sync(0xffffffffu, s2, 1);
        s2 += __shfl_xor_sync(0xffffffffu, s2, 2);
        l1 = l1*al1 + s1;
        l2 = l2*al2 + s2;
#pragma unroll
        for (int i = 0; i < 16; i++) {
            oacc[i][0] *= al1; oacc[i][1] *= al1;
            oacc[i][2] *= al2; oacc[i][3] *= al2;
        }

#pragma unroll
        for (int kk = 0; kk < 4; kk++) {
            uint32_t pah[4];
            {
                __half2 t0(__float2half_rn(sacc[2*kk][0]),   __float2half_rn(sacc[2*kk][1]));
                __half2 t1(__float2half_rn(sacc[2*kk][2]),   __float2half_rn(sacc[2*kk][3]));
                __half2 t2(__float2half_rn(sacc[2*kk+1][0]), __float2half_rn(sacc[2*kk+1][1]));
                __half2 t3(__float2half_rn(sacc[2*kk+1][2]), __float2half_rn(sacc[2*kk+1][3]));
                pah[0] = *(uint32_t*)&t0; pah[1] = *(uint32_t*)&t1;
                pah[2] = *(uint32_t*)&t2; pah[3] = *(uint32_t*)&t3;
            }
#pragma unroll
            for (int nt = 0; nt < 8; nt++) {
                const int row = nt*16 + bNadd;
                const int ch = kk*2 + bCpar;
                const uint32_t bd = st + 16384u + (uint32_t)row*128u + (uint32_t)((ch ^ (row & 7)) << 4);
                uint32_t bh[4];
                ldsm4(bh, bd);
                mma16816(oacc[nt*2],   pah, bh[0], bh[1]);
                mma16816(oacc[nt*2+1], pah, bh[2], bh[3]);
            }
        }
        __syncthreads();
    }

    const float inv1 = 1.f / l1, inv2 = 1.f / l2;
    const ll row1 = (ll)(bS + qpos1);
#pragma unroll
    for (int nt = 0; nt < 16; nt++) {
        const int col = h*128 + nt*8 + colq;
        __half2 th(__float2half_rn(oacc[nt][0]*inv1), __float2half_rn(oacc[nt][1]*inv1));
        __half2 uh(__float2half_rn(oacc[nt][2]*inv2), __float2half_rn(oacc[nt][3]*inv2));
        *(__half2*)(oh + row1*HID + col)     = th;
        *(__half2*)(oh + (row1+8)*HID + col) = uh;
    }
}

// ------------------------- reductions -------------------------
__device__ __forceinline__ float wsum(float v) {
#pragma unroll
    for (int o = 16; o; o >>= 1) v += __shfl_xor_sync(0xffffffffu, v, o);
    return v;
}
__device__ __forceinline__ float bsum(float v) {
    __shared__ float sh[8];
    v = wsum(v); __syncthreads();
    if ((threadIdx.x & 31) == 0) sh[threadIdx.x >> 5] = v;
    __syncthreads();
    float r = 0.f;
#pragma unroll
    for (int i = 0; i < 8; i++) r += sh[i];
    return r;
}

// ------------------------- elementwise kernels -------------------------
__global__ __launch_bounds__(256)
void roundw_kernel(const float* __restrict__ s, f16* __restrict__ oh, int n4)
{
    const int i = blockIdx.x * 256 + threadIdx.x;
    if (i >= n4) return;
    float4 v = ((const float4*)s)[i];
    ((__half2*)oh)[2*i]   = __half2(__float2half_rn(v.x), __float2half_rn(v.y));
    ((__half2*)oh)[2*i+1] = __half2(__float2half_rn(v.z), __float2half_rn(v.w));
}

__global__ __launch_bounds__(256)
void rmsnorm_round(const float* __restrict__ in, const float* __restrict__ w,
                   f16* __restrict__ oh)
{
    const ll base = (ll)blockIdx.x * HID;
    const float4* xin = (const float4*)(in + base);
    float ss = 0.f;
    for (int i = threadIdx.x; i < HID/4; i += 256) {
        float4 v = xin[i];
        ss += v.x*v.x + v.y*v.y + v.z*v.z + v.w*v.w;
    }
    ss = bsum(ss);
    const float r = rsqrtf(ss * (1.f/HID) + RMS_EPS);
    for (int i = threadIdx.x; i < HID/4; i += 256) {
        float4 v = xin[i];
        float4 ww = ((const float4*)w)[i];
        ((__half2*)(oh + base))[2*i]   = __half2(__float2half_rn(v.x*r*ww.x), __float2half_rn(v.y*r*ww.y));
        ((__half2*)(oh + base))[2*i+1] = __half2(__float2half_rn(v.z*r*ww.z), __float2half_rn(v.w*r*ww.w));
    }
}

__global__ __launch_bounds__(256)
void rmsadd_kernel(float* __restrict__ x, const float* __restrict__ w)
{
    const ll base = (ll)blockIdx.x * HID;
    float4* xp = (float4*)(x + base);
    float ss = 0.f;
    for (int i = threadIdx.x; i < HID/4; i += 256) {
        float4 v = xp[i];
        ss += v.x*v.x + v.y*v.y + v.z*v.z + v.w*v.w;
    }
    ss = bsum(ss);
    const float r = rsqrtf(ss * (1.f/HID) + RMS_EPS);
    for (int i = threadIdx.x; i < HID/4; i += 256) {
        float4 v = xp[i];
        float4 ww = ((const float4*)w)[i];
        xp[i] = make_float4(v.x*(1.f+r*ww.x), v.y*(1.f+r*ww.y), v.z*(1.f+r*ww.z), v.w*(1.f+r*ww.w));
    }
}

// in-place RoPE on fp16 [ROWS][HID]; each thread owns pair (j, j+64)
__global__ void rope_inplace(f16* __restrict__ t)
{
    const int idx = blockIdx.x * blockDim.x + threadIdx.x;
    if (idx >= ROWS * NHEAD * 64) return;
    const int j = idx & 63, h = (idx >> 6) & (NHEAD-1), row = idx >> 10;
    const int pos = row & (SEQ - 1);
    const float inv = (float)exp(-(double)(2*j) / (double)HDIM * log(10000.0));
    float s_, c;
    sincosf((float)pos * inv, &s_, &c);
    const ll p0 = (ll)row * HID + h * HDIM + j;
    const float q0 = __half2float(t[p0]), q1 = __half2float(t[p0 + 64]);
    t[p0]      = __float2half_rn(q0*c - q1*s_);
    t[p0+64]   = __float2half_rn(q1*c + q0*s_);
}

// V transpose fp16 -> fp16: v[b*SEQ+s][h*128+d] -> vt[(z*128+d)*SEQ + s]
__global__ void vtrans_kernel(const f16* __restrict__ v, f16* __restrict__ oh)
{
    __shared__ f16 t[32][34];
    const int z = blockIdx.z, b = z >> 4, h = z & 15;
    const int s0 = blockIdx.x * 32, d0 = blockIdx.y * 32;
    const int tx = threadIdx.x, ty = threadIdx.y;
#pragma unroll
    for (int i = 0; i < 4; i++) {
        const int s = s0 + ty + i*8;
        t[ty + i*8][tx] = v[((ll)(b*SEQ + s)) * HID + h*HDIM + d0 + tx];
    }
    __syncthreads();
#pragma unroll
    for (int i = 0; i < 4; i++) {
        const int d = d0 + ty + i*8;
        oh[((ll)z * HDIM + d) * SEQ + s0 + tx] = t[tx][ty + i*8];
    }
}

__device__ __forceinline__ float sigm(float z) { return 1.f / (1.f + expf(-z)); }

// out = sigmoid(t1 + bias) * t2   (t1,t2 fp16)
__global__ void highway_kernel(const f16* __restrict__ t1, const f16* __restrict__ t2,
                               const float* __restrict__ bias, float* __restrict__ out, int n4)
{
    const int i = blockIdx.x * blockDim.x + threadIdx.x;
    if (i >= n4) return;
    __half2 g0 = ((const __half2*)t1)[2*i],   g1 = ((const __half2*)t1)[2*i+1];
    __half2 h0 = ((const __half2*)t2)[2*i],   h1 = ((const __half2*)t2)[2*i+1];
    float4 bv = ((const float4*)bias)[i & (HID/4 - 1)];
    ((float4*)out)[i] = make_float4(
        __half2float(h0.x)*sigm(__half2float(g0.x)+bv.x),
        __half2float(h0.y)*sigm(__half2float(g0.y)+bv.y),
        __half2float(h1.x)*sigm(__half2float(g1.x)+bv.z),
        __half2float(h1.y)*sigm(__half2float(g1.y)+bv.w));
}

// out = xm + mod + sigmoid(t1+bias)*t2   (mod,t1,t2 fp16)
__global__ void combinex_kernel(const float* __restrict__ xm, const f16* __restrict__ mod,
                                const f16* __restrict__ t1, const f16* __restrict__ t2,
                                const float* __restrict__ bias, float* __restrict__ out, int n4)
{
    const int i = blockIdx.x * blockDim.x + threadIdx.x;
    if (i >= n4) return;
    float4 xv = ((const float4*)xm)[i];
    __half2 m0 = ((const __half2*)mod)[2*i], m1 = ((const __half2*)mod)[2*i+1];
    __half2 g0 = ((const __half2*)t1)[2*i],  g1 = ((const __half2*)t1)[2*i+1];
    __half2 h0 = ((const __half2*)t2)[2*i],  h1 = ((const __half2*)t2)[2*i+1];
    float4 bv = ((const float4*)bias)[i & (HID/4 - 1)];
    ((float4*)out)[i] = make_float4(
        xv.x + __half2float(m0.x) + __half2float(h0.x)*sigm(__half2float(g0.x)+bv.x),
        xv.y + __half2float(m0.y) + __half2float(h0.y)*sigm(__half2float(g0.y)+bv.y),
        xv.z + __half2float(m1.x) + __half2float(h1.x)*sigm(__half2float(g1.x)+bv.z),
        xv.w + __half2float(m1.y) + __half2float(h1.y)*sigm(__half2float(g1.y)+bv.w));
}

// oh = silu(g)*u  (g,u fp16 -> fp16)
__global__ void silumul_round(const f16* __restrict__ g, const f16* __restrict__ u,
                              f16* __restrict__ oh, int n4)
{
    const int i = blockIdx.x * blockDim.x + threadIdx.x;
    if (i >= n4) return;
    __half2 g0 = ((const __half2*)g)[2*i], g1 = ((const __half2*)g)[2*i+1];
    __half2 u0 = ((const __half2*)u)[2*i], u1 = ((const __half2*)u)[2*i+1];
    float a = __half2float(g0.x), bq = __half2float(g0.y);
    float c = __half2float(g1.x), d = __half2float(g1.y);
    ((__half2*)oh)[2*i]   = __half2(__float2half_rn(a*sigm(a)*__half2float(u0.x)),
                                    __float2half_rn(bq*sigm(bq)*__half2float(u0.y)));
    ((__half2*)oh)[2*i+1] = __half2(__float2half_rn(c*sigm(c)*__half2float(u1.x)),
                                    __float2half_rn(d*sigm(d)*__half2float(u1.y)));
}

__global__ void add2_kernel(const float* __restrict__ a, const float* __restrict__ b,
                            float* __restrict__ out, int n4)
{
    const int i = blockIdx.x * blockDim.x + threadIdx.x;
    if (i >= n4) return;
    float4 av = ((const float4*)a)[i], bv = ((const float4*)b)[i];
    ((float4*)out)[i] = make_float4(av.x+bv.x, av.y+bv.y, av.z+bv.z, av.w+bv.w);
}

// ------------------------- launch -------------------------
extern "C" void kernel_launch(void* const* d_in, const int* in_sizes, int n_in,
                              void* d_out, int out_size)
{
    const float* x_mod = (const float*)d_in[0];
    const float* x_back= (const float*)d_in[1];
    const float* mask  = (const float*)d_in[2];
    const float* wq = (const float*)d_in[3];
    const float* wk = (const float*)d_in[4];
    const float* wv = (const float*)d_in[5];
    const float* wo = (const float*)d_in[6];
    const float* cross_ln_w = (const float*)d_in[7];
    const float* fb_w = (const float*)d_in[8];
    const float* fb_g = (const float*)d_in[9];
    const float* fb_gb= (const float*)d_in[10];
    const float* dr_w = (const float*)d_in[11];
    const float* dr_g = (const float*)d_in[12];
    const float* dr_gb= (const float*)d_in[13];
    const float* in_ln_w   = (const float*)d_in[14];
    const float* post_ln_w = (const float*)d_in[15];
    const float* w_gate = (const float*)d_in[16];
    const float* w_up   = (const float*)d_in[17];
    const float* w_down = (const float*)d_in[18];

    float* outx = (float*)d_out;
    float* outd = outx + (size_t)ROWS * HID;

    float *mod,*x;
    f16 *wh,*ah,*t1h,*t2h,*modh,*gg16,*uu16;
    cudaGetSymbolAddress((void**)&mod, g_mod);
    cudaGetSymbolAddress((void**)&x, g_x);
    cudaGetSymbolAddress((void**)&wh, g_wh);
    cudaGetSymbolAddress((void**)&ah, g_ah);
    cudaGetSymbolAddress((void**)&t1h, g_t1h);
    cudaGetSymbolAddress((void**)&t2h, g_t2h);
    cudaGetSymbolAddress((void**)&modh, g_modh);
    cudaGetSymbolAddress((void**)&gg16, g_gg16);
    cudaGetSymbolAddress((void**)&uu16, g_uu16);

    cudaFuncSetAttribute(mma_gemm<float>, cudaFuncAttributeMaxDynamicSharedMemorySize, TC_SMEM);
    cudaFuncSetAttribute(mma_gemm<f16>,   cudaFuncAttributeMaxDynamicSharedMemorySize, TC_SMEM);
    cudaFuncSetAttribute(flash_attn,      cudaFuncAttributeMaxDynamicSharedMemorySize, FA_SMEM);

    const int n4h = (int)(RH/4), n4f = (int)(GGN/4), n4w = (int)(H2/4), n4ff = (int)(FF2/4);
    const dim3 B256(256);

    auto gemmF = [&](const f16* pa, const f16* pb, float* c, int M, int N, int K,
                     int lda, int ldb, int ldc) {
        dim3 g(N/128, M/128, 1);
        mma_gemm<float><<<g, 256, TC_SMEM>>>(pa, pb, c, K, lda, ldb, ldc, 1.f, 1, 0,0,0,0,0,0);
    };
    auto gemmH = [&](const f16* pa, const f16* pb, f16* c, int M, int N, int K,
                     int lda, int ldb, int ldc) {
        dim3 g(N/128, M/128, 1);
        mma_gemm<f16><<<g, 256, TC_SMEM>>>(pa, pb, c, K, lda, ldb, ldc, 1.f, 1, 0,0,0,0,0,0);
    };

    // ---- rounds + projections ----
    rmsnorm_round<<<ROWS, B256>>>(x_mod, cross_ln_w, ah+OQN);
    roundw_kernel<<<n4w/256, B256>>>(wq, wh+OWQ, n4w);
    roundw_kernel<<<n4h/256, B256>>>(x_back, ah+OXB, n4h);
    roundw_kernel<<<n4w/256, B256>>>(wk, wh+OWK, n4w);
    roundw_kernel<<<n4w/256, B256>>>(wv, wh+OWV, n4w);
    // q -> ah+OQ (fp16), k -> ah+OK2, v -> ah+OATT (temp; OATT free until flash)
    gemmH(ah+OQN, wh+OWQ, ah+OQ,   ROWS, HID, HID, HID, HID, HID);
    gemmH(ah+OXB, wh+OWK, ah+OK2,  ROWS, HID, HID, HID, HID, HID);
    gemmH(ah+OXB, wh+OWV, ah+OATT, ROWS, HID, HID, HID, HID, HID);

    roundw_kernel<<<n4h/256, B256>>>(x_mod, ah+OXM, n4h);
    roundw_kernel<<<n4w/256, B256>>>(wo,   wh+OWO,  n4w);
    roundw_kernel<<<n4w/256, B256>>>(fb_w, wh+OFBW, n4w);
    roundw_kernel<<<n4w/256, B256>>>(fb_g, wh+OFBG, n4w);
    roundw_kernel<<<n4w/256, B256>>>(dr_w, wh+ODRW, n4w);
    roundw_kernel<<<n4w/256, B256>>>(dr_g, wh+ODRG, n4w);
    roundw_kernel<<<n4ff/256, B256>>>(w_gate, wh+OWG, n4ff);
    roundw_kernel<<<n4ff/256, B256>>>(w_up,   wh+OWU, n4ff);
    roundw_kernel<<<n4ff/256, B256>>>(w_down, wh+OWD, n4ff);

    const int ropeN = ROWS * NHEAD * 64;
    rope_inplace<<<(ropeN+255)/256, B256>>>(ah+OQ);
    rope_inplace<<<(ropeN+255)/256, B256>>>(ah+OK2);
    vtrans_kernel<<<dim3(SEQ/32, HDIM/32, BATCH*NHEAD), dim3(32,8)>>>(ah+OATT, ah+OVT);

    // ---- fused flash attention -> att fp16 (OATT, overwrites v temp) ----
    flash_attn<<<dim3(SEQ/128, BATCH*NHEAD), B256, FA_SMEM>>>(
        ah+OQ, ah+OK2, ah+OVT, mask, ah+OATT);
    gemmH(ah+OATT, wh+OWO, modh, ROWS, HID, HID, HID, HID, HID);

    // ---- feedback highway -> delta ----
    gemmH(ah+OXM, wh+OFBG, t1h, ROWS, HID, HID, HID, HID, HID);
    gemmH(ah+OXM, wh+OFBW, t2h, ROWS, HID, HID, HID, HID, HID);
    highway_kernel<<<n4h/256, B256>>>(t1h, t2h, fb_gb, outd, n4h);

    // ---- driver highway + combine ----
    gemmH(ah+OXB, wh+ODRG, t1h, ROWS, HID, HID, HID, HID, HID);
    gemmH(ah+OXB, wh+ODRW, t2h, ROWS, HID, HID, HID, HID, HID);
    combinex_kernel<<<n4h/256, B256>>>(x_mod, modh, t1h, t2h, dr_gb, x, n4h);

    // ---- decoder ----
    rmsadd_kernel<<<ROWS, B256>>>(x, in_ln_w);
    rmsnorm_round<<<ROWS, B256>>>(x, post_ln_w, ah+OHB);
    gemmH(ah+OHB, wh+OWG, gg16, ROWS, FFD, HID, HID, HID, FFD);
    gemmH(ah+OHB, wh+OWU, uu16, ROWS, FFD, HID, HID, HID, FFD);
    silumul_round<<<n4f/256, B256>>>(gg16, uu16, ah+OGG, n4f);
    gemmF(ah+OGG, wh+OWD, mod, ROWS, HID, FFD, FFD, FFD, HID);
    add2_kernel<<<n4h/256, B256>>>(x, mod, outx, n4h);
}

// round 13
// speedup vs baseline: 2.3457x; 1.0749x over previous
#include <cuda_runtime.h>
#include <cuda_fp16.h>
#include <cstdint>
#include <math.h>
using f16 = __half;
typedef long long ll;

#define BATCH 2
#define SEQ 2048
#define HID 2048
#define NHEAD 16
#define HDIM 128
#define FFD 8192
#define ROWS 4096
#define RMS_EPS 1e-5f
#define RH 8388608LL
#define H2 4194304LL
#define FF2 16777216LL
#define GGN 33554432LL

// ------------------------- scratch -------------------------
__device__ float g_mod[RH], g_x[RH];
__device__ f16 g_wh[8*H2+3*FF2];     // weights fp16 (adjacent pairs for z-merged GEMMs)
__device__ f16 g_ah[8*RH+GGN];       // activations fp16
__device__ f16 g_modh[RH];
__device__ f16 g_t12[2*RH];          // merged highway outputs: [0]=w-path, [RH]=g-path
__device__ f16 g_gu[2*GGN];          // merged gate/up: [0]=gate, [GGN]=up

// weight arena offsets (OWK/OWV, OFBW/OFBG, ODRW/ODRG, OWG/OWU adjacent)
#define OWQ  (0*H2)
#define OWK  (1*H2)
#define OWV  (2*H2)
#define OWO  (3*H2)
#define OFBW (4*H2)
#define OFBG (5*H2)
#define ODRW (6*H2)
#define ODRG (7*H2)
#define OWG  (8*H2)
#define OWU  (8*H2+FF2)
#define OWD  (8*H2+2*FF2)
// activation arena offsets
#define OQN  (0*RH)
#define OXB  (1*RH)
#define OXM  (2*RH)
#define OQ   (3*RH)
#define OK2  (4*RH)   // k ; merged kv GEMM writes z=1 at OK2+2RH = OATT (v temp)
#define OVT  (5*RH)
#define OATT (6*RH)
#define OHB  (7*RH)
#define OGG  (8*RH)

// ------------------------- PTX helpers -------------------------
__device__ __forceinline__ uint32_t smem_u32(const void* p) {
    uint32_t a;
    asm("{ .reg .u64 t; cvta.to.shared.u64 t, %1; cvt.u32.u64 %0, t; }" : "=r"(a) : "l"(p));
    return a;
}
__device__ __forceinline__ void cp16(uint32_t s, const void* g) {
    asm volatile("cp.async.cg.shared.global [%0], [%1], 16;" :: "r"(s), "l"(g));
}
__device__ __forceinline__ void cpcommit() { asm volatile("cp.async.commit_group;" ::: "memory"); }
__device__ __forceinline__ void cpwait0()  { asm volatile("cp.async.wait_group 0;" ::: "memory"); }
__device__ __forceinline__ void cpwait1()  { asm volatile("cp.async.wait_group 1;" ::: "memory"); }

__device__ __forceinline__ void ldsm4(uint32_t* r, uint32_t addr) {
    asm volatile("ldmatrix.sync.aligned.m8n8.x4.shared.b16 {%0,%1,%2,%3}, [%4];"
        : "=r"(r[0]), "=r"(r[1]), "=r"(r[2]), "=r"(r[3]) : "r"(addr));
}
__device__ __forceinline__ void mma16816(float* c, const uint32_t* a, uint32_t b0, uint32_t b1) {
    asm volatile("mma.sync.aligned.m16n8k16.row.col.f32.f16.f16.f32 "
        "{%0,%1,%2,%3}, {%4,%5,%6,%7}, {%8,%9}, {%0,%1,%2,%3};"
        : "+f"(c[0]), "+f"(c[1]), "+f"(c[2]), "+f"(c[3])
        : "r"(a[0]), "r"(a[1]), "r"(a[2]), "r"(a[3]), "r"(b0), "r"(b1));
}

// ---------------------------------------------------------------------------
// fp16 HMMA GEMM (templated output). C = A @ B^T.
// 128x128 CTA tile, KTILE=32, 3-stage cp.async, 8 warps (32x64 warp tile).
// per-z offsets: A += z*sA, B += z*sB, C += z*sC.
// ---------------------------------------------------------------------------
#define STG 16384
#define TC_SMEM (3*STG)

template<typename OT>
__global__ __launch_bounds__(256, 2)
void mma_gemm(const f16* __restrict__ Ahg, const f16* __restrict__ Bhg,
              OT* __restrict__ Cg,
              int K, int lda, int ldb, int ldc,
              ll sA, ll sB, ll sC)
{
    extern __shared__ char smem_raw[];
    const uint32_t tiles = smem_u32(smem_raw);
    const int tid = threadIdx.x, wid = tid >> 5, lane = tid & 31;
    const int wm = wid & 3, wn = wid >> 2;

    const int z = blockIdx.z;
    const f16* Ah = Ahg + (ll)z * sA;
    const f16* Bh = Bhg + (ll)z * sB;
    OT* C = Cg + (ll)z * sC;

    const int bm = blockIdx.y << 7, bn = blockIdx.x << 7;
    const int nk = K >> 5;

    auto load_stage = [&](int kt) {
        const uint32_t st = tiles + (uint32_t)(kt % 3) * STG;
        const ll kb = (ll)kt * 32;
#pragma unroll
        for (int i = tid; i < 512; i += 256) {
            const int r = i >> 2, c = i & 3;
            const uint32_t sw = (uint32_t)r * 64u + (uint32_t)((c ^ ((r >> 1) & 3)) << 4);
            cp16(st        + sw, Ah + (ll)(bm + r) * lda + kb + c * 8);
            cp16(st + 8192 + sw, Bh + (ll)(bn + r) * ldb + kb + c * 8);
        }
        cpcommit();
    };

    float acc[2][8][4];
#pragma unroll
    for (int i = 0; i < 2; i++)
#pragma unroll
        for (int j = 0; j < 8; j++)
#pragma unroll
            for (int t = 0; t < 4; t++) acc[i][j][t] = 0.f;

    const int aRow  = wm * 32 + (lane & 15);
    const int aCpar = lane >> 4;
    const int bNadd = ((lane >> 4) << 3) + (lane & 7);
    const int bCpar = (lane >> 3) & 1;

    load_stage(0);
    if (nk > 1) load_stage(1); else cpcommit();

    for (int kt = 0; kt < nk; kt++) {
        if (kt >= nk - 2) cpwait0(); else cpwait1();
        __syncthreads();
        if (kt + 2 < nk) load_stage(kt + 2); else cpcommit();

        const uint32_t st = tiles + (uint32_t)(kt % 3) * STG;
#pragma unroll
        for (int ks = 0; ks < 2; ks++) {
            uint32_t ahf[2][4];
#pragma unroll
            for (int mt = 0; mt < 2; mt++) {
                const int row = aRow + mt * 16;
                const int ch = ks * 2 + aCpar;
                const uint32_t ad = st + (uint32_t)row * 64u + (uint32_t)((ch ^ ((row >> 1) & 3)) << 4);
                ldsm4(ahf[mt], ad);
            }
#pragma unroll
            for (int np = 0; np < 2; np++) {
                uint32_t bh[2][4];
#pragma unroll
                for (int t = 0; t < 2; t++) {
                    const int nt = np * 2 + t;
                    const int row = wn * 64 + nt * 16 + bNadd;
                    const int ch = ks * 2 + bCpar;
                    const uint32_t bd = st + 8192u + (uint32_t)row * 64u + (uint32_t)((ch ^ ((row >> 1) & 3)) << 4);
                    ldsm4(bh[t], bd);
                }
#pragma unroll
                for (int t = 0; t < 2; t++) {
                    const int nb = (np * 2 + t) * 2;
                    mma16816(acc[0][nb],   ahf[0], bh[t][0], bh[t][1]);
                    mma16816(acc[0][nb+1], ahf[0], bh[t][2], bh[t][3]);
                    mma16816(acc[1][nb],   ahf[1], bh[t][0], bh[t][1]);
                    mma16816(acc[1][nb+1], ahf[1], bh[t][2], bh[t][3]);
                }
            }
        }
    }

    const int erow = bm + wm * 32 + (lane >> 2);
    const int ecol = bn + wn * 64 + (lane & 3) * 2;
#pragma unroll
    for (int mt = 0; mt < 2; mt++) {
#pragma unroll
        for (int j = 0; j < 8; j++) {
            OT* p0 = C + (ll)(erow + mt*16)     * ldc + ecol + j*8;
            OT* p1 = C + (ll)(erow + mt*16 + 8) * ldc + ecol + j*8;
            if constexpr (sizeof(OT) == 4) {
                *(float2*)p0 = make_float2(acc[mt][j][0], acc[mt][j][1]);
                *(float2*)p1 = make_float2(acc[mt][j][2], acc[mt][j][3]);
            } else {
                __half2 h0(__float2half_rn(acc[mt][j][0]), __float2half_rn(acc[mt][j][1]));
                __half2 h1(__float2half_rn(acc[mt][j][2]), __float2half_rn(acc[mt][j][3]));
                *(__half2*)p0 = h0;
                *(__half2*)p1 = h1;
            }
        }
    }
}

// ---------------------------------------------------------------------------
// Flash attention (fp16): CTA = 128 q-rows x 1 head. smem 96KB.
// ---------------------------------------------------------------------------
#define FA_SMEM 98304
#define FA_SCALE 0.08838834764831845f

__global__ __launch_bounds__(256, 1)
void flash_attn(const f16* __restrict__ qh, const f16* __restrict__ kh,
                const f16* __restrict__ vth, const float* __restrict__ mask,
                f16* __restrict__ oh)
{
    extern __shared__ char smem_raw[];
    const uint32_t sQ = smem_u32(smem_raw);
    const uint32_t sKV = sQ + 32768;
    const int tid = threadIdx.x, w = tid >> 5, lane = tid & 31;

    const int qt = blockIdx.x;
    const int z  = blockIdx.y;
    const int b  = z >> 4, h = z & 15;
    const int bS = b * SEQ;

    {
        const ll base = (ll)(bS + qt*128) * HID + h*128;
#pragma unroll
        for (int i = tid; i < 2048; i += 256) {
            const int r = i >> 4, c = i & 15;
            const uint32_t sw = (uint32_t)r*256u + (uint32_t)((c ^ (r & 15)) << 4);
            cp16(sQ + sw, qh + base + (ll)r * HID + c * 8);
        }
    }
    auto load_kv = [&](int kt) {
        const uint32_t st = sKV + (uint32_t)(kt & 1) * 32768;
        const ll kbase = (ll)(bS + kt*64) * HID + h*128;
#pragma unroll
        for (int i = tid; i < 1024; i += 256) {
            const int r = i >> 4, c = i & 15;
            const uint32_t sw = (uint32_t)r*256u + (uint32_t)((c ^ (r & 15)) << 4);
            cp16(st + sw, kh + kbase + (ll)r * HID + c * 8);
        }
        const ll vbase = (ll)z * 128 * SEQ + kt*64;
#pragma unroll
        for (int i = tid; i < 1024; i += 256) {
            const int r = i >> 3, c = i & 7;
            const uint32_t sw = (uint32_t)r*128u + (uint32_t)((c ^ (r & 7)) << 4);
            cp16(st + 16384 + sw, vth + vbase + (ll)r * SEQ + c * 8);
        }
        cpcommit();
    };

    float oacc[16][4];
#pragma unroll
    for (int i = 0; i < 16; i++)
#pragma unroll
        for (int t = 0; t < 4; t++) oacc[i][t] = 0.f;
    float m1 = -1e30f, m2 = -1e30f, l1 = 0.f, l2 = 0.f;

    const int aCpar = lane >> 4;
    const int bNadd = ((lane >> 4) << 3) + (lane & 7);
    const int bCpar = (lane >> 3) & 1;
    const int qRow  = w * 16 + (lane & 15);
    const int qpos1 = qt*128 + w*16 + (lane >> 2);
    const int colq  = (lane & 3) * 2;

    load_kv(0);
    const int NKT = SEQ / 64;

    for (int kt = 0; kt < NKT; kt++) {
        if (kt + 1 < NKT) { load_kv(kt + 1); cpwait1(); } else { cpwait0(); }
        __syncthreads();
        const uint32_t st = sKV + (uint32_t)(kt & 1) * 32768;

        float sacc[8][4];
#pragma unroll
        for (int j = 0; j < 8; j++)
#pragma unroll
            for (int t = 0; t < 4; t++) sacc[j][t] = 0.f;

#pragma unroll
        for (int ks = 0; ks < 8; ks++) {
            uint32_t ahf[4];
            {
                const int ch = ks*2 + aCpar;
                const uint32_t ad = sQ + (uint32_t)qRow*256u + (uint32_t)((ch ^ (qRow & 15)) << 4);
                ldsm4(ahf, ad);
            }
#pragma unroll
            for (int nt = 0; nt < 4; nt++) {
                const int row = nt*16 + bNadd;
                const int ch = ks*2 + bCpar;
                const uint32_t bd = st + (uint32_t)row*256u + (uint32_t)((ch ^ (row & 15)) << 4);
                uint32_t bh[4];
                ldsm4(bh, bd);
                mma16816(sacc[nt*2],   ahf, bh[0], bh[1]);
                mma16816(sacc[nt*2+1], ahf, bh[2], bh[3]);
            }
        }

        const int kbase = kt*64;
#pragma unroll
        for (int j = 0; j < 8; j++) {
            const int kposg = kbase + j*8 + colq;
            float2 mA = *(const float2*)(mask + (ll)qpos1 * SEQ + kposg);
            float2 mB = *(const float2*)(mask + (ll)(qpos1 + 8) * SEQ + kposg);
            sacc[j][0] = sacc[j][0]*FA_SCALE + mA.x;
            sacc[j][1] = sacc[j][1]*FA_SCALE + mA.y;
            sacc[j][2] = sacc[j][2]*FA_SCALE + mB.x;
            sacc[j][3] = sacc[j][3]*FA_SCALE + mB.y;
        }
        float mx1 = -1e30f, mx2 = -1e30f;
#pragma unroll
        for (int j = 0; j < 8; j++) {
            mx1 = fmaxf(mx1, fmaxf(sacc[j][0], sacc[j][1]));
            mx2 = fmaxf(mx2, fmaxf(sacc[j][2], sacc[j][3]));
        }
        mx1 = fmaxf(mx1, __shfl_xor_sync(0xffffffffu, mx1, 1));
        mx1 = fmaxf(mx1, __shfl_xor_sync(0xffffffffu, mx1, 2));
        mx2 = fmaxf(mx2, __shfl_xor_sync(0xffffffffu, mx2, 1));
        mx2 = fmaxf(mx2, __shfl_xor_sync(0xffffffffu, mx2, 2));
        const float nm1 = fmaxf(m1, mx1), nm2 = fmaxf(m2, mx2);
        const float al1 = __expf(m1 - nm1), al2 = __expf(m2 - nm2);
        m1 = nm1; m2 = nm2;
        float s1 = 0.f, s2 = 0.f;
#pragma unroll
        for (int j = 0; j < 8; j++) {
            sacc[j][0] = __expf(sacc[j][0] - nm1);
            sacc[j][1] = __expf(sacc[j][1] - nm1);
            sacc[j][2] = __expf(sacc[j][2] - nm2);
            sacc[j][3] = __expf(sacc[j][3] - nm2);
            s1 += sacc[j][0] + sacc[j][1];
            s2 += sacc[j][2] + sacc[j][3];
        }
        s1 += __shfl_xor_sync(0xffffffffu, s1, 1);
        s1 += __shfl_xor_sync(0xffffffffu, s1, 2);
        s2 += __shfl_xor_sync(0xffffffffu, s2, 1);
        s2 += __shfl_xor_sync(0xffffffffu, s2, 2);
        l1 = l1*al1 + s1;
        l2 = l2*al2 + s2;
#pragma unroll
        for (int i = 0; i < 16; i++) {
            oacc[i][0] *= al1; oacc[i][1] *= al1;
            oacc[i][2] *= al2; oacc[i][3] *= al2;
        }

#pragma unroll
        for (int kk = 0; kk < 4; kk++) {
            uint32_t pah[4];
            {
                __half2 t0(__float2half_rn(sacc[2*kk][0]),   __float2half_rn(sacc[2*kk][1]));
                __half2 t1(__float2half_rn(sacc[2*kk][2]),   __float2half_rn(sacc[2*kk][3]));
                __half2 t2(__float2half_rn(sacc[2*kk+1][0]), __float2half_rn(sacc[2*kk+1][1]));
                __half2 t3(__float2half_rn(sacc[2*kk+1][2]), __float2half_rn(sacc[2*kk+1][3]));
                pah[0] = *(uint32_t*)&t0; pah[1] = *(uint32_t*)&t1;
                pah[2] = *(uint32_t*)&t2; pah[3] = *(uint32_t*)&t3;
            }
#pragma unroll
            for (int nt = 0; nt < 8; nt++) {
                const int row = nt*16 + bNadd;
                const int ch = kk*2 + bCpar;
                const uint32_t bd = st + 16384u + (uint32_t)row*128u + (uint32_t)((ch ^ (row & 7)) << 4);
                uint32_t bh[4];
                ldsm4(bh, bd);
                mma16816(oacc[nt*2],   pah, bh[0], bh[1]);
                mma16816(oacc[nt*2+1], pah, bh[2], bh[3]);
            }
        }
        __syncthreads();
    }

    const float inv1 = 1.f / l1, inv2 = 1.f / l2;
    const ll row1 = (ll)(bS + qpos1);
#pragma unroll
    for (int nt = 0; nt < 16; nt++) {
        const int col = h*128 + nt*8 + colq;
        __half2 th(__float2half_rn(oacc[nt][0]*inv1), __float2half_rn(oacc[nt][1]*inv1));
        __half2 uh(__float2half_rn(oacc[nt][2]*inv2), __float2half_rn(oacc[nt][3]*inv2));
        *(__half2*)(oh + row1*HID + col)     = th;
        *(__half2*)(oh + (row1+8)*HID + col) = uh;
    }
}

// ------------------------- reductions -------------------------
__device__ __forceinline__ float wsum(float v) {
#pragma unroll
    for (int o = 16; o; o >>= 1) v += __shfl_xor_sync(0xffffffffu, v, o);
    return v;
}
__device__ __forceinline__ float bsum(float v) {
    __shared__ float sh[8];
    v = wsum(v); __syncthreads();
    if ((threadIdx.x & 31) == 0) sh[threadIdx.x >> 5] = v;
    __syncthreads();
    float r = 0.f;
#pragma unroll
    for (int i = 0; i < 8; i++) r += sh[i];
    return r;
}

// ------------------------- elementwise kernels -------------------------
__global__ __launch_bounds__(256)
void roundw_kernel(const float* __restrict__ s, f16* __restrict__ oh, int n4)
{
    const int i = blockIdx.x * 256 + threadIdx.x;
    if (i >= n4) return;
    float4 v = ((const float4*)s)[i];
    ((__half2*)oh)[2*i]   = __half2(__float2half_rn(v.x), __float2half_rn(v.y));
    ((__half2*)oh)[2*i+1] = __half2(__float2half_rn(v.z), __float2half_rn(v.w));
}

__global__ __launch_bounds__(256)
void rmsnorm_round(const float* __restrict__ in, const float* __restrict__ w,
                   f16* __restrict__ oh)
{
    const ll base = (ll)blockIdx.x * HID;
    const float4* xin = (const float4*)(in + base);
    float ss = 0.f;
    for (int i = threadIdx.x; i < HID/4; i += 256) {
        float4 v = xin[i];
        ss += v.x*v.x + v.y*v.y + v.z*v.z + v.w*v.w;
    }
    ss = bsum(ss);
    const float r = rsqrtf(ss * (1.f/HID) + RMS_EPS);
    for (int i = threadIdx.x; i < HID/4; i += 256) {
        float4 v = xin[i];
        float4 ww = ((const float4*)w)[i];
        ((__half2*)(oh + base))[2*i]   = __half2(__float2half_rn(v.x*r*ww.x), __float2half_rn(v.y*r*ww.y));
        ((__half2*)(oh + base))[2*i+1] = __half2(__float2half_rn(v.z*r*ww.z), __float2half_rn(v.w*r*ww.w));
    }
}

__global__ __launch_bounds__(256)
void rmsadd_kernel(float* __restrict__ x, const float* __restrict__ w)
{
    const ll base = (ll)blockIdx.x * HID;
    float4* xp = (float4*)(x + base);
    float ss = 0.f;
    for (int i = threadIdx.x; i < HID/4; i += 256) {
        float4 v = xp[i];
        ss += v.x*v.x + v.y*v.y + v.z*v.z + v.w*v.w;
    }
    ss = bsum(ss);
    const float r = rsqrtf(ss * (1.f/HID) + RMS_EPS);
    for (int i = threadIdx.x; i < HID/4; i += 256) {
        float4 v = xp[i];
        float4 ww = ((const float4*)w)[i];
        xp[i] = make_float4(v.x*(1.f+r*ww.x), v.y*(1.f+r*ww.y), v.z*(1.f+r*ww.z), v.w*(1.f+r*ww.w));
    }
}

__global__ void rope_inplace(f16* __restrict__ t)
{
    const int idx = blockIdx.x * blockDim.x + threadIdx.x;
    if (idx >= ROWS * NHEAD * 64) return;
    const int j = idx & 63, h = (idx >> 6) & (NHEAD-1), row = idx >> 10;
    const int pos = row & (SEQ - 1);
    const float inv = (float)exp(-(double)(2*j) / (double)HDIM * log(10000.0));
    float s_, c;
    sincosf((float)pos * inv, &s_, &c);
    const ll p0 = (ll)row * HID + h * HDIM + j;
    const float q0 = __half2float(t[p0]), q1 = __half2float(t[p0 + 64]);
    t[p0]      = __float2half_rn(q0*c - q1*s_);
    t[p0+64]   = __float2half_rn(q1*c + q0*s_);
}

__global__ void vtrans_kernel(const f16* __restrict__ v, f16* __restrict__ oh)
{
    __shared__ f16 t[32][34];
    const int z = blockIdx.z, b = z >> 4, h = z & 15;
    const int s0 = blockIdx.x * 32, d0 = blockIdx.y * 32;
    const int tx = threadIdx.x, ty = threadIdx.y;
#pragma unroll
    for (int i = 0; i < 4; i++) {
        const int s = s0 + ty + i*8;
        t[ty + i*8][tx] = v[((ll)(b*SEQ + s)) * HID + h*HDIM + d0 + tx];
    }
    __syncthreads();
#pragma unroll
    for (int i = 0; i < 4; i++) {
        const int d = d0 + ty + i*8;
        oh[((ll)z * HDIM + d) * SEQ + s0 + tx] = t[tx][ty + i*8];
    }
}

__device__ __forceinline__ float sigm(float z) { return 1.f / (1.f + expf(-z)); }

// out = sigmoid(t1 + bias) * t2
__global__ void highway_kernel(const f16* __restrict__ t1, const f16* __restrict__ t2,
                               const float* __restrict__ bias, float* __restrict__ out, int n4)
{
    const int i = blockIdx.x * blockDim.x + threadIdx.x;
    if (i >= n4) return;
    __half2 g0 = ((const __half2*)t1)[2*i],   g1 = ((const __half2*)t1)[2*i+1];
    __half2 h0 = ((const __half2*)t2)[2*i],   h1 = ((const __half2*)t2)[2*i+1];
    float4 bv = ((const float4*)bias)[i & (HID/4 - 1)];
    ((float4*)out)[i] = make_float4(
        __half2float(h0.x)*sigm(__half2float(g0.x)+bv.x),
        __half2float(h0.y)*sigm(__half2float(g0.y)+bv.y),
        __half2float(h1.x)*sigm(__half2float(g1.x)+bv.z),
        __half2float(h1.y)*sigm(__half2float(g1.y)+bv.w));
}

__global__ void combinex_kernel(const float* __restrict__ xm, const f16* __restrict__ mod,
                                const f16* __restrict__ t1, const f16* __restrict__ t2,
                                const float* __restrict__ bias, float* __restrict__ out, int n4)
{
    const int i = blockIdx.x * blockDim.x + threadIdx.x;
    if (i >= n4) return;
    float4 xv = ((const float4*)xm)[i];
    __half2 m0 = ((const __half2*)mod)[2*i], m1 = ((const __half2*)mod)[2*i+1];
    __half2 g0 = ((const __half2*)t1)[2*i],  g1 = ((const __half2*)t1)[2*i+1];
    __half2 h0 = ((const __half2*)t2)[2*i],  h1 = ((const __half2*)t2)[2*i+1];
    float4 bv = ((const float4*)bias)[i & (HID/4 - 1)];
    ((float4*)out)[i] = make_float4(
        xv.x + __half2float(m0.x) + __half2float(h0.x)*sigm(__half2float(g0.x)+bv.x),
        xv.y + __half2float(m0.y) + __half2float(h0.y)*sigm(__half2float(g0.y)+bv.y),
        xv.z + __half2float(m1.x) + __half2float(h1.x)*sigm(__half2float(g1.x)+bv.z),
        xv.w + __half2float(m1.y) + __half2float(h1.y)*sigm(__half2float(g1.y)+bv.w));
}

__global__ void silumul_round(const f16* __restrict__ g, const f16* __restrict__ u,
                              f16* __restrict__ oh, int n4)
{
    const int i = blockIdx.x * blockDim.x + threadIdx.x;
    if (i >= n4) return;
    __half2 g0 = ((const __half2*)g)[2*i], g1 = ((const __half2*)g)[2*i+1];
    __half2 u0 = ((const __half2*)u)[2*i], u1 = ((const __half2*)u)[2*i+1];
    float a = __half2float(g0.x), bq = __half2float(g0.y);
    float c = __half2float(g1.x), d = __half2float(g1.y);
    ((__half2*)oh)[2*i]   = __half2(__float2half_rn(a*sigm(a)*__half2float(u0.x)),
                                    __float2half_rn(bq*sigm(bq)*__half2float(u0.y)));
    ((__half2*)oh)[2*i+1] = __half2(__float2half_rn(c*sigm(c)*__half2float(u1.x)),
                                    __float2half_rn(d*sigm(d)*__half2float(u1.y)));
}

__global__ void add2_kernel(const float* __restrict__ a, const float* __restrict__ b,
                            float* __restrict__ out, int n4)
{
    const int i = blockIdx.x * blockDim.x + threadIdx.x;
    if (i >= n4) return;
    float4 av = ((const float4*)a)[i], bv = ((const float4*)b)[i];
    ((float4*)out)[i] = make_float4(av.x+bv.x, av.y+bv.y, av.z+bv.z, av.w+bv.w);
}

// ------------------------- launch (single stream, z-merged GEMMs) ---------
extern "C" void kernel_launch(void* const* d_in, const int* in_sizes, int n_in,
                              void* d_out, int out_size)
{
    const float* x_mod = (const float*)d_in[0];
    const float* x_back= (const float*)d_in[1];
    const float* mask  = (const float*)d_in[2];
    const float* wq = (const float*)d_in[3];
    const float* wk = (const float*)d_in[4];
    const float* wv = (const float*)d_in[5];
    const float* wo = (const float*)d_in[6];
    const float* cross_ln_w = (const float*)d_in[7];
    const float* fb_w = (const float*)d_in[8];
    const float* fb_g = (const float*)d_in[9];
    const float* fb_gb= (const float*)d_in[10];
    const float* dr_w = (const float*)d_in[11];
    const float* dr_g = (const float*)d_in[12];
    const float* dr_gb= (const float*)d_in[13];
    const float* in_ln_w   = (const float*)d_in[14];
    const float* post_ln_w = (const float*)d_in[15];
    const float* w_gate = (const float*)d_in[16];
    const float* w_up   = (const float*)d_in[17];
    const float* w_down = (const float*)d_in[18];

    float* outx = (float*)d_out;
    float* outd = outx + (size_t)ROWS * HID;

    float *mod,*x;
    f16 *wh,*ah,*modh,*t12,*gu;
    cudaGetSymbolAddress((void**)&mod, g_mod);
    cudaGetSymbolAddress((void**)&x, g_x);
    cudaGetSymbolAddress((void**)&wh, g_wh);
    cudaGetSymbolAddress((void**)&ah, g_ah);
    cudaGetSymbolAddress((void**)&modh, g_modh);
    cudaGetSymbolAddress((void**)&t12, g_t12);
    cudaGetSymbolAddress((void**)&gu, g_gu);

    cudaFuncSetAttribute(mma_gemm<float>, cudaFuncAttributeMaxDynamicSharedMemorySize, TC_SMEM);
    cudaFuncSetAttribute(mma_gemm<f16>,   cudaFuncAttributeMaxDynamicSharedMemorySize, TC_SMEM);
    cudaFuncSetAttribute(flash_attn,      cudaFuncAttributeMaxDynamicSharedMemorySize, FA_SMEM);

    const int n4h = (int)(RH/4), n4f = (int)(GGN/4), n4w = (int)(H2/4), n4ff = (int)(FF2/4);
    const dim3 B256(256);

    auto gemmH = [&](const f16* pa, const f16* pb, f16* c,
                     int M, int N, int K, int lda, int ldb, int ldc,
                     int gz, ll sa, ll sb, ll sc) {
        dim3 g(N/128, M/128, gz);
        mma_gemm<f16><<<g, 256, TC_SMEM>>>(pa, pb, c, K, lda, ldb, ldc, sa, sb, sc);
    };
    auto gemmF = [&](const f16* pa, const f16* pb, float* c,
                     int M, int N, int K, int lda, int ldb, int ldc) {
        dim3 g(N/128, M/128, 1);
        mma_gemm<float><<<g, 256, TC_SMEM>>>(pa, pb, c, K, lda, ldb, ldc, 0, 0, 0);
    };

    // ---- rounds ----
    roundw_kernel<<<n4h/256, B256>>>(x_back, ah+OXB, n4h);
    roundw_kernel<<<n4h/256, B256>>>(x_mod,  ah+OXM, n4h);
    rmsnorm_round<<<ROWS, B256>>>(x_mod, cross_ln_w, ah+OQN);
    roundw_kernel<<<n4w/256, B256>>>(wq, wh+OWQ, n4w);
    roundw_kernel<<<n4w/256, B256>>>(wk, wh+OWK, n4w);
    roundw_kernel<<<n4w/256, B256>>>(wv, wh+OWV, n4w);
    roundw_kernel<<<n4w/256, B256>>>(wo, wh+OWO, n4w);
    roundw_kernel<<<n4w/256, B256>>>(fb_w, wh+OFBW, n4w);
    roundw_kernel<<<n4w/256, B256>>>(fb_g, wh+OFBG, n4w);
    roundw_kernel<<<n4w/256, B256>>>(dr_w, wh+ODRW, n4w);
    roundw_kernel<<<n4w/256, B256>>>(dr_g, wh+ODRG, n4w);
    roundw_kernel<<<n4ff/256, B256>>>(w_gate, wh+OWG, n4ff);
    roundw_kernel<<<n4ff/256, B256>>>(w_up,   wh+OWU, n4ff);
    roundw_kernel<<<n4ff/256, B256>>>(w_down, wh+OWD, n4ff);

    // ---- projections: q single, k+v merged (z=1 -> OK2+2RH = OATT v-temp) ----
    gemmH(ah+OQN, wh+OWQ, ah+OQ,  ROWS, HID, HID, HID, HID, HID, 1, 0, 0, 0);
    gemmH(ah+OXB, wh+OWK, ah+OK2, ROWS, HID, HID, HID, HID, HID, 2, 0, H2, 2*RH);

    const int ropeN = ROWS * NHEAD * 64;
    rope_inplace<<<(ropeN+255)/256, B256>>>(ah+OQ);
    rope_inplace<<<(ropeN+255)/256, B256>>>(ah+OK2);
    vtrans_kernel<<<dim3(SEQ/32, HDIM/32, BATCH*NHEAD), dim3(32,8)>>>(ah+OATT, ah+OVT);

    // ---- flash attention -> OATT (overwrites v-temp), then WO ----
    flash_attn<<<dim3(SEQ/128, BATCH*NHEAD), B256, FA_SMEM>>>(
        ah+OQ, ah+OK2, ah+OVT, mask, ah+OATT);
    gemmH(ah+OATT, wh+OWO, modh, ROWS, HID, HID, HID, HID, HID, 1, 0, 0, 0);

    // ---- feedback highway (merged pair) -> delta ----
    gemmH(ah+OXM, wh+OFBW, t12, ROWS, HID, HID, HID, HID, HID, 2, 0, H2, RH);
    highway_kernel<<<n4h/256, B256>>>(t12+RH, t12, fb_gb, outd, n4h);

    // ---- driver highway (merged pair) + combine ----
    gemmH(ah+OXB, wh+ODRW, t12, ROWS, HID, HID, HID, HID, HID, 2, 0, H2, RH);
    combinex_kernel<<<n4h/256, B256>>>(x_mod, modh, t12+RH, t12, dr_gb, x, n4h);

    // ---- decoder ----
    rmsadd_kernel<<<ROWS, B256>>>(x, in_ln_w);
    rmsnorm_round<<<ROWS, B256>>>(x, post_ln_w, ah+OHB);
    gemmH(ah+OHB, wh+OWG, gu, ROWS, FFD, HID, HID, HID, FFD, 2, 0, FF2, GGN);
    silumul_round<<<n4f/256, B256>>>(gu, gu+GGN, ah+OGG, n4f);
    gemmF(ah+OGG, wh+OWD, mod, ROWS, HID, FFD, FFD, FFD, HID);
    add2_kernel<<<n4h/256, B256>>>(x, mod, outx, n4h);
}

// round 15
// speedup vs baseline: 2.3727x; 1.0115x over previous
#include <cuda_runtime.h>
#include <cuda_fp16.h>
#include <cstdint>
#include <math.h>
using f16 = __half;
typedef long long ll;

#define BATCH 2
#define SEQ 2048
#define HID 2048
#define NHEAD 16
#define HDIM 128
#define FFD 8192
#define ROWS 4096
#define RMS_EPS 1e-5f
#define RH 8388608LL
#define H2 4194304LL
#define FF2 16777216LL
#define GGN 33554432LL

// ------------------------- scratch -------------------------
__device__ float g_mod[RH], g_x[RH];
__device__ f16 g_wh[8*H2+3*FF2];     // weights fp16 (contiguous for merged rounds / z-GEMMs)
__device__ f16 g_ah[8*RH+GGN];       // activations fp16
__device__ f16 g_modh[RH];
__device__ f16 g_t12[4*RH];          // z=4 highway outputs: fb_w, fb_g, dr_w, dr_g
__device__ f16 g_gu[2*GGN];          // merged gate/up

// weight arena offsets (fb_w..dr_g contiguous; gate/up adjacent)
#define OWQ  (0*H2)
#define OWK  (1*H2)
#define OWV  (2*H2)
#define OWO  (3*H2)
#define OFBW (4*H2)
#define OFBG (5*H2)
#define ODRW (6*H2)
#define ODRG (7*H2)
#define OWG  (8*H2)
#define OWU  (8*H2+FF2)
#define OWD  (8*H2+2*FF2)
// activation arena offsets
#define OQN  (0*RH)
#define OXB  (1*RH)
#define OXM  (2*RH)   // OXM - RH = OXB (used by z=4 highway A stride)
#define OQ   (3*RH)
#define OK2  (4*RH)   // merged kv GEMM writes z=1 at OK2+2RH = OATT (v temp)
#define OVT  (5*RH)
#define OATT (6*RH)
#define OHB  (7*RH)
#define OGG  (8*RH)

// ------------------------- PTX helpers -------------------------
__device__ __forceinline__ uint32_t smem_u32(const void* p) {
    uint32_t a;
    asm("{ .reg .u64 t; cvta.to.shared.u64 t, %1; cvt.u32.u64 %0, t; }" : "=r"(a) : "l"(p));
    return a;
}
__device__ __forceinline__ void cp16(uint32_t s, const void* g) {
    asm volatile("cp.async.cg.shared.global [%0], [%1], 16;" :: "r"(s), "l"(g));
}
__device__ __forceinline__ void cpcommit() { asm volatile("cp.async.commit_group;" ::: "memory"); }
__device__ __forceinline__ void cpwait0()  { asm volatile("cp.async.wait_group 0;" ::: "memory"); }
__device__ __forceinline__ void cpwait1()  { asm volatile("cp.async.wait_group 1;" ::: "memory"); }

__device__ __forceinline__ void ldsm4(uint32_t* r, uint32_t addr) {
    asm volatile("ldmatrix.sync.aligned.m8n8.x4.shared.b16 {%0,%1,%2,%3}, [%4];"
        : "=r"(r[0]), "=r"(r[1]), "=r"(r[2]), "=r"(r[3]) : "r"(addr));
}
__device__ __forceinline__ void mma16816(float* c, const uint32_t* a, uint32_t b0, uint32_t b1) {
    asm volatile("mma.sync.aligned.m16n8k16.row.col.f32.f16.f16.f32 "
        "{%0,%1,%2,%3}, {%4,%5,%6,%7}, {%8,%9}, {%0,%1,%2,%3};"
        : "+f"(c[0]), "+f"(c[1]), "+f"(c[2]), "+f"(c[3])
        : "r"(a[0]), "r"(a[1]), "r"(a[2]), "r"(a[3]), "r"(b0), "r"(b1));
}

// ---------------------------------------------------------------------------
// fp16 HMMA GEMM (templated output). C = A @ B^T.
// 128x128 CTA tile, KTILE=32, 3-stage cp.async, 8 warps.
// per-z offsets: off = (z/zdiv)*sXa + (z%zdiv)*sXb
// ---------------------------------------------------------------------------
#define STG 16384
#define TC_SMEM (3*STG)

template<typename OT>
__global__ __launch_bounds__(256, 2)
void mma_gemm(const f16* __restrict__ Ahg, const f16* __restrict__ Bhg,
              OT* __restrict__ Cg,
              int K, int lda, int ldb, int ldc, int zdiv,
              ll sAa, ll sAb, ll sBa, ll sBb, ll sCa, ll sCb)
{
    extern __shared__ char smem_raw[];
    const uint32_t tiles = smem_u32(smem_raw);
    const int tid = threadIdx.x, wid = tid >> 5, lane = tid & 31;
    const int wm = wid & 3, wn = wid >> 2;

    const int z = blockIdx.z;
    const f16* Ah = Ahg + (ll)(z / zdiv) * sAa + (ll)(z % zdiv) * sAb;
    const f16* Bh = Bhg + (ll)(z / zdiv) * sBa + (ll)(z % zdiv) * sBb;
    OT* C = Cg + (ll)(z / zdiv) * sCa + (ll)(z % zdiv) * sCb;

    const int bm = blockIdx.y << 7, bn = blockIdx.x << 7;
    const int nk = K >> 5;

    auto load_stage = [&](int kt) {
        const uint32_t st = tiles + (uint32_t)(kt % 3) * STG;
        const ll kb = (ll)kt * 32;
#pragma unroll
        for (int i = tid; i < 512; i += 256) {
            const int r = i >> 2, c = i & 3;
            const uint32_t sw = (uint32_t)r * 64u + (uint32_t)((c ^ ((r >> 1) & 3)) << 4);
            cp16(st        + sw, Ah + (ll)(bm + r) * lda + kb + c * 8);
            cp16(st + 8192 + sw, Bh + (ll)(bn + r) * ldb + kb + c * 8);
        }
        cpcommit();
    };

    float acc[2][8][4];
#pragma unroll
    for (int i = 0; i < 2; i++)
#pragma unroll
        for (int j = 0; j < 8; j++)
#pragma unroll
            for (int t = 0; t < 4; t++) acc[i][j][t] = 0.f;

    const int aRow  = wm * 32 + (lane & 15);
    const int aCpar = lane >> 4;
    const int bNadd = ((lane >> 4) << 3) + (lane & 7);
    const int bCpar = (lane >> 3) & 1;

    load_stage(0);
    if (nk > 1) load_stage(1); else cpcommit();

    for (int kt = 0; kt < nk; kt++) {
        if (kt >= nk - 2) cpwait0(); else cpwait1();
        __syncthreads();
        if (kt + 2 < nk) load_stage(kt + 2); else cpcommit();

        const uint32_t st = tiles + (uint32_t)(kt % 3) * STG;
#pragma unroll
        for (int ks = 0; ks < 2; ks++) {
            uint32_t ahf[2][4];
#pragma unroll
            for (int mt = 0; mt < 2; mt++) {
                const int row = aRow + mt * 16;
                const int ch = ks * 2 + aCpar;
                const uint32_t ad = st + (uint32_t)row * 64u + (uint32_t)((ch ^ ((row >> 1) & 3)) << 4);
                ldsm4(ahf[mt], ad);
            }
#pragma unroll
            for (int np = 0; np < 2; np++) {
                uint32_t bh[2][4];
#pragma unroll
                for (int t = 0; t < 2; t++) {
                    const int nt = np * 2 + t;
                    const int row = wn * 64 + nt * 16 + bNadd;
                    const int ch = ks * 2 + bCpar;
                    const uint32_t bd = st + 8192u + (uint32_t)row * 64u + (uint32_t)((ch ^ ((row >> 1) & 3)) << 4);
                    ldsm4(bh[t], bd);
                }
#pragma unroll
                for (int t = 0; t < 2; t++) {
                    const int nb = (np * 2 + t) * 2;
                    mma16816(acc[0][nb],   ahf[0], bh[t][0], bh[t][1]);
                    mma16816(acc[0][nb+1], ahf[0], bh[t][2], bh[t][3]);
                    mma16816(acc[1][nb],   ahf[1], bh[t][0], bh[t][1]);
                    mma16816(acc[1][nb+1], ahf[1], bh[t][2], bh[t][3]);
                }
            }
        }
    }

    const int erow = bm + wm * 32 + (lane >> 2);
    const int ecol = bn + wn * 64 + (lane & 3) * 2;
#pragma unroll
    for (int mt = 0; mt < 2; mt++) {
#pragma unroll
        for (int j = 0; j < 8; j++) {
            OT* p0 = C + (ll)(erow + mt*16)     * ldc + ecol + j*8;
            OT* p1 = C + (ll)(erow + mt*16 + 8) * ldc + ecol + j*8;
            if constexpr (sizeof(OT) == 4) {
                *(float2*)p0 = make_float2(acc[mt][j][0], acc[mt][j][1]);
                *(float2*)p1 = make_float2(acc[mt][j][2], acc[mt][j][3]);
            } else {
                __half2 h0(__float2half_rn(acc[mt][j][0]), __float2half_rn(acc[mt][j][1]));
                __half2 h1(__float2half_rn(acc[mt][j][2]), __float2half_rn(acc[mt][j][3]));
                *(__half2*)p0 = h0;
                *(__half2*)p1 = h1;
            }
        }
    }
}

// ---------------------------------------------------------------------------
// Flash attention (fp16): CTA = 128 q-rows x 1 head. smem 96KB.
// ---------------------------------------------------------------------------
#define FA_SMEM 98304
#define FA_SCALE 0.08838834764831845f

__global__ __launch_bounds__(256, 1)
void flash_attn(const f16* __restrict__ qh, const f16* __restrict__ kh,
                const f16* __restrict__ vth, const float* __restrict__ mask,
                f16* __restrict__ oh)
{
    extern __shared__ char smem_raw[];
    const uint32_t sQ = smem_u32(smem_raw);
    const uint32_t sKV = sQ + 32768;
    const int tid = threadIdx.x, w = tid >> 5, lane = tid & 31;

    const int qt = blockIdx.x;
    const int z  = blockIdx.y;
    const int b  = z >> 4, h = z & 15;
    const int bS = b * SEQ;

    {
        const ll base = (ll)(bS + qt*128) * HID + h*128;
#pragma unroll
        for (int i = tid; i < 2048; i += 256) {
            const int r = i >> 4, c = i & 15;
            const uint32_t sw = (uint32_t)r*256u + (uint32_t)((c ^ (r & 15)) << 4);
            cp16(sQ + sw, qh + base + (ll)r * HID + c * 8);
        }
    }
    auto load_kv = [&](int kt) {
        const uint32_t st = sKV + (uint32_t)(kt & 1) * 32768;
        const ll kbase = (ll)(bS + kt*64) * HID + h*128;
#pragma unroll
        for (int i = tid; i < 1024; i += 256) {
            const int r = i >> 4, c = i & 15;
            const uint32_t sw = (uint32_t)r*256u + (uint32_t)((c ^ (r & 15)) << 4);
            cp16(st + sw, kh + kbase + (ll)r * HID + c * 8);
        }
        const ll vbase = (ll)z * 128 * SEQ + kt*64;
#pragma unroll
        for (int i = tid; i < 1024; i += 256) {
            const int r = i >> 3, c = i & 7;
            const uint32_t sw = (uint32_t)r*128u + (uint32_t)((c ^ (r & 7)) << 4);
            cp16(st + 16384 + sw, vth + vbase + (ll)r * SEQ + c * 8);
        }
        cpcommit();
    };

    float oacc[16][4];
#pragma unroll
    for (int i = 0; i < 16; i++)
#pragma unroll
        for (int t = 0; t < 4; t++) oacc[i][t] = 0.f;
    float m1 = -1e30f, m2 = -1e30f, l1 = 0.f, l2 = 0.f;

    const int aCpar = lane >> 4;
    const int bNadd = ((lane >> 4) << 3) + (lane & 7);
    const int bCpar = (lane >> 3) & 1;
    const int qRow  = w * 16 + (lane & 15);
    const int qpos1 = qt*128 + w*16 + (lane >> 2);
    const int colq  = (lane & 3) * 2;

    load_kv(0);
    const int NKT = SEQ / 64;

    for (int kt = 0; kt < NKT; kt++) {
        if (kt + 1 < NKT) { load_kv(kt + 1); cpwait1(); } else { cpwait0(); }
        __syncthreads();
        const uint32_t st = sKV + (uint32_t)(kt & 1) * 32768;

        float sacc[8][4];
#pragma unroll
        for (int j = 0; j < 8; j++)
#pragma unroll
            for (int t = 0; t < 4; t++) sacc[j][t] = 0.f;

#pragma unroll
        for (int ks = 0; ks < 8; ks++) {
            uint32_t ahf[4];
            {
                const int ch = ks*2 + aCpar;
                const uint32_t ad = sQ + (uint32_t)qRow*256u + (uint32_t)((ch ^ (qRow & 15)) << 4);
                ldsm4(ahf, ad);
            }
#pragma unroll
            for (int nt = 0; nt < 4; nt++) {
                const int row = nt*16 + bNadd;
                const int ch = ks*2 + bCpar;
                const uint32_t bd = st + (uint32_t)row*256u + (uint32_t)((ch ^ (row & 15)) << 4);
                uint32_t bh[4];
                ldsm4(bh, bd);
                mma16816(sacc[nt*2],   ahf, bh[0], bh[1]);
                mma16816(sacc[nt*2+1], ahf, bh[2], bh[3]);
            }
        }

        const int kbase = kt*64;
#pragma unroll
        for (int j = 0; j < 8; j++) {
            const int kposg = kbase + j*8 + colq;
            float2 mA = *(const float2*)(mask + (ll)qpos1 * SEQ + kposg);
            float2 mB = *(const float2*)(mask + (ll)(qpos1 + 8) * SEQ + kposg);
            sacc[j][0] = sacc[j][0]*FA_SCALE + mA.x;
            sacc[j][1] = sacc[j][1]*FA_SCALE + mA.y;
            sacc[j][2] = sacc[j][2]*FA_SCALE + mB.x;
            sacc[j][3] = sacc[j][3]*FA_SCALE + mB.y;
        }
        float mx1 = -1e30f, mx2 = -1e30f;
#pragma unroll
        for (int j = 0; j < 8; j++) {
            mx1 = fmaxf(mx1, fmaxf(sacc[j][0], sacc[j][1]));
            mx2 = fmaxf(mx2, fmaxf(sacc[j][2], sacc[j][3]));
        }
        mx1 = fmaxf(mx1, __shfl_xor_sync(0xffffffffu, mx1, 1));
        mx1 = fmaxf(mx1, __shfl_xor_sync(0xffffffffu, mx1, 2));
        mx2 = fmaxf(mx2, __shfl_xor_sync(0xffffffffu, mx2, 1));
        mx2 = fmaxf(mx2, __shfl_xor_sync(0xffffffffu, mx2, 2));
        const float nm1 = fmaxf(m1, mx1), nm2 = fmaxf(m2, mx2);
        const float al1 = __expf(m1 - nm1), al2 = __expf(m2 - nm2);
        m1 = nm1; m2 = nm2;
        float s1 = 0.f, s2 = 0.f;
#pragma unroll
        for (int j = 0; j < 8; j++) {
            sacc[j][0] = __expf(sacc[j][0] - nm1);
            sacc[j][1] = __expf(sacc[j][1] - nm1);
            sacc[j][2] = __expf(sacc[j][2] - nm2);
            sacc[j][3] = __expf(sacc[j][3] - nm2);
            s1 += sacc[j][0] + sacc[j][1];
            s2 += sacc[j][2] + sacc[j][3];
        }
        s1 += __shfl_xor_sync(0xffffffffu, s1, 1);
        s1 += __shfl_xor_sync(0xffffffffu, s1, 2);
        s2 += __shfl_xor_sync(0xffffffffu, s2, 1);
        s2 += __shfl_xor_sync(0xffffffffu, s2, 2);
        l1 = l1*al1 + s1;
        l2 = l2*al2 + s2;
#pragma unroll
        for (int i = 0; i < 16; i++) {
            oacc[i][0] *= al1; oacc[i][1] *= al1;
            oacc[i][2] *= al2; oacc[i][3] *= al2;
        }

#pragma unroll
        for (int kk = 0; kk < 4; kk++) {
            uint32_t pah[4];
            {
                __half2 t0(__float2half_rn(sacc[2*kk][0]),   __float2half_rn(sacc[2*kk][1]));
                __half2 t1(__float2half_rn(sacc[2*kk][2]),   __float2half_rn(sacc[2*kk][3]));
                __half2 t2(__float2half_rn(sacc[2*kk+1][0]), __float2half_rn(sacc[2*kk+1][1]));
                __half2 t3(__float2half_rn(sacc[2*kk+1][2]), __float2half_rn(sacc[2*kk+1][3]));
                pah[0] = *(uint32_t*)&t0; pah[1] = *(uint32_t*)&t1;
                pah[2] = *(uint32_t*)&t2; pah[3] = *(uint32_t*)&t3;
            }
#pragma unroll
            for (int nt = 0; nt < 8; nt++) {
                const int row = nt*16 + bNadd;
                const int ch = kk*2 + bCpar;
                const uint32_t bd = st + 16384u + (uint32_t)row*128u + (uint32_t)((ch ^ (row & 7)) << 4);
                uint32_t bh[4];
                ldsm4(bh, bd);
                mma16816(oacc[nt*2],   pah, bh[0], bh[1]);
                mma16816(oacc[nt*2+1], pah, bh[2], bh[3]);
            }
        }
        __syncthreads();
    }

    const float inv1 = 1.f / l1, inv2 = 1.f / l2;
    const ll row1 = (ll)(bS + qpos1);
#pragma unroll
    for (int nt = 0; nt < 16; nt++) {
        const int col = h*128 + nt*8 + colq;
        __half2 th(__float2half_rn(oacc[nt][0]*inv1), __float2half_rn(oacc[nt][1]*inv1));
        __half2 uh(__float2half_rn(oacc[nt][2]*inv2), __float2half_rn(oacc[nt][3]*inv2));
        *(__half2*)(oh + row1*HID + col)     = th;
        *(__half2*)(oh + (row1+8)*HID + col) = uh;
    }
}

// ------------------------- reductions -------------------------
__device__ __forceinline__ float wsum(float v) {
#pragma unroll
    for (int o = 16; o; o >>= 1) v += __shfl_xor_sync(0xffffffffu, v, o);
    return v;
}
__device__ __forceinline__ float bsum(float v) {
    __shared__ float sh[8];
    v = wsum(v); __syncthreads();
    if ((threadIdx.x & 31) == 0) sh[threadIdx.x >> 5] = v;
    __syncthreads();
    float r = 0.f;
#pragma unroll
    for (int i = 0; i < 8; i++) r += sh[i];
    return r;
}

// ------------------------- elementwise kernels -------------------------
__global__ __launch_bounds__(256)
void roundw_kernel(const float* __restrict__ s, f16* __restrict__ oh, int n4)
{
    const int i = blockIdx.x * 256 + threadIdx.x;
    if (i >= n4) return;
    float4 v = ((const float4*)s)[i];
    ((__half2*)oh)[2*i]   = __half2(__float2half_rn(v.x), __float2half_rn(v.y));
    ((__half2*)oh)[2*i+1] = __half2(__float2half_rn(v.z), __float2half_rn(v.w));
}

__global__ __launch_bounds__(256)
void roundw8_kernel(const float* p0, const float* p1, const float* p2, const float* p3,
                    const float* p4, const float* p5, const float* p6, const float* p7,
                    f16* __restrict__ oh, int n4)
{
    const int i = blockIdx.x * 256 + threadIdx.x;
    if (i >= n4) return;
    const int seg = blockIdx.y;
    const float* p;
    switch (seg) {
        case 0: p = p0; break; case 1: p = p1; break;
        case 2: p = p2; break; case 3: p = p3; break;
        case 4: p = p4; break; case 5: p = p5; break;
        case 6: p = p6; break; default: p = p7; break;
    }
    f16* o = oh + (ll)seg * H2;
    float4 v = ((const float4*)p)[i];
    ((__half2*)o)[2*i]   = __half2(__float2half_rn(v.x), __float2half_rn(v.y));
    ((__half2*)o)[2*i+1] = __half2(__float2half_rn(v.z), __float2half_rn(v.w));
}

__global__ __launch_bounds__(256)
void roundw3_kernel(const float* p0, const float* p1, const float* p2,
                    f16* __restrict__ oh, int n4)
{
    const int i = blockIdx.x * 256 + threadIdx.x;
    if (i >= n4) return;
    const int seg = blockIdx.y;
    const float* p = (seg == 0) ? p0 : (seg == 1 ? p1 : p2);
    f16* o = oh + (ll)seg * FF2;
    float4 v = ((const float4*)p)[i];
    ((__half2*)o)[2*i]   = __half2(__float2half_rn(v.x), __float2half_rn(v.y));
    ((__half2*)o)[2*i+1] = __half2(__float2half_rn(v.z), __float2half_rn(v.w));
}

__global__ __launch_bounds__(256)
void rmsnorm_round(const float* __restrict__ in, const float* __restrict__ w,
                   f16* __restrict__ oh)
{
    const ll base = (ll)blockIdx.x * HID;
    const float4* xin = (const float4*)(in + base);
    float ss = 0.f;
    for (int i = threadIdx.x; i < HID/4; i += 256) {
        float4 v = xin[i];
        ss += v.x*v.x + v.y*v.y + v.z*v.z + v.w*v.w;
    }
    ss = bsum(ss);
    const float r = rsqrtf(ss * (1.f/HID) + RMS_EPS);
    for (int i = threadIdx.x; i < HID/4; i += 256) {
        float4 v = xin[i];
        float4 ww = ((const float4*)w)[i];
        ((__half2*)(oh + base))[2*i]   = __half2(__float2half_rn(v.x*r*ww.x), __float2half_rn(v.y*r*ww.y));
        ((__half2*)(oh + base))[2*i+1] = __half2(__float2half_rn(v.z*r*ww.z), __float2half_rn(v.w*r*ww.w));
    }
}

__global__ void rope_inplace(f16* __restrict__ t)
{
    const int idx = blockIdx.x * blockDim.x + threadIdx.x;
    if (idx >= ROWS * NHEAD * 64) return;
    const int j = idx & 63, h = (idx >> 6) & (NHEAD-1), row = idx >> 10;
    const int pos = row & (SEQ - 1);
    const float inv = (float)exp(-(double)(2*j) / (double)HDIM * log(10000.0));
    float s_, c;
    sincosf((float)pos * inv, &s_, &c);
    const ll p0 = (ll)row * HID + h * HDIM + j;
    const float q0 = __half2float(t[p0]), q1 = __half2float(t[p0 + 64]);
    t[p0]      = __float2half_rn(q0*c - q1*s_);
    t[p0+64]   = __float2half_rn(q1*c + q0*s_);
}

__global__ void vtrans_kernel(const f16* __restrict__ v, f16* __restrict__ oh)
{
    __shared__ f16 t[32][34];
    const int z = blockIdx.z, b = z >> 4, h = z & 15;
    const int s0 = blockIdx.x * 32, d0 = blockIdx.y * 32;
    const int tx = threadIdx.x, ty = threadIdx.y;
#pragma unroll
    for (int i = 0; i < 4; i++) {
        const int s = s0 + ty + i*8;
        t[ty + i*8][tx] = v[((ll)(b*SEQ + s)) * HID + h*HDIM + d0 + tx];
    }
    __syncthreads();
#pragma unroll
    for (int i = 0; i < 4; i++) {
        const int d = d0 + ty + i*8;
        oh[((ll)z * HDIM + d) * SEQ + s0 + tx] = t[tx][ty + i*8];
    }
}

__device__ __forceinline__ float sigm(float z) { return 1.f / (1.f + expf(-z)); }

// out = sigmoid(g + bias) * h
__global__ void highway_kernel(const f16* __restrict__ gsrc, const f16* __restrict__ hsrc,
                               const float* __restrict__ bias, float* __restrict__ out, int n4)
{
    const int i = blockIdx.x * blockDim.x + threadIdx.x;
    if (i >= n4) return;
    __half2 g0 = ((const __half2*)gsrc)[2*i], g1 = ((const __half2*)gsrc)[2*i+1];
    __half2 h0 = ((const __half2*)hsrc)[2*i], h1 = ((const __half2*)hsrc)[2*i+1];
    float4 bv = ((const float4*)bias)[i & (HID/4 - 1)];
    ((float4*)out)[i] = make_float4(
        __half2float(h0.x)*sigm(__half2float(g0.x)+bv.x),
        __half2float(h0.y)*sigm(__half2float(g0.y)+bv.y),
        __half2float(h1.x)*sigm(__half2float(g1.x)+bv.z),
        __half2float(h1.y)*sigm(__half2float(g1.y)+bv.w));
}

// Fused: v = xm + mod + sigmoid(dg + bias)*dw ; x = v*(1 + r1*w_in) ;
//        hb = fp16(x * r2 * w_post) ; also store x (fp32).
__global__ __launch_bounds__(256)
void combine_fused(const float* __restrict__ xm, const f16* __restrict__ mod,
                   const f16* __restrict__ dw, const f16* __restrict__ dg,
                   const float* __restrict__ bias,
                   const float* __restrict__ w_in, const float* __restrict__ w_post,
                   float* __restrict__ xout, f16* __restrict__ hb)
{
    const ll base = (ll)blockIdx.x * HID;
    const int t = threadIdx.x;
    float v[8];
    float ss = 0.f;
#pragma unroll
    for (int u = 0; u < 2; u++) {
        const int i = t + u * 256;
        float4 xv = ((const float4*)(xm + base))[i];
        __half2 m0 = ((const __half2*)(mod + base))[2*i], m1 = ((const __half2*)(mod + base))[2*i+1];
        __half2 g0 = ((const __half2*)(dg + base))[2*i],  g1 = ((const __half2*)(dg + base))[2*i+1];
        __half2 h0 = ((const __half2*)(dw + base))[2*i],  h1 = ((const __half2*)(dw + base))[2*i+1];
        float4 bv = ((const float4*)bias)[i];
        v[u*4+0] = xv.x + __half2float(m0.x) + __half2float(h0.x)*sigm(__half2float(g0.x)+bv.x);
        v[u*4+1] = xv.y + __half2float(m0.y) + __half2float(h0.y)*sigm(__half2float(g0.y)+bv.y);
        v[u*4+2] = xv.z + __half2float(m1.x) + __half2float(h1.x)*sigm(__half2float(g1.x)+bv.z);
        v[u*4+3] = xv.w + __half2float(m1.y) + __half2float(h1.y)*sigm(__half2float(g1.y)+bv.w);
        ss += v[u*4+0]*v[u*4+0] + v[u*4+1]*v[u*4+1] + v[u*4+2]*v[u*4+2] + v[u*4+3]*v[u*4+3];
    }
    ss = bsum(ss);
    const float r1 = rsqrtf(ss * (1.f/HID) + RMS_EPS);
    float ss2 = 0.f;
#pragma unroll
    for (int u = 0; u < 2; u++) {
        const int i = t + u * 256;
        float4 wi = ((const float4*)w_in)[i];
        v[u*4+0] *= (1.f + r1*wi.x);
        v[u*4+1] *= (1.f + r1*wi.y);
        v[u*4+2] *= (1.f + r1*wi.z);
        v[u*4+3] *= (1.f + r1*wi.w);
        ss2 += v[u*4+0]*v[u*4+0] + v[u*4+1]*v[u*4+1] + v[u*4+2]*v[u*4+2] + v[u*4+3]*v[u*4+3];
        ((float4*)(xout + base))[i] = make_float4(v[u*4+0], v[u*4+1], v[u*4+2], v[u*4+3]);
    }
    ss2 = bsum(ss2);
    const float r2 = rsqrtf(ss2 * (1.f/HID) + RMS_EPS);
#pragma unroll
    for (int u = 0; u < 2; u++) {
        const int i = t + u * 256;
        float4 wp = ((const float4*)w_post)[i];
        ((__half2*)(hb + base))[2*i]   = __half2(__float2half_rn(v[u*4+0]*r2*wp.x),
                                                 __float2half_rn(v[u*4+1]*r2*wp.y));
        ((__half2*)(hb + base))[2*i+1] = __half2(__float2half_rn(v[u*4+2]*r2*wp.z),
                                                 __float2half_rn(v[u*4+3]*r2*wp.w));
    }
}

__global__ void silumul_round(const f16* __restrict__ g, const f16* __restrict__ u,
                              f16* __restrict__ oh, int n4)
{
    const int i = blockIdx.x * blockDim.x + threadIdx.x;
    if (i >= n4) return;
    __half2 g0 = ((const __half2*)g)[2*i], g1 = ((const __half2*)g)[2*i+1];
    __half2 u0 = ((const __half2*)u)[2*i], u1 = ((const __half2*)u)[2*i+1];
    float a = __half2float(g0.x), bq = __half2float(g0.y);
    float c = __half2float(g1.x), d = __half2float(g1.y);
    ((__half2*)oh)[2*i]   = __half2(__float2half_rn(a*sigm(a)*__half2float(u0.x)),
                                    __float2half_rn(bq*sigm(bq)*__half2float(u0.y)));
    ((__half2*)oh)[2*i+1] = __half2(__float2half_rn(c*sigm(c)*__half2float(u1.x)),
                                    __float2half_rn(d*sigm(d)*__half2float(u1.y)));
}

__global__ void add2_kernel(const float* __restrict__ a, const float* __restrict__ b,
                            float* __restrict__ out, int n4)
{
    const int i = blockIdx.x * blockDim.x + threadIdx.x;
    if (i >= n4) return;
    float4 av = ((const float4*)a)[i], bv = ((const float4*)b)[i];
    ((float4*)out)[i] = make_float4(av.x+bv.x, av.y+bv.y, av.z+bv.z, av.w+bv.w);
}

// ------------------------- launch -------------------------
extern "C" void kernel_launch(void* const* d_in, const int* in_sizes, int n_in,
                              void* d_out, int out_size)
{
    const float* x_mod = (const float*)d_in[0];
    const float* x_back= (const float*)d_in[1];
    const float* mask  = (const float*)d_in[2];
    const float* wq = (const float*)d_in[3];
    const float* wk = (const float*)d_in[4];
    const float* wv = (const float*)d_in[5];
    const float* wo = (const float*)d_in[6];
    const float* cross_ln_w = (const float*)d_in[7];
    const float* fb_w = (const float*)d_in[8];
    const float* fb_g = (const float*)d_in[9];
    const float* fb_gb= (const float*)d_in[10];
    const float* dr_w = (const float*)d_in[11];
    const float* dr_g = (const float*)d_in[12];
    const float* dr_gb= (const float*)d_in[13];
    const float* in_ln_w   = (const float*)d_in[14];
    const float* post_ln_w = (const float*)d_in[15];
    const float* w_gate = (const float*)d_in[16];
    const float* w_up   = (const float*)d_in[17];
    const float* w_down = (const float*)d_in[18];

    float* outx = (float*)d_out;
    float* outd = outx + (size_t)ROWS * HID;

    float *mod,*x;
    f16 *wh,*ah,*modh,*t12,*gu;
    cudaGetSymbolAddress((void**)&mod, g_mod);
    cudaGetSymbolAddress((void**)&x, g_x);
    cudaGetSymbolAddress((void**)&wh, g_wh);
    cudaGetSymbolAddress((void**)&ah, g_ah);
    cudaGetSymbolAddress((void**)&modh, g_modh);
    cudaGetSymbolAddress((void**)&t12, g_t12);
    cudaGetSymbolAddress((void**)&gu, g_gu);

    cudaFuncSetAttribute(mma_gemm<float>, cudaFuncAttributeMaxDynamicSharedMemorySize, TC_SMEM);
    cudaFuncSetAttribute(mma_gemm<f16>,   cudaFuncAttributeMaxDynamicSharedMemorySize, TC_SMEM);
    cudaFuncSetAttribute(flash_attn,      cudaFuncAttributeMaxDynamicSharedMemorySize, FA_SMEM);

    const int n4h = (int)(RH/4), n4f = (int)(GGN/4), n4w = (int)(H2/4), n4ff = (int)(FF2/4);
    const dim3 B256(256);

    auto gemmH = [&](const f16* pa, const f16* pb, f16* c,
                     int M, int N, int K, int lda, int ldb, int ldc,
                     int gz, int zdiv, ll saa, ll sab, ll sba, ll sbb, ll sca, ll scb) {
        dim3 g(N/128, M/128, gz);
        mma_gemm<f16><<<g, 256, TC_SMEM>>>(pa, pb, c, K, lda, ldb, ldc, zdiv,
                                           saa, sab, sba, sbb, sca, scb);
    };
    auto gemmF = [&](const f16* pa, const f16* pb, float* c,
                     int M, int N, int K, int lda, int ldb, int ldc) {
        dim3 g(N/128, M/128, 1);
        mma_gemm<float><<<g, 256, TC_SMEM>>>(pa, pb, c, K, lda, ldb, ldc, 1, 0,0,0,0,0,0);
    };

    // ---- rounds (merged) ----
    roundw_kernel<<<n4h/256, B256>>>(x_back, ah+OXB, n4h);
    roundw_kernel<<<n4h/256, B256>>>(x_mod,  ah+OXM, n4h);
    rmsnorm_round<<<ROWS, B256>>>(x_mod, cross_ln_w, ah+OQN);
    roundw8_kernel<<<dim3(n4w/256, 8), B256>>>(wq, wk, wv, wo, fb_w, fb_g, dr_w, dr_g, wh, n4w);
    roundw3_kernel<<<dim3(n4ff/256, 3), B256>>>(w_gate, w_up, w_down, wh+OWG, n4ff);

    // ---- projections: q single, k+v merged (A stride = 0 !) ----
    gemmH(ah+OQN, wh+OWQ, ah+OQ,  ROWS, HID, HID, HID, HID, HID, 1, 1, 0,0, 0,0, 0,0);
    gemmH(ah+OXB, wh+OWK, ah+OK2, ROWS, HID, HID, HID, HID, HID, 2, 1, 0,0, H2,0, 2*RH,0);

    // ---- z=4 merged highway GEMM: z<2 -> A=OXM (feedback), z>=2 -> A=OXB (driver)
    gemmH(ah+OXM, wh+OFBW, t12, ROWS, HID, HID, HID, HID, HID,
          4, 2, -(ll)RH, 0, 2*H2, H2, 2*RH, RH);
    highway_kernel<<<n4h/256, B256>>>(t12+RH, t12, fb_gb, outd, n4h);

    const int ropeN = ROWS * NHEAD * 64;
    rope_inplace<<<(ropeN+255)/256, B256>>>(ah+OQ);
    rope_inplace<<<(ropeN+255)/256, B256>>>(ah+OK2);
    vtrans_kernel<<<dim3(SEQ/32, HDIM/32, BATCH*NHEAD), dim3(32,8)>>>(ah+OATT, ah+OVT);

    // ---- flash attention -> OATT, then WO ----
    flash_attn<<<dim3(SEQ/128, BATCH*NHEAD), B256, FA_SMEM>>>(
        ah+OQ, ah+OK2, ah+OVT, mask, ah+OATT);
    gemmH(ah+OATT, wh+OWO, modh, ROWS, HID, HID, HID, HID, HID, 1, 1, 0,0, 0,0, 0,0);

    // ---- fused combine + rmsadd + rmsnorm ----
    combine_fused<<<ROWS, B256>>>(x_mod, modh, t12+2*RH, t12+3*RH, dr_gb,
                                  in_ln_w, post_ln_w, x, ah+OHB);

    // ---- MLP ----
    gemmH(ah+OHB, wh+OWG, gu, ROWS, FFD, HID, HID, HID, FFD, 2, 1, 0,0, FF2,0, GGN,0);
    silumul_round<<<n4f/256, B256>>>(gu, gu+GGN, ah+OGG, n4f);
    gemmF(ah+OGG, wh+OWD, mod, ROWS, HID, FFD, FFD, FFD, HID);
    add2_kernel<<<n4h/256, B256>>>(x, mod, outx, n4h);
}

// round 16
// speedup vs baseline: 2.3790x; 1.0027x over previous
#include <cuda_runtime.h>
#include <cuda_fp16.h>
#include <cstdint>
#include <math.h>
using f16 = __half;
typedef long long ll;

#define BATCH 2
#define SEQ 2048
#define HID 2048
#define NHEAD 16
#define HDIM 128
#define FFD 8192
#define ROWS 4096
#define RMS_EPS 1e-5f
#define RH 8388608LL
#define H2 4194304LL
#define FF2 16777216LL
#define GGN 33554432LL

// ------------------------- scratch -------------------------
__device__ float g_x[RH];
__device__ f16 g_wh[8*H2+3*FF2];     // weights fp16 (contiguous for merged rounds / z-GEMMs)
__device__ f16 g_ah[8*RH+GGN];       // activations fp16
__device__ f16 g_modh[RH];
__device__ f16 g_t12[4*RH];          // z=4 highway outputs: fb_w, fb_g, dr_w, dr_g
__device__ f16 g_gu[2*GGN];          // merged gate/up

// weight arena offsets (wq,wk,wv adjacent; fb_w..dr_g contiguous; gate/up adjacent)
#define OWQ  (0*H2)
#define OWK  (1*H2)
#define OWV  (2*H2)
#define OWO  (3*H2)
#define OFBW (4*H2)
#define OFBG (5*H2)
#define ODRW (6*H2)
#define ODRG (7*H2)
#define OWG  (8*H2)
#define OWU  (8*H2+FF2)
#define OWD  (8*H2+2*FF2)
// activation arena offsets
#define OQN  (0*RH)   // OQN = OXB - RH (used by z=3 qkv A stride)
#define OXB  (1*RH)
#define OXM  (2*RH)
#define OQ   (3*RH)   // OQ = OK2 - RH ; rope runs over OQ..OK2 contiguous
#define OK2  (4*RH)
#define OVT  (5*RH)
#define OATT (6*RH)   // = OK2 + 2RH (v temp from merged qkv GEMM)
#define OHB  (7*RH)
#define OGG  (8*RH)

// ------------------------- PTX helpers -------------------------
__device__ __forceinline__ uint32_t smem_u32(const void* p) {
    uint32_t a;
    asm("{ .reg .u64 t; cvta.to.shared.u64 t, %1; cvt.u32.u64 %0, t; }" : "=r"(a) : "l"(p));
    return a;
}
__device__ __forceinline__ void cp16(uint32_t s, const void* g) {
    asm volatile("cp.async.cg.shared.global [%0], [%1], 16;" :: "r"(s), "l"(g));
}
__device__ __forceinline__ void cpcommit() { asm volatile("cp.async.commit_group;" ::: "memory"); }
__device__ __forceinline__ void cpwait0()  { asm volatile("cp.async.wait_group 0;" ::: "memory"); }
__device__ __forceinline__ void cpwait1()  { asm volatile("cp.async.wait_group 1;" ::: "memory"); }

__device__ __forceinline__ void ldsm4(uint32_t* r, uint32_t addr) {
    asm volatile("ldmatrix.sync.aligned.m8n8.x4.shared.b16 {%0,%1,%2,%3}, [%4];"
        : "=r"(r[0]), "=r"(r[1]), "=r"(r[2]), "=r"(r[3]) : "r"(addr));
}
__device__ __forceinline__ void mma16816(float* c, const uint32_t* a, uint32_t b0, uint32_t b1) {
    asm volatile("mma.sync.aligned.m16n8k16.row.col.f32.f16.f16.f32 "
        "{%0,%1,%2,%3}, {%4,%5,%6,%7}, {%8,%9}, {%0,%1,%2,%3};"
        : "+f"(c[0]), "+f"(c[1]), "+f"(c[2]), "+f"(c[3])
        : "r"(a[0]), "r"(a[1]), "r"(a[2]), "r"(a[3]), "r"(b0), "r"(b1));
}

// ---------------------------------------------------------------------------
// fp16 HMMA GEMM (templated output). C = A @ B^T [+ addsrc if float out].
// 128x128 CTA tile, KTILE=32, 3-stage cp.async, 8 warps.
// per-z offsets: off = (z/zdiv)*sXa + (z%zdiv)*sXb
// ---------------------------------------------------------------------------
#define STG 16384
#define TC_SMEM (3*STG)

template<typename OT>
__global__ __launch_bounds__(256, 2)
void mma_gemm(const f16* __restrict__ Ahg, const f16* __restrict__ Bhg,
              OT* __restrict__ Cg, const float* __restrict__ addsrc,
              int K, int lda, int ldb, int ldc, int zdiv,
              ll sAa, ll sAb, ll sBa, ll sBb, ll sCa, ll sCb)
{
    extern __shared__ char smem_raw[];
    const uint32_t tiles = smem_u32(smem_raw);
    const int tid = threadIdx.x, wid = tid >> 5, lane = tid & 31;
    const int wm = wid & 3, wn = wid >> 2;

    const int z = blockIdx.z;
    const f16* Ah = Ahg + (ll)(z / zdiv) * sAa + (ll)(z % zdiv) * sAb;
    const f16* Bh = Bhg + (ll)(z / zdiv) * sBa + (ll)(z % zdiv) * sBb;
    OT* C = Cg + (ll)(z / zdiv) * sCa + (ll)(z % zdiv) * sCb;

    const int bm = blockIdx.y << 7, bn = blockIdx.x << 7;
    const int nk = K >> 5;

    auto load_stage = [&](int kt) {
        const uint32_t st = tiles + (uint32_t)(kt % 3) * STG;
        const ll kb = (ll)kt * 32;
#pragma unroll
        for (int i = tid; i < 512; i += 256) {
            const int r = i >> 2, c = i & 3;
            const uint32_t sw = (uint32_t)r * 64u + (uint32_t)((c ^ ((r >> 1) & 3)) << 4);
            cp16(st        + sw, Ah + (ll)(bm + r) * lda + kb + c * 8);
            cp16(st + 8192 + sw, Bh + (ll)(bn + r) * ldb + kb + c * 8);
        }
        cpcommit();
    };

    float acc[2][8][4];
#pragma unroll
    for (int i = 0; i < 2; i++)
#pragma unroll
        for (int j = 0; j < 8; j++)
#pragma unroll
            for (int t = 0; t < 4; t++) acc[i][j][t] = 0.f;

    const int aRow  = wm * 32 + (lane & 15);
    const int aCpar = lane >> 4;
    const int bNadd = ((lane >> 4) << 3) + (lane & 7);
    const int bCpar = (lane >> 3) & 1;

    load_stage(0);
    if (nk > 1) load_stage(1); else cpcommit();

    for (int kt = 0; kt < nk; kt++) {
        if (kt >= nk - 2) cpwait0(); else cpwait1();
        __syncthreads();
        if (kt + 2 < nk) load_stage(kt + 2); else cpcommit();

        const uint32_t st = tiles + (uint32_t)(kt % 3) * STG;
#pragma unroll
        for (int ks = 0; ks < 2; ks++) {
            uint32_t ahf[2][4];
#pragma unroll
            for (int mt = 0; mt < 2; mt++) {
                const int row = aRow + mt * 16;
                const int ch = ks * 2 + aCpar;
                const uint32_t ad = st + (uint32_t)row * 64u + (uint32_t)((ch ^ ((row >> 1) & 3)) << 4);
                ldsm4(ahf[mt], ad);
            }
#pragma unroll
            for (int np = 0; np < 2; np++) {
                uint32_t bh[2][4];
#pragma unroll
                for (int t = 0; t < 2; t++) {
                    const int nt = np * 2 + t;
                    const int row = wn * 64 + nt * 16 + bNadd;
                    const int ch = ks * 2 + bCpar;
                    const uint32_t bd = st + 8192u + (uint32_t)row * 64u + (uint32_t)((ch ^ ((row >> 1) & 3)) << 4);
                    ldsm4(bh[t], bd);
                }
#pragma unroll
                for (int t = 0; t < 2; t++) {
                    const int nb = (np * 2 + t) * 2;
                    mma16816(acc[0][nb],   ahf[0], bh[t][0], bh[t][1]);
                    mma16816(acc[0][nb+1], ahf[0], bh[t][2], bh[t][3]);
                    mma16816(acc[1][nb],   ahf[1], bh[t][0], bh[t][1]);
                    mma16816(acc[1][nb+1], ahf[1], bh[t][2], bh[t][3]);
                }
            }
        }
    }

    const int erow = bm + wm * 32 + (lane >> 2);
    const int ecol = bn + wn * 64 + (lane & 3) * 2;
#pragma unroll
    for (int mt = 0; mt < 2; mt++) {
#pragma unroll
        for (int j = 0; j < 8; j++) {
            const ll o0 = (ll)(erow + mt*16)     * ldc + ecol + j*8;
            const ll o1 = (ll)(erow + mt*16 + 8) * ldc + ecol + j*8;
            if constexpr (sizeof(OT) == 4) {
                float2 a0 = make_float2(0.f, 0.f), a1 = make_float2(0.f, 0.f);
                if (addsrc) {
                    a0 = *(const float2*)(addsrc + o0);
                    a1 = *(const float2*)(addsrc + o1);
                }
                *(float2*)(C + o0) = make_float2(acc[mt][j][0] + a0.x, acc[mt][j][1] + a0.y);
                *(float2*)(C + o1) = make_float2(acc[mt][j][2] + a1.x, acc[mt][j][3] + a1.y);
            } else {
                __half2 h0(__float2half_rn(acc[mt][j][0]), __float2half_rn(acc[mt][j][1]));
                __half2 h1(__float2half_rn(acc[mt][j][2]), __float2half_rn(acc[mt][j][3]));
                *(__half2*)(C + o0) = h0;
                *(__half2*)(C + o1) = h1;
            }
        }
    }
}

// ---------------------------------------------------------------------------
// Flash attention (fp16): CTA = 128 q-rows x 1 head. smem 96KB.
// ---------------------------------------------------------------------------
#define FA_SMEM 98304
#define FA_SCALE 0.08838834764831845f

__global__ __launch_bounds__(256, 1)
void flash_attn(const f16* __restrict__ qh, const f16* __restrict__ kh,
                const f16* __restrict__ vth, const float* __restrict__ mask,
                f16* __restrict__ oh)
{
    extern __shared__ char smem_raw[];
    const uint32_t sQ = smem_u32(smem_raw);
    const uint32_t sKV = sQ + 32768;
    const int tid = threadIdx.x, w = tid >> 5, lane = tid & 31;

    const int qt = blockIdx.x;
    const int z  = blockIdx.y;
    const int b  = z >> 4, h = z & 15;
    const int bS = b * SEQ;

    {
        const ll base = (ll)(bS + qt*128) * HID + h*128;
#pragma unroll
        for (int i = tid; i < 2048; i += 256) {
            const int r = i >> 4, c = i & 15;
            const uint32_t sw = (uint32_t)r*256u + (uint32_t)((c ^ (r & 15)) << 4);
            cp16(sQ + sw, qh + base + (ll)r * HID + c * 8);
        }
    }
    auto load_kv = [&](int kt) {
        const uint32_t st = sKV + (uint32_t)(kt & 1) * 32768;
        const ll kbase = (ll)(bS + kt*64) * HID + h*128;
#pragma unroll
        for (int i = tid; i < 1024; i += 256) {
            const int r = i >> 4, c = i & 15;
            const uint32_t sw = (uint32_t)r*256u + (uint32_t)((c ^ (r & 15)) << 4);
            cp16(st + sw, kh + kbase + (ll)r * HID + c * 8);
        }
        const ll vbase = (ll)z * 128 * SEQ + kt*64;
#pragma unroll
        for (int i = tid; i < 1024; i += 256) {
            const int r = i >> 3, c = i & 7;
            const uint32_t sw = (uint32_t)r*128u + (uint32_t)((c ^ (r & 7)) << 4);
            cp16(st + 16384 + sw, vth + vbase + (ll)r * SEQ + c * 8);
        }
        cpcommit();
    };

    float oacc[16][4];
#pragma unroll
    for (int i = 0; i < 16; i++)
#pragma unroll
        for (int t = 0; t < 4; t++) oacc[i][t] = 0.f;
    float m1 = -1e30f, m2 = -1e30f, l1 = 0.f, l2 = 0.f;

    const int aCpar = lane >> 4;
    const int bNadd = ((lane >> 4) << 3) + (lane & 7);
    const int bCpar = (lane >> 3) & 1;
    const int qRow  = w * 16 + (lane & 15);
    const int qpos1 = qt*128 + w*16 + (lane >> 2);
    const int colq  = (lane & 3) * 2;

    load_kv(0);
    const int NKT = SEQ / 64;

    for (int kt = 0; kt < NKT; kt++) {
        if (kt + 1 < NKT) { load_kv(kt + 1); cpwait1(); } else { cpwait0(); }
        __syncthreads();
        const uint32_t st = sKV + (uint32_t)(kt & 1) * 32768;

        float sacc[8][4];
#pragma unroll
        for (int j = 0; j < 8; j++)
#pragma unroll
            for (int t = 0; t < 4; t++) sacc[j][t] = 0.f;

#pragma unroll
        for (int ks = 0; ks < 8; ks++) {
            uint32_t ahf[4];
            {
                const int ch = ks*2 + aCpar;
                const uint32_t ad = sQ + (uint32_t)qRow*256u + (uint32_t)((ch ^ (qRow & 15)) << 4);
                ldsm4(ahf, ad);
            }
#pragma unroll
            for (int nt = 0; nt < 4; nt++) {
                const int row = nt*16 + bNadd;
                const int ch = ks*2 + bCpar;
                const uint32_t bd = st + (uint32_t)row*256u + (uint32_t)((ch ^ (row & 15)) << 4);
                uint32_t bh[4];
                ldsm4(bh, bd);
                mma16816(sacc[nt*2],   ahf, bh[0], bh[1]);
                mma16816(sacc[nt*2+1], ahf, bh[2], bh[3]);
            }
        }

        const int kbase = kt*64;
#pragma unroll
        for (int j = 0; j < 8; j++) {
            const int kposg = kbase + j*8 + colq;
            float2 mA = *(const float2*)(mask + (ll)qpos1 * SEQ + kposg);
            float2 mB = *(const float2*)(mask + (ll)(qpos1 + 8) * SEQ + kposg);
            sacc[j][0] = sacc[j][0]*FA_SCALE + mA.x;
            sacc[j][1] = sacc[j][1]*FA_SCALE + mA.y;
            sacc[j][2] = sacc[j][2]*FA_SCALE + mB.x;
            sacc[j][3] = sacc[j][3]*FA_SCALE + mB.y;
        }
        float mx1 = -1e30f, mx2 = -1e30f;
#pragma unroll
        for (int j = 0; j < 8; j++) {
            mx1 = fmaxf(mx1, fmaxf(sacc[j][0], sacc[j][1]));
            mx2 = fmaxf(mx2, fmaxf(sacc[j][2], sacc[j][3]));
        }
        mx1 = fmaxf(mx1, __shfl_xor_sync(0xffffffffu, mx1, 1));
        mx1 = fmaxf(mx1, __shfl_xor_sync(0xffffffffu, mx1, 2));
        mx2 = fmaxf(mx2, __shfl_xor_sync(0xffffffffu, mx2, 1));
        mx2 = fmaxf(mx2, __shfl_xor_sync(0xffffffffu, mx2, 2));
        const float nm1 = fmaxf(m1, mx1), nm2 = fmaxf(m2, mx2);
        const float al1 = __expf(m1 - nm1), al2 = __expf(m2 - nm2);
        m1 = nm1; m2 = nm2;
        float s1 = 0.f, s2 = 0.f;
#pragma unroll
        for (int j = 0; j < 8; j++) {
            sacc[j][0] = __expf(sacc[j][0] - nm1);
            sacc[j][1] = __expf(sacc[j][1] - nm1);
            sacc[j][2] = __expf(sacc[j][2] - nm2);
            sacc[j][3] = __expf(sacc[j][3] - nm2);
            s1 += sacc[j][0] + sacc[j][1];
            s2 += sacc[j][2] + sacc[j][3];
        }
        s1 += __shfl_xor_sync(0xffffffffu, s1, 1);
        s1 += __shfl_xor_sync(0xffffffffu, s1, 2);
        s2 += __shfl_xor_sync(0xffffffffu, s2, 1);
        s2 += __shfl_xor_sync(0xffffffffu, s2, 2);
        l1 = l1*al1 + s1;
        l2 = l2*al2 + s2;
#pragma unroll
        for (int i = 0; i < 16; i++) {
            oacc[i][0] *= al1; oacc[i][1] *= al1;
            oacc[i][2] *= al2; oacc[i][3] *= al2;
        }

#pragma unroll
        for (int kk = 0; kk < 4; kk++) {
            uint32_t pah[4];
            {
                __half2 t0(__float2half_rn(sacc[2*kk][0]),   __float2half_rn(sacc[2*kk][1]));
                __half2 t1(__float2half_rn(sacc[2*kk][2]),   __float2half_rn(sacc[2*kk][3]));
                __half2 t2(__float2half_rn(sacc[2*kk+1][0]), __float2half_rn(sacc[2*kk+1][1]));
                __half2 t3(__float2half_rn(sacc[2*kk+1][2]), __float2half_rn(sacc[2*kk+1][3]));
                pah[0] = *(uint32_t*)&t0; pah[1] = *(uint32_t*)&t1;
                pah[2] = *(uint32_t*)&t2; pah[3] = *(uint32_t*)&t3;
            }
#pragma unroll
            for (int nt = 0; nt < 8; nt++) {
                const int row = nt*16 + bNadd;
                const int ch = kk*2 + bCpar;
                const uint32_t bd = st + 16384u + (uint32_t)row*128u + (uint32_t)((ch ^ (row & 7)) << 4);
                uint32_t bh[4];
                ldsm4(bh, bd);
                mma16816(oacc[nt*2],   pah, bh[0], bh[1]);
                mma16816(oacc[nt*2+1], pah, bh[2], bh[3]);
            }
        }
        __syncthreads();
    }

    const float inv1 = 1.f / l1, inv2 = 1.f / l2;
    const ll row1 = (ll)(bS + qpos1);
#pragma unroll
    for (int nt = 0; nt < 16; nt++) {
        const int col = h*128 + nt*8 + colq;
        __half2 th(__float2half_rn(oacc[nt][0]*inv1), __float2half_rn(oacc[nt][1]*inv1));
        __half2 uh(__float2half_rn(oacc[nt][2]*inv2), __float2half_rn(oacc[nt][3]*inv2));
        *(__half2*)(oh + row1*HID + col)     = th;
        *(__half2*)(oh + (row1+8)*HID + col) = uh;
    }
}

// ------------------------- reductions -------------------------
__device__ __forceinline__ float wsum(float v) {
#pragma unroll
    for (int o = 16; o; o >>= 1) v += __shfl_xor_sync(0xffffffffu, v, o);
    return v;
}
__device__ __forceinline__ float bsum(float v) {
    __shared__ float sh[8];
    v = wsum(v); __syncthreads();
    if ((threadIdx.x & 31) == 0) sh[threadIdx.x >> 5] = v;
    __syncthreads();
    float r = 0.f;
#pragma unroll
    for (int i = 0; i < 8; i++) r += sh[i];
    return r;
}

// ------------------------- elementwise kernels -------------------------
__global__ __launch_bounds__(256)
void roundw_kernel(const float* __restrict__ s, f16* __restrict__ oh, int n4)
{
    const int i = blockIdx.x * 256 + threadIdx.x;
    if (i >= n4) return;
    float4 v = ((const float4*)s)[i];
    ((__half2*)oh)[2*i]   = __half2(__float2half_rn(v.x), __float2half_rn(v.y));
    ((__half2*)oh)[2*i+1] = __half2(__float2half_rn(v.z), __float2half_rn(v.w));
}

__global__ __launch_bounds__(256)
void roundw8_kernel(const float* p0, const float* p1, const float* p2, const float* p3,
                    const float* p4, const float* p5, const float* p6, const float* p7,
                    f16* __restrict__ oh, int n4)
{
    const int i = blockIdx.x * 256 + threadIdx.x;
    if (i >= n4) return;
    const int seg = blockIdx.y;
    const float* p;
    switch (seg) {
        case 0: p = p0; break; case 1: p = p1; break;
        case 2: p = p2; break; case 3: p = p3; break;
        case 4: p = p4; break; case 5: p = p5; break;
        case 6: p = p6; break; default: p = p7; break;
    }
    f16* o = oh + (ll)seg * H2;
    float4 v = ((const float4*)p)[i];
    ((__half2*)o)[2*i]   = __half2(__float2half_rn(v.x), __float2half_rn(v.y));
    ((__half2*)o)[2*i+1] = __half2(__float2half_rn(v.z), __float2half_rn(v.w));
}

__global__ __launch_bounds__(256)
void roundw3_kernel(const float* p0, const float* p1, const float* p2,
                    f16* __restrict__ oh, int n4)
{
    const int i = blockIdx.x * 256 + threadIdx.x;
    if (i >= n4) return;
    const int seg = blockIdx.y;
    const float* p = (seg == 0) ? p0 : (seg == 1 ? p1 : p2);
    f16* o = oh + (ll)seg * FF2;
    float4 v = ((const float4*)p)[i];
    ((__half2*)o)[2*i]   = __half2(__float2half_rn(v.x), __float2half_rn(v.y));
    ((__half2*)o)[2*i+1] = __half2(__float2half_rn(v.z), __float2half_rn(v.w));
}

__global__ __launch_bounds__(256)
void rmsnorm_round(const float* __restrict__ in, const float* __restrict__ w,
                   f16* __restrict__ oh)
{
    const ll base = (ll)blockIdx.x * HID;
    const float4* xin = (const float4*)(in + base);
    float ss = 0.f;
    for (int i = threadIdx.x; i < HID/4; i += 256) {
        float4 v = xin[i];
        ss += v.x*v.x + v.y*v.y + v.z*v.z + v.w*v.w;
    }
    ss = bsum(ss);
    const float r = rsqrtf(ss * (1.f/HID) + RMS_EPS);
    for (int i = threadIdx.x; i < HID/4; i += 256) {
        float4 v = xin[i];
        float4 ww = ((const float4*)w)[i];
        ((__half2*)(oh + base))[2*i]   = __half2(__float2half_rn(v.x*r*ww.x), __float2half_rn(v.y*r*ww.y));
        ((__half2*)(oh + base))[2*i+1] = __half2(__float2half_rn(v.z*r*ww.z), __float2half_rn(v.w*r*ww.w));
    }
}

// in-place rope over n rows (row & (SEQ-1) gives position; works for Q||K concat)
__global__ void rope_inplace(f16* __restrict__ t, int nrows)
{
    const int idx = blockIdx.x * blockDim.x + threadIdx.x;
    if (idx >= nrows * NHEAD * 64) return;
    const int j = idx & 63, h = (idx >> 6) & (NHEAD-1), row = idx >> 10;
    const int pos = row & (SEQ - 1);
    const float inv = (float)exp(-(double)(2*j) / (double)HDIM * log(10000.0));
    float s_, c;
    sincosf((float)pos * inv, &s_, &c);
    const ll p0 = (ll)row * HID + h * HDIM + j;
    const float q0 = __half2float(t[p0]), q1 = __half2float(t[p0 + 64]);
    t[p0]      = __float2half_rn(q0*c - q1*s_);
    t[p0+64]   = __float2half_rn(q1*c + q0*s_);
}

__global__ void vtrans_kernel(const f16* __restrict__ v, f16* __restrict__ oh)
{
    __shared__ f16 t[32][34];
    const int z = blockIdx.z, b = z >> 4, h = z & 15;
    const int s0 = blockIdx.x * 32, d0 = blockIdx.y * 32;
    const int tx = threadIdx.x, ty = threadIdx.y;
#pragma unroll
    for (int i = 0; i < 4; i++) {
        const int s = s0 + ty + i*8;
        t[ty + i*8][tx] = v[((ll)(b*SEQ + s)) * HID + h*HDIM + d0 + tx];
    }
    __syncthreads();
#pragma unroll
    for (int i = 0; i < 4; i++) {
        const int d = d0 + ty + i*8;
        oh[((ll)z * HDIM + d) * SEQ + s0 + tx] = t[tx][ty + i*8];
    }
}

__device__ __forceinline__ float sigm(float z) { return 1.f / (1.f + expf(-z)); }

__global__ void highway_kernel(const f16* __restrict__ gsrc, const f16* __restrict__ hsrc,
                               const float* __restrict__ bias, float* __restrict__ out, int n4)
{
    const int i = blockIdx.x * blockDim.x + threadIdx.x;
    if (i >= n4) return;
    __half2 g0 = ((const __half2*)gsrc)[2*i], g1 = ((const __half2*)gsrc)[2*i+1];
    __half2 h0 = ((const __half2*)hsrc)[2*i], h1 = ((const __half2*)hsrc)[2*i+1];
    float4 bv = ((const float4*)bias)[i & (HID/4 - 1)];
    ((float4*)out)[i] = make_float4(
        __half2float(h0.x)*sigm(__half2float(g0.x)+bv.x),
        __half2float(h0.y)*sigm(__half2float(g0.y)+bv.y),
        __half2float(h1.x)*sigm(__half2float(g1.x)+bv.z),
        __half2float(h1.y)*sigm(__half2float(g1.y)+bv.w));
}

// Fused: v = xm + mod + sigmoid(dg + bias)*dw ; x = v*(1 + r1*w_in) ;
//        hb = fp16(x * r2 * w_post) ; also store x (fp32).
__global__ __launch_bounds__(256)
void combine_fused(const float* __restrict__ xm, const f16* __restrict__ mod,
                   const f16* __restrict__ dw, const f16* __restrict__ dg,
                   const float* __restrict__ bias,
                   const float* __restrict__ w_in, const float* __restrict__ w_post,
                   float* __restrict__ xout, f16* __restrict__ hb)
{
    const ll base = (ll)blockIdx.x * HID;
    const int t = threadIdx.x;
    float v[8];
    float ss = 0.f;
#pragma unroll
    for (int u = 0; u < 2; u++) {
        const int i = t + u * 256;
        float4 xv = ((const float4*)(xm + base))[i];
        __half2 m0 = ((const __half2*)(mod + base))[2*i], m1 = ((const __half2*)(mod + base))[2*i+1];
        __half2 g0 = ((const __half2*)(dg + base))[2*i],  g1 = ((const __half2*)(dg + base))[2*i+1];
        __half2 h0 = ((const __half2*)(dw + base))[2*i],  h1 = ((const __half2*)(dw + base))[2*i+1];
        float4 bv = ((const float4*)bias)[i];
        v[u*4+0] = xv.x + __half2float(m0.x) + __half2float(h0.x)*sigm(__half2float(g0.x)+bv.x);
        v[u*4+1] = xv.y + __half2float(m0.y) + __half2float(h0.y)*sigm(__half2float(g0.y)+bv.y);
        v[u*4+2] = xv.z + __half2float(m1.x) + __half2float(h1.x)*sigm(__half2float(g1.x)+bv.z);
        v[u*4+3] = xv.w + __half2float(m1.y) + __half2float(h1.y)*sigm(__half2float(g1.y)+bv.w);
        ss += v[u*4+0]*v[u*4+0] + v[u*4+1]*v[u*4+1] + v[u*4+2]*v[u*4+2] + v[u*4+3]*v[u*4+3];
    }
    ss = bsum(ss);
    const float r1 = rsqrtf(ss * (1.f/HID) + RMS_EPS);
    float ss2 = 0.f;
#pragma unroll
    for (int u = 0; u < 2; u++) {
        const int i = t + u * 256;
        float4 wi = ((const float4*)w_in)[i];
        v[u*4+0] *= (1.f + r1*wi.x);
        v[u*4+1] *= (1.f + r1*wi.y);
        v[u*4+2] *= (1.f + r1*wi.z);
        v[u*4+3] *= (1.f + r1*wi.w);
        ss2 += v[u*4+0]*v[u*4+0] + v[u*4+1]*v[u*4+1] + v[u*4+2]*v[u*4+2] + v[u*4+3]*v[u*4+3];
        ((float4*)(xout + base))[i] = make_float4(v[u*4+0], v[u*4+1], v[u*4+2], v[u*4+3]);
    }
    ss2 = bsum(ss2);
    const float r2 = rsqrtf(ss2 * (1.f/HID) + RMS_EPS);
#pragma unroll
    for (int u = 0; u < 2; u++) {
        const int i = t + u * 256;
        float4 wp = ((const float4*)w_post)[i];
        ((__half2*)(hb + base))[2*i]   = __half2(__float2half_rn(v[u*4+0]*r2*wp.x),
                                                 __float2half_rn(v[u*4+1]*r2*wp.y));
        ((__half2*)(hb + base))[2*i+1] = __half2(__float2half_rn(v[u*4+2]*r2*wp.z),
                                                 __float2half_rn(v[u*4+3]*r2*wp.w));
    }
}

__global__ void silumul_round(const f16* __restrict__ g, const f16* __restrict__ u,
                              f16* __restrict__ oh, int n4)
{
    const int i = blockIdx.x * blockDim.x + threadIdx.x;
    if (i >= n4) return;
    __half2 g0 = ((const __half2*)g)[2*i], g1 = ((const __half2*)g)[2*i+1];
    __half2 u0 = ((const __half2*)u)[2*i], u1 = ((const __half2*)u)[2*i+1];
    float a = __half2float(g0.x), bq = __half2float(g0.y);
    float c = __half2float(g1.x), d = __half2float(g1.y);
    ((__half2*)oh)[2*i]   = __half2(__float2half_rn(a*sigm(a)*__half2float(u0.x)),
                                    __float2half_rn(bq*sigm(bq)*__half2float(u0.y)));
    ((__half2*)oh)[2*i+1] = __half2(__float2half_rn(c*sigm(c)*__half2float(u1.x)),
                                    __float2half_rn(d*sigm(d)*__half2float(u1.y)));
}

// ------------------------- launch -------------------------
extern "C" void kernel_launch(void* const* d_in, const int* in_sizes, int n_in,
                              void* d_out, int out_size)
{
    const float* x_mod = (const float*)d_in[0];
    const float* x_back= (const float*)d_in[1];
    const float* mask  = (const float*)d_in[2];
    const float* wq = (const float*)d_in[3];
    const float* wk = (const float*)d_in[4];
    const float* wv = (const float*)d_in[5];
    const float* wo = (const float*)d_in[6];
    const float* cross_ln_w = (const float*)d_in[7];
    const float* fb_w = (const float*)d_in[8];
    const float* fb_g = (const float*)d_in[9];
    const float* fb_gb= (const float*)d_in[10];
    const float* dr_w = (const float*)d_in[11];
    const float* dr_g = (const float*)d_in[12];
    const float* dr_gb= (const float*)d_in[13];
    const float* in_ln_w   = (const float*)d_in[14];
    const float* post_ln_w = (const float*)d_in[15];
    const float* w_gate = (const float*)d_in[16];
    const float* w_up   = (const float*)d_in[17];
    const float* w_down = (const float*)d_in[18];

    float* outx = (float*)d_out;
    float* outd = outx + (size_t)ROWS * HID;

    float *x;
    f16 *wh,*ah,*modh,*t12,*gu;
    cudaGetSymbolAddress((void**)&x, g_x);
    cudaGetSymbolAddress((void**)&wh, g_wh);
    cudaGetSymbolAddress((void**)&ah, g_ah);
    cudaGetSymbolAddress((void**)&modh, g_modh);
    cudaGetSymbolAddress((void**)&t12, g_t12);
    cudaGetSymbolAddress((void**)&gu, g_gu);

    cudaFuncSetAttribute(mma_gemm<float>, cudaFuncAttributeMaxDynamicSharedMemorySize, TC_SMEM);
    cudaFuncSetAttribute(mma_gemm<f16>,   cudaFuncAttributeMaxDynamicSharedMemorySize, TC_SMEM);
    cudaFuncSetAttribute(flash_attn,      cudaFuncAttributeMaxDynamicSharedMemorySize, FA_SMEM);

    const int n4h = (int)(RH/4), n4f = (int)(GGN/4), n4w = (int)(H2/4), n4ff = (int)(FF2/4);
    const dim3 B256(256);

    auto gemmH = [&](const f16* pa, const f16* pb, f16* c,
                     int M, int N, int K, int lda, int ldb, int ldc,
                     int gz, int zdiv, ll saa, ll sab, ll sba, ll sbb, ll sca, ll scb) {
        dim3 g(N/128, M/128, gz);
        mma_gemm<f16><<<g, 256, TC_SMEM>>>(pa, pb, c, nullptr, K, lda, ldb, ldc, zdiv,
                                           saa, sab, sba, sbb, sca, scb);
    };
    auto gemmFA = [&](const f16* pa, const f16* pb, float* c, const float* add,
                      int M, int N, int K, int lda, int ldb, int ldc) {
        dim3 g(N/128, M/128, 1);
        mma_gemm<float><<<g, 256, TC_SMEM>>>(pa, pb, c, add, K, lda, ldb, ldc, 1, 0,0,0,0,0,0);
    };

    // ---- rounds (merged) ----
    roundw_kernel<<<n4h/256, B256>>>(x_back, ah+OXB, n4h);
    roundw_kernel<<<n4h/256, B256>>>(x_mod,  ah+OXM, n4h);
    rmsnorm_round<<<ROWS, B256>>>(x_mod, cross_ln_w, ah+OQN);
    roundw8_kernel<<<dim3(n4w/256, 8), B256>>>(wq, wk, wv, wo, fb_w, fb_g, dr_w, dr_g, wh, n4w);
    roundw3_kernel<<<dim3(n4ff/256, 3), B256>>>(w_gate, w_up, w_down, wh+OWG, n4ff);

    // ---- z=3 merged q+k+v GEMM (zdiv=2):
    //   z0: A=OXB,     B=OWK,      C=OK2       (k)
    //   z1: A=OXB,     B=OWK+H2,   C=OK2+2RH   (v -> OATT temp)
    //   z2: A=OXB-RH,  B=OWK-H2,   C=OK2-RH    (q: A=OQN, B=OWQ, C=OQ)
    gemmH(ah+OXB, wh+OWK, ah+OK2, ROWS, HID, HID, HID, HID, HID,
          3, 2, -(ll)RH, 0, -(ll)H2, H2, -(ll)RH, 2*RH);

    // ---- z=4 merged highway GEMM ----
    gemmH(ah+OXM, wh+OFBW, t12, ROWS, HID, HID, HID, HID, HID,
          4, 2, -(ll)RH, 0, 2*H2, H2, 2*RH, RH);
    highway_kernel<<<n4h/256, B256>>>(t12+RH, t12, fb_gb, outd, n4h);

    // ---- single rope over Q||K (contiguous), then V transpose ----
    const int ropeN2 = 2 * ROWS * NHEAD * 64;
    rope_inplace<<<(ropeN2+255)/256, B256>>>(ah+OQ, 2*ROWS);
    vtrans_kernel<<<dim3(SEQ/32, HDIM/32, BATCH*NHEAD), dim3(32,8)>>>(ah+OATT, ah+OVT);

    // ---- flash attention -> OATT, then WO ----
    flash_attn<<<dim3(SEQ/128, BATCH*NHEAD), B256, FA_SMEM>>>(
        ah+OQ, ah+OK2, ah+OVT, mask, ah+OATT);
    gemmH(ah+OATT, wh+OWO, modh, ROWS, HID, HID, HID, HID, HID, 1, 1, 0,0, 0,0, 0,0);

    // ---- fused combine + rmsadd + rmsnorm ----
    combine_fused<<<ROWS, B256>>>(x_mod, modh, t12+2*RH, t12+3*RH, dr_gb,
                                  in_ln_w, post_ln_w, x, ah+OHB);

    // ---- MLP: gate/up merged; down-GEMM fuses residual add -> outx ----
    gemmH(ah+OHB, wh+OWG, gu, ROWS, FFD, HID, HID, HID, FFD, 2, 1, 0,0, FF2,0, GGN,0);
    silumul_round<<<n4f/256, B256>>>(gu, gu+GGN, ah+OGG, n4f);
    gemmFA(ah+OGG, wh+OWD, outx, x, ROWS, HID, FFD, FFD, FFD, HID);
}

// round 17
// speedup vs baseline: 2.4122x; 1.0140x over previous
#include <cuda_runtime.h>
#include <cuda_fp16.h>
#include <cstdint>
#include <math.h>
using f16 = __half;
typedef long long ll;

#define BATCH 2
#define SEQ 2048
#define HID 2048
#define NHEAD 16
#define HDIM 128
#define FFD 8192
#define ROWS 4096
#define RMS_EPS 1e-5f
#define RH 8388608LL
#define H2 4194304LL
#define FF2 16777216LL
#define GGN 33554432LL

// ------------------------- scratch -------------------------
__device__ float g_x[RH];
__device__ f16 g_wh[8*H2+3*FF2];
__device__ f16 g_ah[8*RH+GGN];
__device__ f16 g_modh[RH];
__device__ f16 g_t12[4*RH];
__device__ f16 g_gu[2*GGN];

#define OWQ  (0*H2)
#define OWK  (1*H2)
#define OWV  (2*H2)
#define OWO  (3*H2)
#define OFBW (4*H2)
#define OFBG (5*H2)
#define ODRW (6*H2)
#define ODRG (7*H2)
#define OWG  (8*H2)
#define OWU  (8*H2+FF2)
#define OWD  (8*H2+2*FF2)
#define OQN  (0*RH)
#define OXB  (1*RH)
#define OXM  (2*RH)
#define OQ   (3*RH)
#define OK2  (4*RH)
#define OVT  (5*RH)
#define OATT (6*RH)
#define OHB  (7*RH)
#define OGG  (8*RH)

// ------------------------- PTX helpers -------------------------
__device__ __forceinline__ uint32_t smem_u32(const void* p) {
    uint32_t a;
    asm("{ .reg .u64 t; cvta.to.shared.u64 t, %1; cvt.u32.u64 %0, t; }" : "=r"(a) : "l"(p));
    return a;
}
__device__ __forceinline__ void cp16(uint32_t s, const void* g) {
    asm volatile("cp.async.cg.shared.global [%0], [%1], 16;" :: "r"(s), "l"(g));
}
__device__ __forceinline__ void cpcommit() { asm volatile("cp.async.commit_group;" ::: "memory"); }
__device__ __forceinline__ void cpwait0()  { asm volatile("cp.async.wait_group 0;" ::: "memory"); }
__device__ __forceinline__ void cpwait1()  { asm volatile("cp.async.wait_group 1;" ::: "memory"); }

__device__ __forceinline__ void ldsm4(uint32_t* r, uint32_t addr) {
    asm volatile("ldmatrix.sync.aligned.m8n8.x4.shared.b16 {%0,%1,%2,%3}, [%4];"
        : "=r"(r[0]), "=r"(r[1]), "=r"(r[2]), "=r"(r[3]) : "r"(addr));
}
__device__ __forceinline__ void mma16816(float* c, const uint32_t* a, uint32_t b0, uint32_t b1) {
    asm volatile("mma.sync.aligned.m16n8k16.row.col.f32.f16.f16.f32 "
        "{%0,%1,%2,%3}, {%4,%5,%6,%7}, {%8,%9}, {%0,%1,%2,%3};"
        : "+f"(c[0]), "+f"(c[1]), "+f"(c[2]), "+f"(c[3])
        : "r"(a[0]), "r"(a[1]), "r"(a[2]), "r"(a[3]), "r"(b0), "r"(b1));
}

// ---------------------------------------------------------------------------
// fp16 HMMA GEMM (templated output). C = A @ B^T [+ addsrc if float out].
// ---------------------------------------------------------------------------
#define STG 16384
#define TC_SMEM (3*STG)

template<typename OT>
__global__ __launch_bounds__(256, 2)
void mma_gemm(const f16* __restrict__ Ahg, const f16* __restrict__ Bhg,
              OT* __restrict__ Cg, const float* __restrict__ addsrc,
              int K, int lda, int ldb, int ldc, int zdiv,
              ll sAa, ll sAb, ll sBa, ll sBb, ll sCa, ll sCb)
{
    extern __shared__ char smem_raw[];
    const uint32_t tiles = smem_u32(smem_raw);
    const int tid = threadIdx.x, wid = tid >> 5, lane = tid & 31;
    const int wm = wid & 3, wn = wid >> 2;

    const int z = blockIdx.z;
    const f16* Ah = Ahg + (ll)(z / zdiv) * sAa + (ll)(z % zdiv) * sAb;
    const f16* Bh = Bhg + (ll)(z / zdiv) * sBa + (ll)(z % zdiv) * sBb;
    OT* C = Cg + (ll)(z / zdiv) * sCa + (ll)(z % zdiv) * sCb;

    const int bm = blockIdx.y << 7, bn = blockIdx.x << 7;
    const int nk = K >> 5;

    auto load_stage = [&](int kt) {
        const uint32_t st = tiles + (uint32_t)(kt % 3) * STG;
        const ll kb = (ll)kt * 32;
#pragma unroll
        for (int i = tid; i < 512; i += 256) {
            const int r = i >> 2, c = i & 3;
            const uint32_t sw = (uint32_t)r * 64u + (uint32_t)((c ^ ((r >> 1) & 3)) << 4);
            cp16(st        + sw, Ah + (ll)(bm + r) * lda + kb + c * 8);
            cp16(st + 8192 + sw, Bh + (ll)(bn + r) * ldb + kb + c * 8);
        }
        cpcommit();
    };

    float acc[2][8][4];
#pragma unroll
    for (int i = 0; i < 2; i++)
#pragma unroll
        for (int j = 0; j < 8; j++)
#pragma unroll
            for (int t = 0; t < 4; t++) acc[i][j][t] = 0.f;

    const int aRow  = wm * 32 + (lane & 15);
    const int aCpar = lane >> 4;
    const int bNadd = ((lane >> 4) << 3) + (lane & 7);
    const int bCpar = (lane >> 3) & 1;

    load_stage(0);
    if (nk > 1) load_stage(1); else cpcommit();

    for (int kt = 0; kt < nk; kt++) {
        if (kt >= nk - 2) cpwait0(); else cpwait1();
        __syncthreads();
        if (kt + 2 < nk) load_stage(kt + 2); else cpcommit();

        const uint32_t st = tiles + (uint32_t)(kt % 3) * STG;
#pragma unroll
        for (int ks = 0; ks < 2; ks++) {
            uint32_t ahf[2][4];
#pragma unroll
            for (int mt = 0; mt < 2; mt++) {
                const int row = aRow + mt * 16;
                const int ch = ks * 2 + aCpar;
                const uint32_t ad = st + (uint32_t)row * 64u + (uint32_t)((ch ^ ((row >> 1) & 3)) << 4);
                ldsm4(ahf[mt], ad);
            }
#pragma unroll
            for (int np = 0; np < 2; np++) {
                uint32_t bh[2][4];
#pragma unroll
                for (int t = 0; t < 2; t++) {
                    const int nt = np * 2 + t;
                    const int row = wn * 64 + nt * 16 + bNadd;
                    const int ch = ks * 2 + bCpar;
                    const uint32_t bd = st + 8192u + (uint32_t)row * 64u + (uint32_t)((ch ^ ((row >> 1) & 3)) << 4);
                    ldsm4(bh[t], bd);
                }
#pragma unroll
                for (int t = 0; t < 2; t++) {
                    const int nb = (np * 2 + t) * 2;
                    mma16816(acc[0][nb],   ahf[0], bh[t][0], bh[t][1]);
                    mma16816(acc[0][nb+1], ahf[0], bh[t][2], bh[t][3]);
                    mma16816(acc[1][nb],   ahf[1], bh[t][0], bh[t][1]);
                    mma16816(acc[1][nb+1], ahf[1], bh[t][2], bh[t][3]);
                }
            }
        }
    }

    const int erow = bm + wm * 32 + (lane >> 2);
    const int ecol = bn + wn * 64 + (lane & 3) * 2;
#pragma unroll
    for (int mt = 0; mt < 2; mt++) {
#pragma unroll
        for (int j = 0; j < 8; j++) {
            const ll o0 = (ll)(erow + mt*16)     * ldc + ecol + j*8;
            const ll o1 = (ll)(erow + mt*16 + 8) * ldc + ecol + j*8;
            if constexpr (sizeof(OT) == 4) {
                float2 a0 = make_float2(0.f, 0.f), a1 = make_float2(0.f, 0.f);
                if (addsrc) {
                    a0 = *(const float2*)(addsrc + o0);
                    a1 = *(const float2*)(addsrc + o1);
                }
                *(float2*)(C + o0) = make_float2(acc[mt][j][0] + a0.x, acc[mt][j][1] + a0.y);
                *(float2*)(C + o1) = make_float2(acc[mt][j][2] + a1.x, acc[mt][j][3] + a1.y);
            } else {
                __half2 h0(__float2half_rn(acc[mt][j][0]), __float2half_rn(acc[mt][j][1]));
                __half2 h1(__float2half_rn(acc[mt][j][2]), __float2half_rn(acc[mt][j][3]));
                *(__half2*)(C + o0) = h0;
                *(__half2*)(C + o1) = h1;
            }
        }
    }
}

// ---------------------------------------------------------------------------
// Flash attention (fp16): CTA = 128 q-rows x 1 head. smem 96KB, 2 CTAs/SM.
// ---------------------------------------------------------------------------
#define FA_SMEM 98304
#define FA_SCALE 0.08838834764831845f

__global__ __launch_bounds__(256, 2)
void flash_attn(const f16* __restrict__ qh, const f16* __restrict__ kh,
                const f16* __restrict__ vth, const float* __restrict__ mask,
                f16* __restrict__ oh)
{
    extern __shared__ char smem_raw[];
    const uint32_t sQ = smem_u32(smem_raw);
    const uint32_t sKV = sQ + 32768;
    const int tid = threadIdx.x, w = tid >> 5, lane = tid & 31;

    const int qt = blockIdx.x;
    const int z  = blockIdx.y;
    const int b  = z >> 4, h = z & 15;
    const int bS = b * SEQ;

    {
        const ll base = (ll)(bS + qt*128) * HID + h*128;
#pragma unroll
        for (int i = tid; i < 2048; i += 256) {
            const int r = i >> 4, c = i & 15;
            const uint32_t sw = (uint32_t)r*256u + (uint32_t)((c ^ (r & 15)) << 4);
            cp16(sQ + sw, qh + base + (ll)r * HID + c * 8);
        }
    }
    auto load_kv = [&](int kt) {
        const uint32_t st = sKV + (uint32_t)(kt & 1) * 32768;
        const ll kbase = (ll)(bS + kt*64) * HID + h*128;
#pragma unroll
        for (int i = tid; i < 1024; i += 256) {
            const int r = i >> 4, c = i & 15;
            const uint32_t sw = (uint32_t)r*256u + (uint32_t)((c ^ (r & 15)) << 4);
            cp16(st + sw, kh + kbase + (ll)r * HID + c * 8);
        }
        const ll vbase = (ll)z * 128 * SEQ + kt*64;
#pragma unroll
        for (int i = tid; i < 1024; i += 256) {
            const int r = i >> 3, c = i & 7;
            const uint32_t sw = (uint32_t)r*128u + (uint32_t)((c ^ (r & 7)) << 4);
            cp16(st + 16384 + sw, vth + vbase + (ll)r * SEQ + c * 8);
        }
        cpcommit();
    };

    float oacc[16][4];
#pragma unroll
    for (int i = 0; i < 16; i++)
#pragma unroll
        for (int t = 0; t < 4; t++) oacc[i][t] = 0.f;
    float m1 = -1e30f, m2 = -1e30f, l1 = 0.f, l2 = 0.f;

    const int aCpar = lane >> 4;
    const int bNadd = ((lane >> 4) << 3) + (lane & 7);
    const int bCpar = (lane >> 3) & 1;
    const int qRow  = w * 16 + (lane & 15);
    const int qpos1 = qt*128 + w*16 + (lane >> 2);
    const int colq  = (lane & 3) * 2;

    load_kv(0);
    const int NKT = SEQ / 64;

    for (int kt = 0; kt < NKT; kt++) {
        if (kt + 1 < NKT) { load_kv(kt + 1); cpwait1(); } else { cpwait0(); }
        __syncthreads();
        const uint32_t st = sKV + (uint32_t)(kt & 1) * 32768;

        float sacc[8][4];
#pragma unroll
        for (int j = 0; j < 8; j++)
#pragma unroll
            for (int t = 0; t < 4; t++) sacc[j][t] = 0.f;

#pragma unroll
        for (int ks = 0; ks < 8; ks++) {
            uint32_t ahf[4];
            {
                const int ch = ks*2 + aCpar;
                const uint32_t ad = sQ + (uint32_t)qRow*256u + (uint32_t)((ch ^ (qRow & 15)) << 4);
                ldsm4(ahf, ad);
            }
#pragma unroll
            for (int nt = 0; nt < 4; nt++) {
                const int row = nt*16 + bNadd;
                const int ch = ks*2 + bCpar;
                const uint32_t bd = st + (uint32_t)row*256u + (uint32_t)((ch ^ (row & 15)) << 4);
                uint32_t bh[4];
                ldsm4(bh, bd);
                mma16816(sacc[nt*2],   ahf, bh[0], bh[1]);
                mma16816(sacc[nt*2+1], ahf, bh[2], bh[3]);
            }
        }

        const int kbase = kt*64;
#pragma unroll
        for (int j = 0; j < 8; j++) {
            const int kposg = kbase + j*8 + colq;
            float2 mA = *(const float2*)(mask + (ll)qpos1 * SEQ + kposg);
            float2 mB = *(const float2*)(mask + (ll)(qpos1 + 8) * SEQ + kposg);
            sacc[j][0] = sacc[j][0]*FA_SCALE + mA.x;
            sacc[j][1] = sacc[j][1]*FA_SCALE + mA.y;
            sacc[j][2] = sacc[j][2]*FA_SCALE + mB.x;
            sacc[j][3] = sacc[j][3]*FA_SCALE + mB.y;
        }
        float mx1 = -1e30f, mx2 = -1e30f;
#pragma unroll
        for (int j = 0; j < 8; j++) {
            mx1 = fmaxf(mx1, fmaxf(sacc[j][0], sacc[j][1]));
            mx2 = fmaxf(mx2, fmaxf(sacc[j][2], sacc[j][3]));
        }
        mx1 = fmaxf(mx1, __shfl_xor_sync(0xffffffffu, mx1, 1));
        mx1 = fmaxf(mx1, __shfl_xor_sync(0xffffffffu, mx1, 2));
        mx2 = fmaxf(mx2, __shfl_xor_sync(0xffffffffu, mx2, 1));
        mx2 = fmaxf(mx2, __shfl_xor_sync(0xffffffffu, mx2, 2));
        const float nm1 = fmaxf(m1, mx1), nm2 = fmaxf(m2, mx2);
        const float al1 = __expf(m1 - nm1), al2 = __expf(m2 - nm2);
        m1 = nm1; m2 = nm2;
        float s1 = 0.f, s2 = 0.f;
#pragma unroll
        for (int j = 0; j < 8; j++) {
            sacc[j][0] = __expf(sacc[j][0] - nm1);
            sacc[j][1] = __expf(sacc[j][1] - nm1);
            sacc[j][2] = __expf(sacc[j][2] - nm2);
            sacc[j][3] = __expf(sacc[j][3] - nm2);
            s1 += sacc[j][0] + sacc[j][1];
            s2 += sacc[j][2] + sacc[j][3];
        }
        s1 += __shfl_xor_sync(0xffffffffu, s1, 1);
        s1 += __shfl_xor_sync(0xffffffffu, s1, 2);
        s2 += __shfl_xor_sync(0xffffffffu, s2, 1);
        s2 += __shfl_xor_sync(0xffffffffu, s2, 2);
        l1 = l1*al1 + s1;
        l2 = l2*al2 + s2;
#pragma unroll
        for (int i = 0; i < 16; i++) {
            oacc[i][0] *= al1; oacc[i][1] *= al1;
            oacc[i][2] *= al2; oacc[i][3] *= al2;
        }

#pragma unroll
        for (int kk = 0; kk < 4; kk++) {
            uint32_t pah[4];
            {
                __half2 t0(__float2half_rn(sacc[2*kk][0]),   __float2half_rn(sacc[2*kk][1]));
                __half2 t1(__float2half_rn(sacc[2*kk][2]),   __float2half_rn(sacc[2*kk][3]));
                __half2 t2(__float2half_rn(sacc[2*kk+1][0]), __float2half_rn(sacc[2*kk+1][1]));
                __half2 t3(__float2half_rn(sacc[2*kk+1][2]), __float2half_rn(sacc[2*kk+1][3]));
                pah[0] = *(uint32_t*)&t0; pah[1] = *(uint32_t*)&t1;
                pah[2] = *(uint32_t*)&t2; pah[3] = *(uint32_t*)&t3;
            }
#pragma unroll
            for (int nt = 0; nt < 8; nt++) {
                const int row = nt*16 + bNadd;
                const int ch = kk*2 + bCpar;
                const uint32_t bd = st + 16384u + (uint32_t)row*128u + (uint32_t)((ch ^ (row & 7)) << 4);
                uint32_t bh[4];
                ldsm4(bh, bd);
                mma16816(oacc[nt*2],   pah, bh[0], bh[1]);
                mma16816(oacc[nt*2+1], pah, bh[2], bh[3]);
            }
        }
        __syncthreads();
    }

    const float inv1 = 1.f / l1, inv2 = 1.f / l2;
    const ll row1 = (ll)(bS + qpos1);
#pragma unroll
    for (int nt = 0; nt < 16; nt++) {
        const int col = h*128 + nt*8 + colq;
        __half2 th(__float2half_rn(oacc[nt][0]*inv1), __float2half_rn(oacc[nt][1]*inv1));
        __half2 uh(__float2half_rn(oacc[nt][2]*inv2), __float2half_rn(oacc[nt][3]*inv2));
        *(__half2*)(oh + row1*HID + col)     = th;
        *(__half2*)(oh + (row1+8)*HID + col) = uh;
    }
}

// ------------------------- reductions -------------------------
__device__ __forceinline__ float wsum(float v) {
#pragma unroll
    for (int o = 16; o; o >>= 1) v += __shfl_xor_sync(0xffffffffu, v, o);
    return v;
}
__device__ __forceinline__ float bsum(float v) {
    __shared__ float sh[8];
    v = wsum(v); __syncthreads();
    if ((threadIdx.x & 31) == 0) sh[threadIdx.x >> 5] = v;
    __syncthreads();
    float r = 0.f;
#pragma unroll
    for (int i = 0; i < 8; i++) r += sh[i];
    return r;
}

// ------------------------- elementwise kernels -------------------------
__global__ __launch_bounds__(256)
void roundw_kernel(const float* __restrict__ s, f16* __restrict__ oh, int n4)
{
    const int i = blockIdx.x * 256 + threadIdx.x;
    if (i >= n4) return;
    float4 v = ((const float4*)s)[i];
    ((__half2*)oh)[2*i]   = __half2(__float2half_rn(v.x), __float2half_rn(v.y));
    ((__half2*)oh)[2*i+1] = __half2(__float2half_rn(v.z), __float2half_rn(v.w));
}

__global__ __launch_bounds__(256)
void roundw8_kernel(const float* p0, const float* p1, const float* p2, const float* p3,
                    const float* p4, const float* p5, const float* p6, const float* p7,
                    f16* __restrict__ oh, int n4)
{
    const int i = blockIdx.x * 256 + threadIdx.x;
    if (i >= n4) return;
    const int seg = blockIdx.y;
    const float* p;
    switch (seg) {
        case 0: p = p0; break; case 1: p = p1; break;
        case 2: p = p2; break; case 3: p = p3; break;
        case 4: p = p4; break; case 5: p = p5; break;
        case 6: p = p6; break; default: p = p7; break;
    }
    f16* o = oh + (ll)seg * H2;
    float4 v = ((const float4*)p)[i];
    ((__half2*)o)[2*i]   = __half2(__float2half_rn(v.x), __float2half_rn(v.y));
    ((__half2*)o)[2*i+1] = __half2(__float2half_rn(v.z), __float2half_rn(v.w));
}

__global__ __launch_bounds__(256)
void roundw3_kernel(const float* p0, const float* p1, const float* p2,
                    f16* __restrict__ oh, int n4)
{
    const int i = blockIdx.x * 256 + threadIdx.x;
    if (i >= n4) return;
    const int seg = blockIdx.y;
    const float* p = (seg == 0) ? p0 : (seg == 1 ? p1 : p2);
    f16* o = oh + (ll)seg * FF2;
    float4 v = ((const float4*)p)[i];
    ((__half2*)o)[2*i]   = __half2(__float2half_rn(v.x), __float2half_rn(v.y));
    ((__half2*)o)[2*i+1] = __half2(__float2half_rn(v.z), __float2half_rn(v.w));
}

// reads x_mod once: writes fp16 round (OXM) and rmsnorm'd round (OQN)
__global__ __launch_bounds__(256)
void xmod_dual(const float* __restrict__ in, const float* __restrict__ w,
               f16* __restrict__ oround, f16* __restrict__ onorm)
{
    const ll base = (ll)blockIdx.x * HID;
    const float4* xin = (const float4*)(in + base);
    float ss = 0.f;
    for (int i = threadIdx.x; i < HID/4; i += 256) {
        float4 v = xin[i];
        ss += v.x*v.x + v.y*v.y + v.z*v.z + v.w*v.w;
        ((__half2*)(oround + base))[2*i]   = __half2(__float2half_rn(v.x), __float2half_rn(v.y));
        ((__half2*)(oround + base))[2*i+1] = __half2(__float2half_rn(v.z), __float2half_rn(v.w));
    }
    ss = bsum(ss);
    const float r = rsqrtf(ss * (1.f/HID) + RMS_EPS);
    for (int i = threadIdx.x; i < HID/4; i += 256) {
        float4 v = xin[i];
        float4 ww = ((const float4*)w)[i];
        ((__half2*)(onorm + base))[2*i]   = __half2(__float2half_rn(v.x*r*ww.x), __float2half_rn(v.y*r*ww.y));
        ((__half2*)(onorm + base))[2*i+1] = __half2(__float2half_rn(v.z*r*ww.z), __float2half_rn(v.w*r*ww.w));
    }
}

__global__ void rope_inplace(f16* __restrict__ t, int nrows)
{
    const int idx = blockIdx.x * blockDim.x + threadIdx.x;
    if (idx >= nrows * NHEAD * 64) return;
    const int j = idx & 63, h = (idx >> 6) & (NHEAD-1), row = idx >> 10;
    const int pos = row & (SEQ - 1);
    const float inv = (float)exp(-(double)(2*j) / (double)HDIM * log(10000.0));
    float s_, c;
    sincosf((float)pos * inv, &s_, &c);
    const ll p0 = (ll)row * HID + h * HDIM + j;
    const float q0 = __half2float(t[p0]), q1 = __half2float(t[p0 + 64]);
    t[p0]      = __float2half_rn(q0*c - q1*s_);
    t[p0+64]   = __float2half_rn(q1*c + q0*s_);
}

__global__ void vtrans_kernel(const f16* __restrict__ v, f16* __restrict__ oh)
{
    __shared__ f16 t[32][34];
    const int z = blockIdx.z, b = z >> 4, h = z & 15;
    const int s0 = blockIdx.x * 32, d0 = blockIdx.y * 32;
    const int tx = threadIdx.x, ty = threadIdx.y;
#pragma unroll
    for (int i = 0; i < 4; i++) {
        const int s = s0 + ty + i*8;
        t[ty + i*8][tx] = v[((ll)(b*SEQ + s)) * HID + h*HDIM + d0 + tx];
    }
    __syncthreads();
#pragma unroll
    for (int i = 0; i < 4; i++) {
        const int d = d0 + ty + i*8;
        oh[((ll)z * HDIM + d) * SEQ + s0 + tx] = t[tx][ty + i*8];
    }
}

__device__ __forceinline__ float sigm(float z) { return 1.f / (1.f + expf(-z)); }

__global__ void highway_kernel(const f16* __restrict__ gsrc, const f16* __restrict__ hsrc,
                               const float* __restrict__ bias, float* __restrict__ out, int n4)
{
    const int i = blockIdx.x * blockDim.x + threadIdx.x;
    if (i >= n4) return;
    __half2 g0 = ((const __half2*)gsrc)[2*i], g1 = ((const __half2*)gsrc)[2*i+1];
    __half2 h0 = ((const __half2*)hsrc)[2*i], h1 = ((const __half2*)hsrc)[2*i+1];
    float4 bv = ((const float4*)bias)[i & (HID/4 - 1)];
    ((float4*)out)[i] = make_float4(
        __half2float(h0.x)*sigm(__half2float(g0.x)+bv.x),
        __half2float(h0.y)*sigm(__half2float(g0.y)+bv.y),
        __half2float(h1.x)*sigm(__half2float(g1.x)+bv.z),
        __half2float(h1.y)*sigm(__half2float(g1.y)+bv.w));
}

__global__ __launch_bounds__(256)
void combine_fused(const float* __restrict__ xm, const f16* __restrict__ mod,
                   const f16* __restrict__ dw, const f16* __restrict__ dg,
                   const float* __restrict__ bias,
                   const float* __restrict__ w_in, const float* __restrict__ w_post,
                   float* __restrict__ xout, f16* __restrict__ hb)
{
    const ll base = (ll)blockIdx.x * HID;
    const int t = threadIdx.x;
    float v[8];
    float ss = 0.f;
#pragma unroll
    for (int u = 0; u < 2; u++) {
        const int i = t + u * 256;
        float4 xv = ((const float4*)(xm + base))[i];
        __half2 m0 = ((const __half2*)(mod + base))[2*i], m1 = ((const __half2*)(mod + base))[2*i+1];
        __half2 g0 = ((const __half2*)(dg + base))[2*i],  g1 = ((const __half2*)(dg + base))[2*i+1];
        __half2 h0 = ((const __half2*)(dw + base))[2*i],  h1 = ((const __half2*)(dw + base))[2*i+1];
        float4 bv = ((const float4*)bias)[i];
        v[u*4+0] = xv.x + __half2float(m0.x) + __half2float(h0.x)*sigm(__half2float(g0.x)+bv.x);
        v[u*4+1] = xv.y + __half2float(m0.y) + __half2float(h0.y)*sigm(__half2float(g0.y)+bv.y);
        v[u*4+2] = xv.z + __half2float(m1.x) + __half2float(h1.x)*sigm(__half2float(g1.x)+bv.z);
        v[u*4+3] = xv.w + __half2float(m1.y) + __half2float(h1.y)*sigm(__half2float(g1.y)+bv.w);
        ss += v[u*4+0]*v[u*4+0] + v[u*4+1]*v[u*4+1] + v[u*4+2]*v[u*4+2] + v[u*4+3]*v[u*4+3];
    }
    ss = bsum(ss);
    const float r1 = rsqrtf(ss * (1.f/HID) + RMS_EPS);
    float ss2 = 0.f;
#pragma unroll
    for (int u = 0; u < 2; u++) {
        const int i = t + u * 256;
        float4 wi = ((const float4*)w_in)[i];
        v[u*4+0] *= (1.f + r1*wi.x);
        v[u*4+1] *= (1.f + r1*wi.y);
        v[u*4+2] *= (1.f + r1*wi.z);
        v[u*4+3] *= (1.f + r1*wi.w);
        ss2 += v[u*4+0]*v[u*4+0] + v[u*4+1]*v[u*4+1] + v[u*4+2]*v[u*4+2] + v[u*4+3]*v[u*4+3];
        ((float4*)(xout + base))[i] = make_float4(v[u*4+0], v[u*4+1], v[u*4+2], v[u*4+3]);
    }
    ss2 = bsum(ss2);
    const float r2 = rsqrtf(ss2 * (1.f/HID) + RMS_EPS);
#pragma unroll
    for (int u = 0; u < 2; u++) {
        const int i = t + u * 256;
        float4 wp = ((const float4*)w_post)[i];
        ((__half2*)(hb + base))[2*i]   = __half2(__float2half_rn(v[u*4+0]*r2*wp.x),
                                                 __float2half_rn(v[u*4+1]*r2*wp.y));
        ((__half2*)(hb + base))[2*i+1] = __half2(__float2half_rn(v[u*4+2]*r2*wp.z),
                                                 __float2half_rn(v[u*4+3]*r2*wp.w));
    }
}

__global__ void silumul_round(const f16* __restrict__ g, const f16* __restrict__ u,
                              f16* __restrict__ oh, int n4)
{
    const int i = blockIdx.x * blockDim.x + threadIdx.x;
    if (i >= n4) return;
    __half2 g0 = ((const __half2*)g)[2*i], g1 = ((const __half2*)g)[2*i+1];
    __half2 u0 = ((const __half2*)u)[2*i], u1 = ((const __half2*)u)[2*i+1];
    float a = __half2float(g0.x), bq = __half2float(g0.y);
    float c = __half2float(g1.x), d = __half2float(g1.y);
    ((__half2*)oh)[2*i]   = __half2(__float2half_rn(a*sigm(a)*__half2float(u0.x)),
                                    __float2half_rn(bq*sigm(bq)*__half2float(u0.y)));
    ((__half2*)oh)[2*i+1] = __half2(__float2half_rn(c*sigm(c)*__half2float(u1.x)),
                                    __float2half_rn(d*sigm(d)*__half2float(u1.y)));
}

// ------------------------- launch -------------------------
extern "C" void kernel_launch(void* const* d_in, const int* in_sizes, int n_in,
                              void* d_out, int out_size)
{
    const float* x_mod = (const float*)d_in[0];
    const float* x_back= (const float*)d_in[1];
    const float* mask  = (const float*)d_in[2];
    const float* wq = (const float*)d_in[3];
    const float* wk = (const float*)d_in[4];
    const float* wv = (const float*)d_in[5];
    const float* wo = (const float*)d_in[6];
    const float* cross_ln_w = (const float*)d_in[7];
    const float* fb_w = (const float*)d_in[8];
    const float* fb_g = (const float*)d_in[9];
    const float* fb_gb= (const float*)d_in[10];
    const float* dr_w = (const float*)d_in[11];
    const float* dr_g = (const float*)d_in[12];
    const float* dr_gb= (const float*)d_in[13];
    const float* in_ln_w   = (const float*)d_in[14];
    const float* post_ln_w = (const float*)d_in[15];
    const float* w_gate = (const float*)d_in[16];
    const float* w_up   = (const float*)d_in[17];
    const float* w_down = (const float*)d_in[18];

    float* outx = (float*)d_out;
    float* outd = outx + (size_t)ROWS * HID;

    float *x;
    f16 *wh,*ah,*modh,*t12,*gu;
    cudaGetSymbolAddress((void**)&x, g_x);
    cudaGetSymbolAddress((void**)&wh, g_wh);
    cudaGetSymbolAddress((void**)&ah, g_ah);
    cudaGetSymbolAddress((void**)&modh, g_modh);
    cudaGetSymbolAddress((void**)&t12, g_t12);
    cudaGetSymbolAddress((void**)&gu, g_gu);

    cudaFuncSetAttribute(mma_gemm<float>, cudaFuncAttributeMaxDynamicSharedMemorySize, TC_SMEM);
    cudaFuncSetAttribute(mma_gemm<f16>,   cudaFuncAttributeMaxDynamicSharedMemorySize, TC_SMEM);
    cudaFuncSetAttribute(flash_attn,      cudaFuncAttributeMaxDynamicSharedMemorySize, FA_SMEM);

    const int n4h = (int)(RH/4), n4f = (int)(GGN/4), n4w = (int)(H2/4), n4ff = (int)(FF2/4);
    const dim3 B256(256);

    auto gemmH = [&](const f16* pa, const f16* pb, f16* c,
                     int M, int N, int K, int lda, int ldb, int ldc,
                     int gz, int zdiv, ll saa, ll sab, ll sba, ll sbb, ll sca, ll scb) {
        dim3 g(N/128, M/128, gz);
        mma_gemm<f16><<<g, 256, TC_SMEM>>>(pa, pb, c, nullptr, K, lda, ldb, ldc, zdiv,
                                           saa, sab, sba, sbb, sca, scb);
    };
    auto gemmFA = [&](const f16* pa, const f16* pb, float* c, const float* add,
                      int M, int N, int K, int lda, int ldb, int ldc) {
        dim3 g(N/128, M/128, 1);
        mma_gemm<float><<<g, 256, TC_SMEM>>>(pa, pb, c, add, K, lda, ldb, ldc, 1, 0,0,0,0,0,0);
    };

    // ---- rounds (merged) ----
    roundw_kernel<<<n4h/256, B256>>>(x_back, ah+OXB, n4h);
    xmod_dual<<<ROWS, B256>>>(x_mod, cross_ln_w, ah+OXM, ah+OQN);
    roundw8_kernel<<<dim3(n4w/256, 8), B256>>>(wq, wk, wv, wo, fb_w, fb_g, dr_w, dr_g, wh, n4w);
    roundw3_kernel<<<dim3(n4ff/256, 3), B256>>>(w_gate, w_up, w_down, wh+OWG, n4ff);

    // ---- z=3 merged q+k+v GEMM (zdiv=2) ----
    gemmH(ah+OXB, wh+OWK, ah+OK2, ROWS, HID, HID, HID, HID, HID,
          3, 2, -(ll)RH, 0, -(ll)H2, H2, -(ll)RH, 2*RH);

    // ---- z=4 merged highway GEMM ----
    gemmH(ah+OXM, wh+OFBW, t12, ROWS, HID, HID, HID, HID, HID,
          4, 2, -(ll)RH, 0, 2*H2, H2, 2*RH, RH);
    highway_kernel<<<n4h/256, B256>>>(t12+RH, t12, fb_gb, outd, n4h);

    // ---- rope over Q||K, V transpose ----
    const int ropeN2 = 2 * ROWS * NHEAD * 64;
    rope_inplace<<<(ropeN2+255)/256, B256>>>(ah+OQ, 2*ROWS);
    vtrans_kernel<<<dim3(SEQ/32, HDIM/32, BATCH*NHEAD), dim3(32,8)>>>(ah+OATT, ah+OVT);

    // ---- flash attention -> OATT, then WO ----
    flash_attn<<<dim3(SEQ/128, BATCH*NHEAD), B256, FA_SMEM>>>(
        ah+OQ, ah+OK2, ah+OVT, mask, ah+OATT);
    gemmH(ah+OATT, wh+OWO, modh, ROWS, HID, HID, HID, HID, HID, 1, 1, 0,0, 0,0, 0,0);

    // ---- fused combine + rmsadd + rmsnorm ----
    combine_fused<<<ROWS, B256>>>(x_mod, modh, t12+2*RH, t12+3*RH, dr_gb,
                                  in_ln_w, post_ln_w, x, ah+OHB);

    // ---- MLP ----
    gemmH(ah+OHB, wh+OWG, gu, ROWS, FFD, HID, HID, HID, FFD, 2, 1, 0,0, FF2,0, GGN,0);
    silumul_round<<<n4f/256, B256>>>(gu, gu+GGN, ah+OGG, n4f);
    gemmFA(ah+OGG, wh+OWD, outx, x, ROWS, HID, FFD, FFD, FFD, HID);
}